// round 4
// baseline (speedup 1.0000x reference)
#include <cuda_runtime.h>
#include <cuda_bf16.h>
#include <math.h>

// ---------------------------------------------------------------------------
// Problem dims (fixed)
// ---------------------------------------------------------------------------
#define B_   8
#define N_   1024
#define C_   1024
#define H_   16
#define D_   64
#define HID_ 4096
#define M_   (B_*N_)            // 8192 rows
#define O1_  (HID_ + 3*C_)      // 7168  (in_proj out)
#define F_   (HID_ + C_)        // 5120  (cat width)
#define O2_  (2*C_)             // 2048  (out_proj out)
#define EPS_ 1e-5f

// ---------------------------------------------------------------------------
// Scratch (device globals; allocation inside kernel_launch is forbidden)
// ---------------------------------------------------------------------------
__device__ float g_y[(size_t)M_ * C_];          // LN(x)                 32 MB
__device__ float g_z[(size_t)M_ * O1_];         // in_proj output       235 MB
__device__ float g_qT[(size_t)B_*H_*N_*D_];     // q LN'd, [B,H,N,D]     32 MB
__device__ float g_kT[(size_t)B_*H_*N_*D_];     //                       32 MB
__device__ float g_vT[(size_t)B_*H_*N_*D_];     //                       32 MB
__device__ float g_cat[(size_t)M_ * F_];        // [gelu(mlp) | attn]   160 MB
__device__ float g_o2[(size_t)M_ * O2_];        // out_proj output       64 MB
__device__ float g_bias1[O1_];                  // concat(zeros(3C), mlp_bias)

// ---------------------------------------------------------------------------
// 1) Input LayerNorm: one block per row of 1024
// ---------------------------------------------------------------------------
__global__ void __launch_bounds__(256) ln_in_kernel(
    const float* __restrict__ x, const float* __restrict__ w,
    const float* __restrict__ b, float* __restrict__ y)
{
    int row = blockIdx.x;
    const float4* xr = (const float4*)(x + (size_t)row * C_);
    float4 v = xr[threadIdx.x];
    float s  = v.x + v.y + v.z + v.w;
    float ss = v.x*v.x + v.y*v.y + v.z*v.z + v.w*v.w;

    #pragma unroll
    for (int o = 16; o; o >>= 1) {
        s  += __shfl_xor_sync(0xffffffffu, s,  o);
        ss += __shfl_xor_sync(0xffffffffu, ss, o);
    }
    __shared__ float sb[8], ssb[8];
    int wid = threadIdx.x >> 5, lane = threadIdx.x & 31;
    if (lane == 0) { sb[wid] = s; ssb[wid] = ss; }
    __syncthreads();
    __shared__ float s_mean, s_rstd;
    if (threadIdx.x == 0) {
        float t = 0.f, ts = 0.f;
        #pragma unroll
        for (int i = 0; i < 8; i++) { t += sb[i]; ts += ssb[i]; }
        float mean = t * (1.0f / C_);
        float var  = ts * (1.0f / C_) - mean * mean;
        s_mean = mean;
        s_rstd = rsqrtf(var + EPS_);
    }
    __syncthreads();
    float mean = s_mean, rstd = s_rstd;
    const float4* wv = (const float4*)w;
    const float4* bv = (const float4*)b;
    float4 wq = wv[threadIdx.x], bq = bv[threadIdx.x];
    float4 out;
    out.x = (v.x - mean) * rstd * wq.x + bq.x;
    out.y = (v.y - mean) * rstd * wq.y + bq.y;
    out.z = (v.z - mean) * rstd * wq.z + bq.z;
    out.w = (v.w - mean) * rstd * wq.w + bq.w;
    ((float4*)(y + (size_t)row * C_))[threadIdx.x] = out;
}

// ---------------------------------------------------------------------------
// 2) Build bias1 = concat(zeros(3C), mlp_bias)  (replicating reference quirk)
// ---------------------------------------------------------------------------
__global__ void build_bias1_kernel(const float* __restrict__ mlp_bias,
                                   float* __restrict__ bias1)
{
    int o = blockIdx.x * blockDim.x + threadIdx.x;
    if (o < O1_) bias1[o] = (o < 3*C_) ? 0.f : mlp_bias[o - 3*C_];
}

// ---------------------------------------------------------------------------
// 3) SGEMM: C[M,N] = A[M,K] * B[N,K]^T + bias[N]
//    128x128 tile, BK=8, 256 threads, 8x8 microtile. All dims divisible.
// ---------------------------------------------------------------------------
__global__ void __launch_bounds__(256) sgemm_nt(
    const float* __restrict__ A, const float* __restrict__ Bm,
    const float* __restrict__ bias, float* __restrict__ Cm,
    int M, int N, int K)
{
    __shared__ __align__(16) float As[8][128];
    __shared__ __align__(16) float Bs[8][128];

    int tid = threadIdx.x;
    int m0 = blockIdx.y * 128;
    int n0 = blockIdx.x * 128;

    int lr = tid >> 1;            // 0..127
    int lk = (tid & 1) * 4;       // 0 or 4
    const float* Ap = A  + (size_t)(m0 + lr) * K + lk;
    const float* Bp = Bm + (size_t)(n0 + lr) * K + lk;

    int ty = tid >> 4, tx = tid & 15;
    float acc[8][8] = {};

    for (int k0 = 0; k0 < K; k0 += 8) {
        float4 av = *(const float4*)(Ap + k0);
        float4 bv = *(const float4*)(Bp + k0);
        As[lk+0][lr] = av.x; As[lk+1][lr] = av.y;
        As[lk+2][lr] = av.z; As[lk+3][lr] = av.w;
        Bs[lk+0][lr] = bv.x; Bs[lk+1][lr] = bv.y;
        Bs[lk+2][lr] = bv.z; Bs[lk+3][lr] = bv.w;
        __syncthreads();
        #pragma unroll
        for (int k = 0; k < 8; k++) {
            float4 a0 = *(const float4*)(&As[k][ty*8]);
            float4 a1 = *(const float4*)(&As[k][ty*8+4]);
            float4 b0 = *(const float4*)(&Bs[k][tx*8]);
            float4 b1 = *(const float4*)(&Bs[k][tx*8+4]);
            float a[8] = {a0.x,a0.y,a0.z,a0.w,a1.x,a1.y,a1.z,a1.w};
            float b[8] = {b0.x,b0.y,b0.z,b0.w,b1.x,b1.y,b1.z,b1.w};
            #pragma unroll
            for (int i = 0; i < 8; i++)
                #pragma unroll
                for (int j = 0; j < 8; j++)
                    acc[i][j] += a[i] * b[j];
        }
        __syncthreads();
    }

    float bj[8];
    #pragma unroll
    for (int j = 0; j < 8; j++) bj[j] = bias[n0 + tx*8 + j];

    #pragma unroll
    for (int i = 0; i < 8; i++) {
        float* Cr = Cm + (size_t)(m0 + ty*8 + i) * N + n0 + tx*8;
        float4 r0 = make_float4(acc[i][0]+bj[0], acc[i][1]+bj[1],
                                acc[i][2]+bj[2], acc[i][3]+bj[3]);
        float4 r1 = make_float4(acc[i][4]+bj[4], acc[i][5]+bj[5],
                                acc[i][6]+bj[6], acc[i][7]+bj[7]);
        *(float4*)(Cr)     = r0;
        *(float4*)(Cr + 4) = r1;
    }
}

// ---------------------------------------------------------------------------
// 4) q/k LayerNorm (over D=64) + transpose to [B,H,N,D]; v transpose only.
//    One warp per (b,n,h).
// ---------------------------------------------------------------------------
__device__ __forceinline__ void ln64_warp(const float* __restrict__ src,
                                          const float* __restrict__ w,
                                          const float* __restrict__ b,
                                          float* __restrict__ dst, int lane)
{
    float2 v = *(const float2*)(src + lane * 2);
    float s  = v.x + v.y;
    float ss = v.x*v.x + v.y*v.y;
    #pragma unroll
    for (int o = 16; o; o >>= 1) {
        s  += __shfl_xor_sync(0xffffffffu, s,  o);
        ss += __shfl_xor_sync(0xffffffffu, ss, o);
    }
    float mean = s * (1.0f / 64.0f);
    float var  = ss * (1.0f / 64.0f) - mean * mean;
    float rstd = rsqrtf(var + EPS_);
    float2 wv = *(const float2*)(w + lane * 2);
    float2 bv = *(const float2*)(b + lane * 2);
    float2 out;
    out.x = (v.x - mean) * rstd * wv.x + bv.x;
    out.y = (v.y - mean) * rstd * wv.y + bv.y;
    *(float2*)(dst + lane * 2) = out;
}

__global__ void __launch_bounds__(256) qkv_ln_transpose_kernel(
    const float* __restrict__ z,
    const float* __restrict__ qw, const float* __restrict__ qb,
    const float* __restrict__ kw, const float* __restrict__ kb,
    float* __restrict__ Qo, float* __restrict__ Ko, float* __restrict__ Vo)
{
    int g = blockIdx.x * 8 + (threadIdx.x >> 5);   // (b, n, h) flat index
    int lane = threadIdx.x & 31;
    int b = g >> 14;               // /(N*H) = /16384
    int n = (g >> 4) & 1023;
    int h = g & 15;
    const float* zr = z + (size_t)(b * N_ + n) * O1_;
    size_t obase = ((size_t)(b * H_ + h) * N_ + n) * D_;

    ln64_warp(zr + HID_        + h*D_, qw, qb, Qo + obase, lane);
    ln64_warp(zr + HID_ + C_   + h*D_, kw, kb, Ko + obase, lane);
    float2 v = *(const float2*)(zr + HID_ + 2*C_ + h*D_ + lane * 2);
    *(float2*)(Vo + obase + lane * 2) = v;
}

// ---------------------------------------------------------------------------
// 5) Attention: flash-style, 64-query tile per block, full key sweep.
//    Dynamic smem layout (floats):
//      Qt[64][68] (d-major), Kt[64][68] (d-major), Vs[64][68] (n-major),
//      Pt[64][68] (c-major), red[64][16], mrow[64], lrow[64], frow[64]
// ---------------------------------------------------------------------------
#define ATTN_SMEM_FLOATS (4*64*68 + 64*16 + 3*64)
#define ATTN_SMEM_BYTES  (ATTN_SMEM_FLOATS * 4)

__global__ void __launch_bounds__(256) attn_kernel(
    const float* __restrict__ Qg, const float* __restrict__ Kg,
    const float* __restrict__ Vg, float* __restrict__ cat)
{
    extern __shared__ __align__(16) float sm[];
    float* Qt   = sm;                 // [d][n]  stride 68
    float* Kt   = Qt + 64*68;         // [d][c]  stride 68
    float* Vs   = Kt + 64*68;         // [c][d]  stride 68
    float* Pt   = Vs + 64*68;         // [c][r]  stride 68
    float* red  = Pt + 64*68;         // [64][16]
    float* mrow = red + 64*16;
    float* lrow = mrow + 64;
    float* frow = lrow + 64;

    int bh = blockIdx.y;                    // 0..127
    int n0 = blockIdx.x * 64;               // query tile start
    const float* qg = Qg + ((size_t)bh * N_ + n0) * D_;
    const float* kb = Kg + (size_t)bh * N_ * D_;
    const float* vb = Vg + (size_t)bh * N_ * D_;

    int tid = threadIdx.x;
    int ty = tid >> 4, tx = tid & 15;
    int r0 = ty * 4, c0 = tx * 4;

    for (int idx = tid; idx < 4096; idx += 256) {
        int n = idx >> 6, d = idx & 63;
        Qt[d*68 + n] = qg[idx];
    }
    if (tid < 64) { mrow[tid] = -1e30f; lrow[tid] = 0.f; }
    float o[4][4] = {};
    __syncthreads();

    for (int kt = 0; kt < 16; kt++) {
        const float* kg = kb + (size_t)kt * 64 * D_;
        const float* vg = vb + (size_t)kt * 64 * D_;
        for (int idx = tid; idx < 4096; idx += 256) {
            int n = idx >> 6, d = idx & 63;
            Kt[d*68 + n] = kg[idx];
            Vs[n*68 + d] = vg[idx];
        }
        __syncthreads();

        // S = scale * Q K^T  (4x4 fragment per thread)
        float s[4][4] = {};
        #pragma unroll 4
        for (int d = 0; d < 64; d++) {
            float4 aq = *(const float4*)(Qt + d*68 + r0);
            float4 bk = *(const float4*)(Kt + d*68 + c0);
            float a[4] = {aq.x, aq.y, aq.z, aq.w};
            float bb[4] = {bk.x, bk.y, bk.z, bk.w};
            #pragma unroll
            for (int i = 0; i < 4; i++)
                #pragma unroll
                for (int j = 0; j < 4; j++)
                    s[i][j] += a[i] * bb[j];
        }
        const float scale = 0.125f;   // 1/sqrt(64)
        #pragma unroll
        for (int i = 0; i < 4; i++) {
            float pm = -1e30f;
            #pragma unroll
            for (int j = 0; j < 4; j++) { s[i][j] *= scale; pm = fmaxf(pm, s[i][j]); }
            red[(r0+i)*16 + tx] = pm;
        }
        __syncthreads();

        if (tid < 64) {
            float mo = mrow[tid];
            float mx = -1e30f;
            #pragma unroll
            for (int t = 0; t < 16; t++) mx = fmaxf(mx, red[tid*16 + t]);
            float mn = fmaxf(mo, mx);
            mrow[tid] = mn;
            frow[tid] = __expf(mo - mn);
        }
        __syncthreads();

        // exp + write Pt + row sums + rescale O
        #pragma unroll
        for (int i = 0; i < 4; i++) {
            float mr = mrow[r0 + i];
            float ps = 0.f;
            #pragma unroll
            for (int j = 0; j < 4; j++) {
                float p = __expf(s[i][j] - mr);
                Pt[(c0+j)*68 + (r0+i)] = p;
                ps += p;
            }
            red[(r0+i)*16 + tx] = ps;
            float f = frow[r0 + i];
            #pragma unroll
            for (int j = 0; j < 4; j++) o[i][j] *= f;
        }
        __syncthreads();

        if (tid < 64) {
            float ssum = 0.f;
            #pragma unroll
            for (int t = 0; t < 16; t++) ssum += red[tid*16 + t];
            lrow[tid] = lrow[tid] * frow[tid] + ssum;
        }

        // O += P V  (inner over key index c)
        #pragma unroll 4
        for (int c = 0; c < 64; c++) {
            float4 ap = *(const float4*)(Pt + c*68 + r0);
            float4 bv = *(const float4*)(Vs + c*68 + c0);
            float a[4] = {ap.x, ap.y, ap.z, ap.w};
            float bb[4] = {bv.x, bv.y, bv.z, bv.w};
            #pragma unroll
            for (int i = 0; i < 4; i++)
                #pragma unroll
                for (int j = 0; j < 4; j++)
                    o[i][j] += a[i] * bb[j];
        }
        __syncthreads();
    }

    int b = bh >> 4, h = bh & 15;
    #pragma unroll
    for (int i = 0; i < 4; i++) {
        float inv = 1.0f / lrow[r0 + i];
        size_t m = (size_t)b * N_ + n0 + r0 + i;
        float4 out = make_float4(o[i][0]*inv, o[i][1]*inv, o[i][2]*inv, o[i][3]*inv);
        *(float4*)(cat + m * F_ + HID_ + h * D_ + c0) = out;
    }
}

// ---------------------------------------------------------------------------
// 6) GELU (exact) : cat[:, :HID] = gelu(z[:, :HID])
// ---------------------------------------------------------------------------
__global__ void __launch_bounds__(256) gelu_kernel(
    const float* __restrict__ z, float* __restrict__ cat)
{
    int idx = blockIdx.x * blockDim.x + threadIdx.x;     // over M * HID/4
    int row  = idx >> 10;          // HID/4 = 1024 float4 per row
    int col4 = idx & 1023;
    float4 v = *(const float4*)(z + (size_t)row * O1_ + col4 * 4);
    float4 r;
    r.x = v.x * normcdff(v.x);
    r.y = v.y * normcdff(v.y);
    r.z = v.z * normcdff(v.z);
    r.w = v.w * normcdff(v.w);
    *(float4*)(cat + (size_t)row * F_ + col4 * 4) = r;
}

// ---------------------------------------------------------------------------
// 7) Final: out = x + ls_gamma * (o2[:, :C] + o2[:, C:])
// ---------------------------------------------------------------------------
__global__ void __launch_bounds__(256) final_kernel(
    const float* __restrict__ x, const float* __restrict__ o2,
    const float* __restrict__ lsg, float* __restrict__ out)
{
    int idx = blockIdx.x * blockDim.x + threadIdx.x;     // over M * C/4
    int row  = idx >> 8;           // C/4 = 256 float4 per row
    int col4 = idx & 255;
    int c = col4 * 4;
    float4 xv = *(const float4*)(x + (size_t)row * C_ + c);
    float4 a  = *(const float4*)(o2 + (size_t)row * O2_ + c);
    float4 b  = *(const float4*)(o2 + (size_t)row * O2_ + C_ + c);
    float4 g  = *(const float4*)(lsg + c);
    float4 r;
    r.x = xv.x + g.x * (a.x + b.x);
    r.y = xv.y + g.y * (a.y + b.y);
    r.z = xv.z + g.z * (a.z + b.z);
    r.w = xv.w + g.w * (a.w + b.w);
    *(float4*)(out + (size_t)row * C_ + c) = r;
}

// ---------------------------------------------------------------------------
// launch
// ---------------------------------------------------------------------------
extern "C" void kernel_launch(void* const* d_in, const int* in_sizes, int n_in,
                              void* d_out, int out_size)
{
    const float* x          = (const float*)d_in[0];
    const float* in_norm_w  = (const float*)d_in[1];
    const float* in_norm_b  = (const float*)d_in[2];
    const float* in_proj_w  = (const float*)d_in[3];
    const float* mlp_bias   = (const float*)d_in[4];
    const float* q_norm_w   = (const float*)d_in[5];
    const float* q_norm_b   = (const float*)d_in[6];
    const float* k_norm_w   = (const float*)d_in[7];
    const float* k_norm_b   = (const float*)d_in[8];
    const float* out_proj_w = (const float*)d_in[9];
    const float* out_proj_b = (const float*)d_in[10];
    const float* ls_gamma   = (const float*)d_in[11];
    float* out = (float*)d_out;

    float *y, *z, *qT, *kT, *vT, *cat, *o2, *bias1;
    cudaGetSymbolAddress((void**)&y,     g_y);
    cudaGetSymbolAddress((void**)&z,     g_z);
    cudaGetSymbolAddress((void**)&qT,    g_qT);
    cudaGetSymbolAddress((void**)&kT,    g_kT);
    cudaGetSymbolAddress((void**)&vT,    g_vT);
    cudaGetSymbolAddress((void**)&cat,   g_cat);
    cudaGetSymbolAddress((void**)&o2,    g_o2);
    cudaGetSymbolAddress((void**)&bias1, g_bias1);

    cudaFuncSetAttribute(attn_kernel,
                         cudaFuncAttributeMaxDynamicSharedMemorySize,
                         ATTN_SMEM_BYTES);

    // 1) input LN
    ln_in_kernel<<<M_, 256>>>(x, in_norm_w, in_norm_b, y);

    // 2) bias1
    build_bias1_kernel<<<(O1_ + 255) / 256, 256>>>(mlp_bias, bias1);

    // 3) z = y @ in_proj_w^T + bias1
    sgemm_nt<<<dim3(O1_ / 128, M_ / 128), 256>>>(y, in_proj_w, bias1, z,
                                                 M_, O1_, C_);

    // 4) q/k LN + transpose, v transpose
    qkv_ln_transpose_kernel<<<(B_*N_*H_) / 8, 256>>>(
        z, q_norm_w, q_norm_b, k_norm_w, k_norm_b, qT, kT, vT);

    // 5) attention -> cat[:, HID:]
    attn_kernel<<<dim3(N_ / 64, B_ * H_), 256, ATTN_SMEM_BYTES>>>(qT, kT, vT, cat);

    // 6) gelu -> cat[:, :HID]
    gelu_kernel<<<(M_ * (HID_ / 4)) / 256, 256>>>(z, cat);

    // 7) o2 = cat @ out_proj_w^T + out_proj_b
    sgemm_nt<<<dim3(O2_ / 128, M_ / 128), 256>>>(cat, out_proj_w, out_proj_b,
                                                 o2, M_, O2_, F_);

    // 8) residual + layer scale
    final_kernel<<<(M_ * (C_ / 4)) / 256, 256>>>(x, o2, ls_gamma, out);
}

// round 7
// speedup vs baseline: 3.4507x; 3.4507x over previous
#include <cuda_runtime.h>
#include <cuda_bf16.h>
#include <mma.h>
#include <math.h>
#include <cstdint>

using namespace nvcuda;

// ---------------------------------------------------------------------------
// Problem dims (fixed)
// ---------------------------------------------------------------------------
#define B_   8
#define N_   1024
#define C_   1024
#define H_   16
#define D_   64
#define HID_ 4096
#define M_   (B_*N_)            // 8192 rows
#define O1_  (HID_ + 3*C_)      // 7168  (in_proj out)
#define F_   (HID_ + C_)        // 5120  (cat width)
#define O2_  (2*C_)             // 2048  (out_proj out)
#define EPS_ 1e-5f

// ---------------------------------------------------------------------------
// Scratch (device globals)
// ---------------------------------------------------------------------------
__device__ __nv_bfloat16 g_y[(size_t)M_ * C_];        // LN(x) bf16        16 MB
__device__ __nv_bfloat16 g_z[(size_t)M_ * O1_];       // in_proj out bf16 117 MB
__device__ __nv_bfloat16 g_w1[(size_t)O1_ * C_];      // in_proj_w bf16    14 MB
__device__ __nv_bfloat16 g_w2[(size_t)O2_ * F_];      // out_proj_w bf16   21 MB
__device__ __nv_bfloat16 g_cat[(size_t)M_ * F_];      // [gelu | attn]     80 MB
__device__ float g_qT[(size_t)B_*H_*N_*D_];           //                   32 MB
__device__ float g_kT[(size_t)B_*H_*N_*D_];           //                   32 MB
__device__ float g_vT[(size_t)B_*H_*N_*D_];           //                   32 MB
__device__ float g_o2[(size_t)M_ * O2_];              // out_proj out      64 MB
__device__ float g_bias1[O1_];                        // concat(0(3C), mlp_bias)

// ---------------------------------------------------------------------------
// helpers
// ---------------------------------------------------------------------------
__device__ __forceinline__ unsigned smem_u32(const void* p) {
    return (unsigned)__cvta_generic_to_shared(p);
}
__device__ __forceinline__ void cp_async16(void* dst, const void* src) {
    asm volatile("cp.async.cg.shared.global [%0], [%1], 16;\n"
                 :: "r"(smem_u32(dst)), "l"(src));
}
__device__ __forceinline__ void cp_commit() {
    asm volatile("cp.async.commit_group;\n" ::: "memory");
}
__device__ __forceinline__ void cp_wait0() {
    asm volatile("cp.async.wait_group 0;\n" ::: "memory");
}
__device__ __forceinline__ void cp_wait1() {
    asm volatile("cp.async.wait_group 1;\n" ::: "memory");
}

// ---------------------------------------------------------------------------
// fp32 -> bf16 conversion (for weights)
// ---------------------------------------------------------------------------
__global__ void __launch_bounds__(256) f2bf_kernel(
    const float* __restrict__ in, __nv_bfloat16* __restrict__ out, int n4)
{
    int i = blockIdx.x * blockDim.x + threadIdx.x;
    if (i >= n4) return;
    float4 v = ((const float4*)in)[i];
    __nv_bfloat162 a = __floats2bfloat162_rn(v.x, v.y);
    __nv_bfloat162 b = __floats2bfloat162_rn(v.z, v.w);
    ((__nv_bfloat162*)out)[i*2]   = a;
    ((__nv_bfloat162*)out)[i*2+1] = b;
}

// ---------------------------------------------------------------------------
// 1) Input LayerNorm: one block per row of 1024, writes bf16
// ---------------------------------------------------------------------------
__global__ void __launch_bounds__(256) ln_in_kernel(
    const float* __restrict__ x, const float* __restrict__ w,
    const float* __restrict__ b, __nv_bfloat16* __restrict__ y)
{
    int row = blockIdx.x;
    const float4* xr = (const float4*)(x + (size_t)row * C_);
    float4 v = xr[threadIdx.x];
    float s  = v.x + v.y + v.z + v.w;
    float ss = v.x*v.x + v.y*v.y + v.z*v.z + v.w*v.w;

    #pragma unroll
    for (int o = 16; o; o >>= 1) {
        s  += __shfl_xor_sync(0xffffffffu, s,  o);
        ss += __shfl_xor_sync(0xffffffffu, ss, o);
    }
    __shared__ float sb[8], ssb[8];
    int wid = threadIdx.x >> 5, lane = threadIdx.x & 31;
    if (lane == 0) { sb[wid] = s; ssb[wid] = ss; }
    __syncthreads();
    __shared__ float s_mean, s_rstd;
    if (threadIdx.x == 0) {
        float t = 0.f, ts = 0.f;
        #pragma unroll
        for (int i = 0; i < 8; i++) { t += sb[i]; ts += ssb[i]; }
        float mean = t * (1.0f / C_);
        float var  = ts * (1.0f / C_) - mean * mean;
        s_mean = mean;
        s_rstd = rsqrtf(var + EPS_);
    }
    __syncthreads();
    float mean = s_mean, rstd = s_rstd;
    float4 wq = ((const float4*)w)[threadIdx.x];
    float4 bq = ((const float4*)b)[threadIdx.x];
    float ox = (v.x - mean) * rstd * wq.x + bq.x;
    float oy = (v.y - mean) * rstd * wq.y + bq.y;
    float oz = (v.z - mean) * rstd * wq.z + bq.z;
    float ow = (v.w - mean) * rstd * wq.w + bq.w;
    __nv_bfloat16* yr = y + (size_t)row * C_ + threadIdx.x * 4;
    *(__nv_bfloat162*)(yr)     = __floats2bfloat162_rn(ox, oy);
    *(__nv_bfloat162*)(yr + 2) = __floats2bfloat162_rn(oz, ow);
}

// ---------------------------------------------------------------------------
// 2) bias1 = concat(zeros(3C), mlp_bias)
// ---------------------------------------------------------------------------
__global__ void build_bias1_kernel(const float* __restrict__ mlp_bias,
                                   float* __restrict__ bias1)
{
    int o = blockIdx.x * blockDim.x + threadIdx.x;
    if (o < O1_) bias1[o] = (o < 3*C_) ? 0.f : mlp_bias[o - 3*C_];
}

// ---------------------------------------------------------------------------
// 3) bf16 WMMA GEMM: C[M,N] = A[M,K] * B[N,K]^T + bias[N]
//    128x128 block, BK=64, 256 thr (8 warps, 2x4), warp tile 64x32,
//    cp.async double-buffered, fp32 accum, smem-staged epilogue.
//    Smem: 2 stages * (A[128][72] + B[128][72]) bf16 = 73728 B,
//    reused as float Cs[128][132] in epilogue (67584 B).
// ---------------------------------------------------------------------------
#define GPAD   72
#define GSTAGE (128 * GPAD)           // bf16 elems per tile buffer
#define GEMM_SMEM_BYTES (4 * GSTAGE * 2)   // 73728

template<bool BF16OUT>
__global__ void __launch_bounds__(256) wmma_gemm_nt(
    const __nv_bfloat16* __restrict__ A, const __nv_bfloat16* __restrict__ Bm,
    const float* __restrict__ bias, void* __restrict__ Cout,
    int M, int N, int K)
{
    extern __shared__ __align__(16) char smraw[];
    __nv_bfloat16* smb = (__nv_bfloat16*)smraw;
    // stage s: A at s*GSTAGE, B at 2*GSTAGE + s*GSTAGE

    int tid = threadIdx.x;
    int m0 = blockIdx.y * 128;
    int n0 = blockIdx.x * 128;

    int wid = tid >> 5;
    int wm = wid >> 2;        // 0..1
    int wn = wid & 3;         // 0..3

    // copy mapping: 1024 16B-chunks per tile, 4 per thread
    int crow[4], ccol[4];
    #pragma unroll
    for (int i = 0; i < 4; i++) {
        int chunk = tid + i * 256;
        crow[i] = chunk >> 3;
        ccol[i] = (chunk & 7) * 8;
    }

    wmma::fragment<wmma::accumulator, 16, 16, 16, float> acc[4][2];
    #pragma unroll
    for (int i = 0; i < 4; i++)
        #pragma unroll
        for (int j = 0; j < 2; j++)
            wmma::fill_fragment(acc[i][j], 0.0f);

    int nk = K >> 6;

    // prologue: stage 0
    {
        __nv_bfloat16* sA = smb;
        __nv_bfloat16* sB = smb + 2 * GSTAGE;
        #pragma unroll
        for (int i = 0; i < 4; i++) {
            cp_async16(sA + crow[i]*GPAD + ccol[i],
                       A + (size_t)(m0 + crow[i]) * K + ccol[i]);
            cp_async16(sB + crow[i]*GPAD + ccol[i],
                       Bm + (size_t)(n0 + crow[i]) * K + ccol[i]);
        }
        cp_commit();
    }

    for (int k0 = 0; k0 < nk; k0++) {
        if (k0 + 1 < nk) {
            int s = (k0 + 1) & 1;
            int kofs = (k0 + 1) << 6;
            __nv_bfloat16* sA = smb + s * GSTAGE;
            __nv_bfloat16* sB = smb + 2 * GSTAGE + s * GSTAGE;
            #pragma unroll
            for (int i = 0; i < 4; i++) {
                cp_async16(sA + crow[i]*GPAD + ccol[i],
                           A + (size_t)(m0 + crow[i]) * K + kofs + ccol[i]);
                cp_async16(sB + crow[i]*GPAD + ccol[i],
                           Bm + (size_t)(n0 + crow[i]) * K + kofs + ccol[i]);
            }
            cp_commit();
            cp_wait1();
        } else {
            cp_wait0();
        }
        __syncthreads();

        int s = k0 & 1;
        const __nv_bfloat16* sA = smb + s * GSTAGE;
        const __nv_bfloat16* sB = smb + 2 * GSTAGE + s * GSTAGE;

        #pragma unroll
        for (int kk = 0; kk < 4; kk++) {
            wmma::fragment<wmma::matrix_a, 16, 16, 16, __nv_bfloat16, wmma::row_major> af[4];
            wmma::fragment<wmma::matrix_b, 16, 16, 16, __nv_bfloat16, wmma::col_major> bfr[2];
            #pragma unroll
            for (int i = 0; i < 4; i++)
                wmma::load_matrix_sync(af[i], sA + (wm*64 + i*16)*GPAD + kk*16, GPAD);
            #pragma unroll
            for (int j = 0; j < 2; j++)
                wmma::load_matrix_sync(bfr[j], sB + (wn*32 + j*16)*GPAD + kk*16, GPAD);
            #pragma unroll
            for (int i = 0; i < 4; i++)
                #pragma unroll
                for (int j = 0; j < 2; j++)
                    wmma::mma_sync(acc[i][j], af[i], bfr[j], acc[i][j]);
        }
        __syncthreads();
    }

    // epilogue: stage accumulators in smem (reuse tile buffers)
    float* Cs = (float*)smraw;     // [128][132]
    #pragma unroll
    for (int i = 0; i < 4; i++)
        #pragma unroll
        for (int j = 0; j < 2; j++)
            wmma::store_matrix_sync(Cs + (size_t)(wm*64 + i*16)*132 + wn*32 + j*16,
                                    acc[i][j], 132, wmma::mem_row_major);
    __syncthreads();

    // write out with bias; 4096 float4 groups over 256 threads
    #pragma unroll
    for (int it = 0; it < 16; it++) {
        int idx = tid + it * 256;
        int row = idx >> 5;
        int c4  = (idx & 31) * 4;
        float4 v = *(const float4*)(Cs + row*132 + c4);
        float4 bb = *(const float4*)(bias + n0 + c4);
        v.x += bb.x; v.y += bb.y; v.z += bb.z; v.w += bb.w;
        if (BF16OUT) {
            __nv_bfloat16* Cr = (__nv_bfloat16*)Cout + (size_t)(m0 + row) * N + n0 + c4;
            *(__nv_bfloat162*)(Cr)     = __floats2bfloat162_rn(v.x, v.y);
            *(__nv_bfloat162*)(Cr + 2) = __floats2bfloat162_rn(v.z, v.w);
        } else {
            float* Cr = (float*)Cout + (size_t)(m0 + row) * N + n0 + c4;
            *(float4*)Cr = v;
        }
    }
}

// ---------------------------------------------------------------------------
// 4) q/k LayerNorm (over D=64, reading bf16 z) + transpose; v transpose.
// ---------------------------------------------------------------------------
__device__ __forceinline__ void ln64_warp(const __nv_bfloat16* __restrict__ src,
                                          const float* __restrict__ w,
                                          const float* __restrict__ b,
                                          float* __restrict__ dst, int lane)
{
    __nv_bfloat162 raw = *(const __nv_bfloat162*)(src + lane * 2);
    float2 v = make_float2(__bfloat162float(raw.x), __bfloat162float(raw.y));
    float s  = v.x + v.y;
    float ss = v.x*v.x + v.y*v.y;
    #pragma unroll
    for (int o = 16; o; o >>= 1) {
        s  += __shfl_xor_sync(0xffffffffu, s,  o);
        ss += __shfl_xor_sync(0xffffffffu, ss, o);
    }
    float mean = s * (1.0f / 64.0f);
    float var  = ss * (1.0f / 64.0f) - mean * mean;
    float rstd = rsqrtf(var + EPS_);
    float2 wv = *(const float2*)(w + lane * 2);
    float2 bv = *(const float2*)(b + lane * 2);
    float2 out;
    out.x = (v.x - mean) * rstd * wv.x + bv.x;
    out.y = (v.y - mean) * rstd * wv.y + bv.y;
    *(float2*)(dst + lane * 2) = out;
}

__global__ void __launch_bounds__(256) qkv_ln_transpose_kernel(
    const __nv_bfloat16* __restrict__ z,
    const float* __restrict__ qw, const float* __restrict__ qb,
    const float* __restrict__ kw, const float* __restrict__ kb,
    float* __restrict__ Qo, float* __restrict__ Ko, float* __restrict__ Vo)
{
    int g = blockIdx.x * 8 + (threadIdx.x >> 5);   // (b, n, h) flat index
    int lane = threadIdx.x & 31;
    int b = g >> 14;
    int n = (g >> 4) & 1023;
    int h = g & 15;
    const __nv_bfloat16* zr = z + (size_t)(b * N_ + n) * O1_;
    size_t obase = ((size_t)(b * H_ + h) * N_ + n) * D_;

    ln64_warp(zr + HID_        + h*D_, qw, qb, Qo + obase, lane);
    ln64_warp(zr + HID_ + C_   + h*D_, kw, kb, Ko + obase, lane);
    __nv_bfloat162 raw = *(const __nv_bfloat162*)(zr + HID_ + 2*C_ + h*D_ + lane * 2);
    float2 v = make_float2(__bfloat162float(raw.x), __bfloat162float(raw.y));
    *(float2*)(Vo + obase + lane * 2) = v;
}

// ---------------------------------------------------------------------------
// 5) Attention (fp32 flash-style, bf16 cat output)
// ---------------------------------------------------------------------------
#define ATTN_SMEM_FLOATS (4*64*68 + 64*16 + 3*64)
#define ATTN_SMEM_BYTES  (ATTN_SMEM_FLOATS * 4)

__global__ void __launch_bounds__(256) attn_kernel(
    const float* __restrict__ Qg, const float* __restrict__ Kg,
    const float* __restrict__ Vg, __nv_bfloat16* __restrict__ cat)
{
    extern __shared__ __align__(16) float sm[];
    float* Qt   = sm;
    float* Kt   = Qt + 64*68;
    float* Vs   = Kt + 64*68;
    float* Pt   = Vs + 64*68;
    float* red  = Pt + 64*68;
    float* mrow = red + 64*16;
    float* lrow = mrow + 64;
    float* frow = lrow + 64;

    int bh = blockIdx.y;
    int n0 = blockIdx.x * 64;
    const float* qg = Qg + ((size_t)bh * N_ + n0) * D_;
    const float* kb = Kg + (size_t)bh * N_ * D_;
    const float* vb = Vg + (size_t)bh * N_ * D_;

    int tid = threadIdx.x;
    int ty = tid >> 4, tx = tid & 15;
    int r0 = ty * 4, c0 = tx * 4;

    for (int idx = tid; idx < 4096; idx += 256) {
        int n = idx >> 6, d = idx & 63;
        Qt[d*68 + n] = qg[idx];
    }
    if (tid < 64) { mrow[tid] = -1e30f; lrow[tid] = 0.f; }
    float o[4][4] = {};
    __syncthreads();

    for (int kt = 0; kt < 16; kt++) {
        const float* kg = kb + (size_t)kt * 64 * D_;
        const float* vg = vb + (size_t)kt * 64 * D_;
        for (int idx = tid; idx < 4096; idx += 256) {
            int n = idx >> 6, d = idx & 63;
            Kt[d*68 + n] = kg[idx];
            Vs[n*68 + d] = vg[idx];
        }
        __syncthreads();

        float s[4][4] = {};
        #pragma unroll 4
        for (int d = 0; d < 64; d++) {
            float4 aq = *(const float4*)(Qt + d*68 + r0);
            float4 bk = *(const float4*)(Kt + d*68 + c0);
            float a[4] = {aq.x, aq.y, aq.z, aq.w};
            float bb[4] = {bk.x, bk.y, bk.z, bk.w};
            #pragma unroll
            for (int i = 0; i < 4; i++)
                #pragma unroll
                for (int j = 0; j < 4; j++)
                    s[i][j] += a[i] * bb[j];
        }
        const float scale = 0.125f;
        #pragma unroll
        for (int i = 0; i < 4; i++) {
            float pm = -1e30f;
            #pragma unroll
            for (int j = 0; j < 4; j++) { s[i][j] *= scale; pm = fmaxf(pm, s[i][j]); }
            red[(r0+i)*16 + tx] = pm;
        }
        __syncthreads();

        if (tid < 64) {
            float mo = mrow[tid];
            float mx = -1e30f;
            #pragma unroll
            for (int t = 0; t < 16; t++) mx = fmaxf(mx, red[tid*16 + t]);
            float mn = fmaxf(mo, mx);
            mrow[tid] = mn;
            frow[tid] = __expf(mo - mn);
        }
        __syncthreads();

        #pragma unroll
        for (int i = 0; i < 4; i++) {
            float mr = mrow[r0 + i];
            float ps = 0.f;
            #pragma unroll
            for (int j = 0; j < 4; j++) {
                float p = __expf(s[i][j] - mr);
                Pt[(c0+j)*68 + (r0+i)] = p;
                ps += p;
            }
            red[(r0+i)*16 + tx] = ps;
            float f = frow[r0 + i];
            #pragma unroll
            for (int j = 0; j < 4; j++) o[i][j] *= f;
        }
        __syncthreads();

        if (tid < 64) {
            float ssum = 0.f;
            #pragma unroll
            for (int t = 0; t < 16; t++) ssum += red[tid*16 + t];
            lrow[tid] = lrow[tid] * frow[tid] + ssum;
        }

        #pragma unroll 4
        for (int c = 0; c < 64; c++) {
            float4 ap = *(const float4*)(Pt + c*68 + r0);
            float4 bv = *(const float4*)(Vs + c*68 + c0);
            float a[4] = {ap.x, ap.y, ap.z, ap.w};
            float bb[4] = {bv.x, bv.y, bv.z, bv.w};
            #pragma unroll
            for (int i = 0; i < 4; i++)
                #pragma unroll
                for (int j = 0; j < 4; j++)
                    o[i][j] += a[i] * bb[j];
        }
        __syncthreads();
    }

    int b = bh >> 4, h = bh & 15;
    #pragma unroll
    for (int i = 0; i < 4; i++) {
        float inv = 1.0f / lrow[r0 + i];
        size_t m = (size_t)b * N_ + n0 + r0 + i;
        __nv_bfloat16* cr = cat + m * F_ + HID_ + h * D_ + c0;
        *(__nv_bfloat162*)(cr)     = __floats2bfloat162_rn(o[i][0]*inv, o[i][1]*inv);
        *(__nv_bfloat162*)(cr + 2) = __floats2bfloat162_rn(o[i][2]*inv, o[i][3]*inv);
    }
}

// ---------------------------------------------------------------------------
// 6) GELU (exact, bf16 in/out)
// ---------------------------------------------------------------------------
__global__ void __launch_bounds__(256) gelu_kernel(
    const __nv_bfloat16* __restrict__ z, __nv_bfloat16* __restrict__ cat)
{
    int idx = blockIdx.x * blockDim.x + threadIdx.x;     // over M * HID/4
    int row  = idx >> 10;
    int col4 = idx & 1023;
    const __nv_bfloat16* zp = z + (size_t)row * O1_ + col4 * 4;
    __nv_bfloat162 a = *(const __nv_bfloat162*)(zp);
    __nv_bfloat162 b = *(const __nv_bfloat162*)(zp + 2);
    float vx = __bfloat162float(a.x), vy = __bfloat162float(a.y);
    float vz = __bfloat162float(b.x), vw = __bfloat162float(b.y);
    vx *= normcdff(vx);
    vy *= normcdff(vy);
    vz *= normcdff(vz);
    vw *= normcdff(vw);
    __nv_bfloat16* cp = cat + (size_t)row * F_ + col4 * 4;
    *(__nv_bfloat162*)(cp)     = __floats2bfloat162_rn(vx, vy);
    *(__nv_bfloat162*)(cp + 2) = __floats2bfloat162_rn(vz, vw);
}

// ---------------------------------------------------------------------------
// 7) Final: out = x + ls_gamma * (o2[:, :C] + o2[:, C:])
// ---------------------------------------------------------------------------
__global__ void __launch_bounds__(256) final_kernel(
    const float* __restrict__ x, const float* __restrict__ o2,
    const float* __restrict__ lsg, float* __restrict__ out)
{
    int idx = blockIdx.x * blockDim.x + threadIdx.x;
    int row  = idx >> 8;
    int col4 = idx & 255;
    int c = col4 * 4;
    float4 xv = *(const float4*)(x + (size_t)row * C_ + c);
    float4 a  = *(const float4*)(o2 + (size_t)row * O2_ + c);
    float4 b  = *(const float4*)(o2 + (size_t)row * O2_ + C_ + c);
    float4 g  = *(const float4*)(lsg + c);
    float4 r;
    r.x = xv.x + g.x * (a.x + b.x);
    r.y = xv.y + g.y * (a.y + b.y);
    r.z = xv.z + g.z * (a.z + b.z);
    r.w = xv.w + g.w * (a.w + b.w);
    *(float4*)(out + (size_t)row * C_ + c) = r;
}

// ---------------------------------------------------------------------------
// launch
// ---------------------------------------------------------------------------
extern "C" void kernel_launch(void* const* d_in, const int* in_sizes, int n_in,
                              void* d_out, int out_size)
{
    const float* x          = (const float*)d_in[0];
    const float* in_norm_w  = (const float*)d_in[1];
    const float* in_norm_b  = (const float*)d_in[2];
    const float* in_proj_w  = (const float*)d_in[3];
    const float* mlp_bias   = (const float*)d_in[4];
    const float* q_norm_w   = (const float*)d_in[5];
    const float* q_norm_b   = (const float*)d_in[6];
    const float* k_norm_w   = (const float*)d_in[7];
    const float* k_norm_b   = (const float*)d_in[8];
    const float* out_proj_w = (const float*)d_in[9];
    const float* out_proj_b = (const float*)d_in[10];
    const float* ls_gamma   = (const float*)d_in[11];
    float* out = (float*)d_out;

    __nv_bfloat16 *y, *z, *w1, *w2, *cat;
    float *qT, *kT, *vT, *o2, *bias1;
    cudaGetSymbolAddress((void**)&y,     g_y);
    cudaGetSymbolAddress((void**)&z,     g_z);
    cudaGetSymbolAddress((void**)&w1,    g_w1);
    cudaGetSymbolAddress((void**)&w2,    g_w2);
    cudaGetSymbolAddress((void**)&cat,   g_cat);
    cudaGetSymbolAddress((void**)&qT,    g_qT);
    cudaGetSymbolAddress((void**)&kT,    g_kT);
    cudaGetSymbolAddress((void**)&vT,    g_vT);
    cudaGetSymbolAddress((void**)&o2,    g_o2);
    cudaGetSymbolAddress((void**)&bias1, g_bias1);

    cudaFuncSetAttribute(attn_kernel,
                         cudaFuncAttributeMaxDynamicSharedMemorySize,
                         ATTN_SMEM_BYTES);
    cudaFuncSetAttribute(wmma_gemm_nt<true>,
                         cudaFuncAttributeMaxDynamicSharedMemorySize,
                         GEMM_SMEM_BYTES);
    cudaFuncSetAttribute(wmma_gemm_nt<false>,
                         cudaFuncAttributeMaxDynamicSharedMemorySize,
                         GEMM_SMEM_BYTES);

    // 0) weight conversion fp32 -> bf16
    f2bf_kernel<<<(O1_*C_/4 + 255)/256, 256>>>(in_proj_w, w1, O1_*C_/4);
    f2bf_kernel<<<(O2_*F_/4 + 255)/256, 256>>>(out_proj_w, w2, O2_*F_/4);

    // 1) input LN -> y (bf16)
    ln_in_kernel<<<M_, 256>>>(x, in_norm_w, in_norm_b, y);

    // 2) bias1
    build_bias1_kernel<<<(O1_ + 255) / 256, 256>>>(mlp_bias, bias1);

    // 3) z = y @ w1^T + bias1  (bf16 out)
    wmma_gemm_nt<true><<<dim3(O1_ / 128, M_ / 128), 256, GEMM_SMEM_BYTES>>>(
        y, w1, bias1, z, M_, O1_, C_);

    // 4) q/k LN + transpose, v transpose
    qkv_ln_transpose_kernel<<<(B_*N_*H_) / 8, 256>>>(
        z, q_norm_w, q_norm_b, k_norm_w, k_norm_b, qT, kT, vT);

    // 5) attention -> cat[:, HID:] (bf16)
    attn_kernel<<<dim3(N_ / 64, B_ * H_), 256, ATTN_SMEM_BYTES>>>(qT, kT, vT, cat);

    // 6) gelu -> cat[:, :HID] (bf16)
    gelu_kernel<<<(M_ * (HID_ / 4)) / 256, 256>>>(z, cat);

    // 7) o2 = cat @ w2^T + out_proj_b  (fp32 out)
    wmma_gemm_nt<false><<<dim3(O2_ / 128, M_ / 128), 256, GEMM_SMEM_BYTES>>>(
        cat, w2, out_proj_b, o2, M_, O2_, F_);

    // 8) residual + layer scale
    final_kernel<<<(M_ * (C_ / 4)) / 256, 256>>>(x, o2, ls_gamma, out);
}

// round 10
// speedup vs baseline: 5.6485x; 1.6369x over previous
#include <cuda_runtime.h>
#include <cuda_bf16.h>
#include <cuda_fp16.h>
#include <mma.h>
#include <math.h>
#include <cstdint>

using namespace nvcuda;

// ---------------------------------------------------------------------------
// Problem dims (fixed)
// ---------------------------------------------------------------------------
#define B_   8
#define N_   1024
#define C_   1024
#define H_   16
#define D_   64
#define HID_ 4096
#define M_   (B_*N_)            // 8192 rows
#define O1_  (HID_ + 3*C_)      // 7168  (in_proj out)
#define F_   (HID_ + C_)        // 5120  (cat width)
#define O2_  (2*C_)             // 2048  (out_proj out)
#define EPS_ 1e-5f
// 1/sqrt(64) * log2(e), folded into Q so softmax works in exp2 domain
#define QSCALE_ 0.18033688011112042f

// ---------------------------------------------------------------------------
// Scratch (device globals)
// ---------------------------------------------------------------------------
__device__ __nv_bfloat16 g_y[(size_t)M_ * C_];        // LN(x) bf16        16 MB
__device__ __nv_bfloat16 g_z[(size_t)M_ * O1_];       // in_proj out bf16 117 MB
__device__ __nv_bfloat16 g_w1[(size_t)O1_ * C_];      // in_proj_w bf16    14 MB
__device__ __nv_bfloat16 g_w2[(size_t)O2_ * F_];      // out_proj_w bf16   21 MB
__device__ __nv_bfloat16 g_cat[(size_t)M_ * F_];      // [gelu | attn]     80 MB
__device__ __half g_qT[(size_t)B_*H_*N_*D_];          // f16               16 MB
__device__ __half g_kT[(size_t)B_*H_*N_*D_];          //                   16 MB
__device__ __half g_vT[(size_t)B_*H_*N_*D_];          //                   16 MB
__device__ float g_o2[(size_t)M_ * O2_];              // out_proj out      64 MB
__device__ float g_bias1[O1_];                        // concat(0(3C), mlp_bias)

// ---------------------------------------------------------------------------
// helpers
// ---------------------------------------------------------------------------
__device__ __forceinline__ unsigned smem_u32(const void* p) {
    return (unsigned)__cvta_generic_to_shared(p);
}
__device__ __forceinline__ void cp_async16(void* dst, const void* src) {
    asm volatile("cp.async.cg.shared.global [%0], [%1], 16;\n"
                 :: "r"(smem_u32(dst)), "l"(src));
}
__device__ __forceinline__ void cp_commit() {
    asm volatile("cp.async.commit_group;\n" ::: "memory");
}
__device__ __forceinline__ void cp_wait0() {
    asm volatile("cp.async.wait_group 0;\n" ::: "memory");
}
__device__ __forceinline__ void cp_wait1() {
    asm volatile("cp.async.wait_group 1;\n" ::: "memory");
}
__device__ __forceinline__ void ldmatrix_x4(unsigned* r, const void* p) {
    asm volatile("ldmatrix.sync.aligned.m8n8.x4.shared.b16 {%0,%1,%2,%3}, [%4];\n"
                 : "=r"(r[0]), "=r"(r[1]), "=r"(r[2]), "=r"(r[3])
                 : "r"(smem_u32(p)));
}
__device__ __forceinline__ void ldmatrix_x4_trans(unsigned* r, const void* p) {
    asm volatile("ldmatrix.sync.aligned.m8n8.x4.trans.shared.b16 {%0,%1,%2,%3}, [%4];\n"
                 : "=r"(r[0]), "=r"(r[1]), "=r"(r[2]), "=r"(r[3])
                 : "r"(smem_u32(p)));
}
__device__ __forceinline__ void mma16816(float* c, const unsigned* a,
                                         unsigned b0, unsigned b1) {
    asm volatile("mma.sync.aligned.m16n8k16.row.col.f32.f16.f16.f32 "
                 "{%0,%1,%2,%3}, {%4,%5,%6,%7}, {%8,%9}, {%0,%1,%2,%3};\n"
                 : "+f"(c[0]), "+f"(c[1]), "+f"(c[2]), "+f"(c[3])
                 : "r"(a[0]), "r"(a[1]), "r"(a[2]), "r"(a[3]),
                   "r"(b0), "r"(b1));
}

// ---------------------------------------------------------------------------
// fp32 -> bf16 conversion (for weights)
// ---------------------------------------------------------------------------
__global__ void __launch_bounds__(256) f2bf_kernel(
    const float* __restrict__ in, __nv_bfloat16* __restrict__ out, int n4)
{
    int i = blockIdx.x * blockDim.x + threadIdx.x;
    if (i >= n4) return;
    float4 v = ((const float4*)in)[i];
    __nv_bfloat162 a = __floats2bfloat162_rn(v.x, v.y);
    __nv_bfloat162 b = __floats2bfloat162_rn(v.z, v.w);
    ((__nv_bfloat162*)out)[i*2]   = a;
    ((__nv_bfloat162*)out)[i*2+1] = b;
}

// ---------------------------------------------------------------------------
// 1) Input LayerNorm
// ---------------------------------------------------------------------------
__global__ void __launch_bounds__(256) ln_in_kernel(
    const float* __restrict__ x, const float* __restrict__ w,
    const float* __restrict__ b, __nv_bfloat16* __restrict__ y)
{
    int row = blockIdx.x;
    const float4* xr = (const float4*)(x + (size_t)row * C_);
    float4 v = xr[threadIdx.x];
    float s  = v.x + v.y + v.z + v.w;
    float ss = v.x*v.x + v.y*v.y + v.z*v.z + v.w*v.w;

    #pragma unroll
    for (int o = 16; o; o >>= 1) {
        s  += __shfl_xor_sync(0xffffffffu, s,  o);
        ss += __shfl_xor_sync(0xffffffffu, ss, o);
    }
    __shared__ float sb[8], ssb[8];
    int wid = threadIdx.x >> 5, lane = threadIdx.x & 31;
    if (lane == 0) { sb[wid] = s; ssb[wid] = ss; }
    __syncthreads();
    __shared__ float s_mean, s_rstd;
    if (threadIdx.x == 0) {
        float t = 0.f, ts = 0.f;
        #pragma unroll
        for (int i = 0; i < 8; i++) { t += sb[i]; ts += ssb[i]; }
        float mean = t * (1.0f / C_);
        float var  = ts * (1.0f / C_) - mean * mean;
        s_mean = mean;
        s_rstd = rsqrtf(var + EPS_);
    }
    __syncthreads();
    float mean = s_mean, rstd = s_rstd;
    float4 wq = ((const float4*)w)[threadIdx.x];
    float4 bq = ((const float4*)b)[threadIdx.x];
    float ox = (v.x - mean) * rstd * wq.x + bq.x;
    float oy = (v.y - mean) * rstd * wq.y + bq.y;
    float oz = (v.z - mean) * rstd * wq.z + bq.z;
    float ow = (v.w - mean) * rstd * wq.w + bq.w;
    __nv_bfloat16* yr = y + (size_t)row * C_ + threadIdx.x * 4;
    *(__nv_bfloat162*)(yr)     = __floats2bfloat162_rn(ox, oy);
    *(__nv_bfloat162*)(yr + 2) = __floats2bfloat162_rn(oz, ow);
}

// ---------------------------------------------------------------------------
// 2) bias1 = concat(zeros(3C), mlp_bias)
// ---------------------------------------------------------------------------
__global__ void build_bias1_kernel(const float* __restrict__ mlp_bias,
                                   float* __restrict__ bias1)
{
    int o = blockIdx.x * blockDim.x + threadIdx.x;
    if (o < O1_) bias1[o] = (o < 3*C_) ? 0.f : mlp_bias[o - 3*C_];
}

// ---------------------------------------------------------------------------
// 3) bf16 WMMA GEMM (unchanged from R7)
// ---------------------------------------------------------------------------
#define GPAD   72
#define GSTAGE (128 * GPAD)
#define GEMM_SMEM_BYTES (4 * GSTAGE * 2)

template<bool BF16OUT>
__global__ void __launch_bounds__(256) wmma_gemm_nt(
    const __nv_bfloat16* __restrict__ A, const __nv_bfloat16* __restrict__ Bm,
    const float* __restrict__ bias, void* __restrict__ Cout,
    int M, int N, int K)
{
    extern __shared__ __align__(16) char smraw[];
    __nv_bfloat16* smb = (__nv_bfloat16*)smraw;

    int tid = threadIdx.x;
    int m0 = blockIdx.y * 128;
    int n0 = blockIdx.x * 128;

    int wid = tid >> 5;
    int wm = wid >> 2;
    int wn = wid & 3;

    int crow[4], ccol[4];
    #pragma unroll
    for (int i = 0; i < 4; i++) {
        int chunk = tid + i * 256;
        crow[i] = chunk >> 3;
        ccol[i] = (chunk & 7) * 8;
    }

    wmma::fragment<wmma::accumulator, 16, 16, 16, float> acc[4][2];
    #pragma unroll
    for (int i = 0; i < 4; i++)
        #pragma unroll
        for (int j = 0; j < 2; j++)
            wmma::fill_fragment(acc[i][j], 0.0f);

    int nk = K >> 6;

    {
        __nv_bfloat16* sA = smb;
        __nv_bfloat16* sB = smb + 2 * GSTAGE;
        #pragma unroll
        for (int i = 0; i < 4; i++) {
            cp_async16(sA + crow[i]*GPAD + ccol[i],
                       A + (size_t)(m0 + crow[i]) * K + ccol[i]);
            cp_async16(sB + crow[i]*GPAD + ccol[i],
                       Bm + (size_t)(n0 + crow[i]) * K + ccol[i]);
        }
        cp_commit();
    }

    for (int k0 = 0; k0 < nk; k0++) {
        if (k0 + 1 < nk) {
            int s = (k0 + 1) & 1;
            int kofs = (k0 + 1) << 6;
            __nv_bfloat16* sA = smb + s * GSTAGE;
            __nv_bfloat16* sB = smb + 2 * GSTAGE + s * GSTAGE;
            #pragma unroll
            for (int i = 0; i < 4; i++) {
                cp_async16(sA + crow[i]*GPAD + ccol[i],
                           A + (size_t)(m0 + crow[i]) * K + kofs + ccol[i]);
                cp_async16(sB + crow[i]*GPAD + ccol[i],
                           Bm + (size_t)(n0 + crow[i]) * K + kofs + ccol[i]);
            }
            cp_commit();
            cp_wait1();
        } else {
            cp_wait0();
        }
        __syncthreads();

        int s = k0 & 1;
        const __nv_bfloat16* sA = smb + s * GSTAGE;
        const __nv_bfloat16* sB = smb + 2 * GSTAGE + s * GSTAGE;

        #pragma unroll
        for (int kk = 0; kk < 4; kk++) {
            wmma::fragment<wmma::matrix_a, 16, 16, 16, __nv_bfloat16, wmma::row_major> af[4];
            wmma::fragment<wmma::matrix_b, 16, 16, 16, __nv_bfloat16, wmma::col_major> bfr[2];
            #pragma unroll
            for (int i = 0; i < 4; i++)
                wmma::load_matrix_sync(af[i], sA + (wm*64 + i*16)*GPAD + kk*16, GPAD);
            #pragma unroll
            for (int j = 0; j < 2; j++)
                wmma::load_matrix_sync(bfr[j], sB + (wn*32 + j*16)*GPAD + kk*16, GPAD);
            #pragma unroll
            for (int i = 0; i < 4; i++)
                #pragma unroll
                for (int j = 0; j < 2; j++)
                    wmma::mma_sync(acc[i][j], af[i], bfr[j], acc[i][j]);
        }
        __syncthreads();
    }

    float* Cs = (float*)smraw;     // [128][132]
    #pragma unroll
    for (int i = 0; i < 4; i++)
        #pragma unroll
        for (int j = 0; j < 2; j++)
            wmma::store_matrix_sync(Cs + (size_t)(wm*64 + i*16)*132 + wn*32 + j*16,
                                    acc[i][j], 132, wmma::mem_row_major);
    __syncthreads();

    #pragma unroll
    for (int it = 0; it < 16; it++) {
        int idx = tid + it * 256;
        int row = idx >> 5;
        int c4  = (idx & 31) * 4;
        float4 v = *(const float4*)(Cs + row*132 + c4);
        float4 bb = *(const float4*)(bias + n0 + c4);
        v.x += bb.x; v.y += bb.y; v.z += bb.z; v.w += bb.w;
        if (BF16OUT) {
            __nv_bfloat16* Cr = (__nv_bfloat16*)Cout + (size_t)(m0 + row) * N + n0 + c4;
            *(__nv_bfloat162*)(Cr)     = __floats2bfloat162_rn(v.x, v.y);
            *(__nv_bfloat162*)(Cr + 2) = __floats2bfloat162_rn(v.z, v.w);
        } else {
            float* Cr = (float*)Cout + (size_t)(m0 + row) * N + n0 + c4;
            *(float4*)Cr = v;
        }
    }
}

// ---------------------------------------------------------------------------
// 4) q/k LayerNorm (reading bf16 z, writing f16) + transpose; v transpose.
//    Q is pre-scaled by QSCALE_ (softmax exp2 domain).
// ---------------------------------------------------------------------------
__device__ __forceinline__ void ln64_warp(const __nv_bfloat16* __restrict__ src,
                                          const float* __restrict__ w,
                                          const float* __restrict__ b,
                                          __half* __restrict__ dst, int lane,
                                          float oscale)
{
    __nv_bfloat162 raw = *(const __nv_bfloat162*)(src + lane * 2);
    float2 v = make_float2(__bfloat162float(raw.x), __bfloat162float(raw.y));
    float s  = v.x + v.y;
    float ss = v.x*v.x + v.y*v.y;
    #pragma unroll
    for (int o = 16; o; o >>= 1) {
        s  += __shfl_xor_sync(0xffffffffu, s,  o);
        ss += __shfl_xor_sync(0xffffffffu, ss, o);
    }
    float mean = s * (1.0f / 64.0f);
    float var  = ss * (1.0f / 64.0f) - mean * mean;
    float rstd = rsqrtf(var + EPS_);
    float2 wv = *(const float2*)(w + lane * 2);
    float2 bv = *(const float2*)(b + lane * 2);
    float ox = ((v.x - mean) * rstd * wv.x + bv.x) * oscale;
    float oy = ((v.y - mean) * rstd * wv.y + bv.y) * oscale;
    *(__half2*)(dst + lane * 2) = __floats2half2_rn(ox, oy);
}

__global__ void __launch_bounds__(256) qkv_ln_transpose_kernel(
    const __nv_bfloat16* __restrict__ z,
    const float* __restrict__ qw, const float* __restrict__ qb,
    const float* __restrict__ kw, const float* __restrict__ kb,
    __half* __restrict__ Qo, __half* __restrict__ Ko, __half* __restrict__ Vo)
{
    int g = blockIdx.x * 8 + (threadIdx.x >> 5);   // (b, n, h) flat index
    int lane = threadIdx.x & 31;
    int b = g >> 14;
    int n = (g >> 4) & 1023;
    int h = g & 15;
    const __nv_bfloat16* zr = z + (size_t)(b * N_ + n) * O1_;
    size_t obase = ((size_t)(b * H_ + h) * N_ + n) * D_;

    ln64_warp(zr + HID_        + h*D_, qw, qb, Qo + obase, lane, QSCALE_);
    ln64_warp(zr + HID_ + C_   + h*D_, kw, kb, Ko + obase, lane, 1.0f);
    __nv_bfloat162 raw = *(const __nv_bfloat162*)(zr + HID_ + 2*C_ + h*D_ + lane * 2);
    *(__half2*)(Vo + obase + lane * 2) =
        __floats2half2_rn(__bfloat162float(raw.x), __bfloat162float(raw.y));
}

// ---------------------------------------------------------------------------
// 5) Flash attention, mma.sync f16, 128-query tile, 8 warps x 16 rows.
//    Softmax in exp2 domain (scale folded into Q), f16x2 MUFU exps.
//    Smem: Qs[128][72] + K/V double buffer 2*2*[64][72]  (f16) = 55296 B.
// ---------------------------------------------------------------------------
#define AT_PAD 72
#define ATTN_SMEM_BYTES ((128*AT_PAD + 4*64*AT_PAD) * 2)

__global__ void __launch_bounds__(256, 2) attn_mma_kernel(
    const __half* __restrict__ Qg, const __half* __restrict__ Kg,
    const __half* __restrict__ Vg, __nv_bfloat16* __restrict__ cat)
{
    extern __shared__ __align__(16) __half smh[];
    __half* Qs  = smh;                       // 128 x 72
    __half* Ks0 = Qs + 128*AT_PAD;           // 2 stages of 64 x 72
    __half* Vs0 = Ks0 + 2*64*AT_PAD;

    int bh = blockIdx.y;
    int n0 = blockIdx.x * 128;
    const __half* qg = Qg + ((size_t)bh * N_ + n0) * D_;
    const __half* kg = Kg + (size_t)bh * N_ * D_;
    const __half* vg = Vg + (size_t)bh * N_ * D_;

    int tid = threadIdx.x;
    int lane = tid & 31, wid = tid >> 5;
    int m0 = wid * 16;

    // --- load Q (group 0): 128 rows x 8 chunks = 1024 chunks
    #pragma unroll
    for (int i = 0; i < 4; i++) {
        int chunk = tid + i * 256;
        int r = chunk >> 3, c = (chunk & 7) * 8;
        cp_async16(Qs + r*AT_PAD + c, qg + r*64 + c);
    }
    cp_commit();
    // --- prefetch K/V stage 0 (group 1)
    #pragma unroll
    for (int i = 0; i < 2; i++) {
        int chunk = tid + i * 256;
        int r = chunk >> 3, c = (chunk & 7) * 8;
        cp_async16(Ks0 + r*AT_PAD + c, kg + r*64 + c);
        cp_async16(Vs0 + r*AT_PAD + c, vg + r*64 + c);
    }
    cp_commit();

    cp_wait1();            // Q complete
    __syncthreads();

    // --- Q fragments (held in regs whole kernel)
    unsigned qf[4][4];
    {
        int row = m0 + (lane & 15);
        int colb = (lane >> 4) * 8;
        #pragma unroll
        for (int kc = 0; kc < 4; kc++)
            ldmatrix_x4(qf[kc], Qs + row*AT_PAD + kc*16 + colb);
    }

    float o[8][4];
    #pragma unroll
    for (int j = 0; j < 8; j++)
        #pragma unroll
        for (int e = 0; e < 4; e++) o[j][e] = 0.f;
    float m1 = -1e30f, m2 = -1e30f, l1 = 0.f, l2 = 0.f;

    for (int kt = 0; kt < 16; kt++) {
        // prefetch next stage
        if (kt + 1 < 16) {
            int s = (kt + 1) & 1;
            const __half* kgn = kg + (size_t)(kt + 1) * 64 * D_;
            const __half* vgn = vg + (size_t)(kt + 1) * 64 * D_;
            __half* Kd = Ks0 + s * 64*AT_PAD;
            __half* Vd = Vs0 + s * 64*AT_PAD;
            #pragma unroll
            for (int i = 0; i < 2; i++) {
                int chunk = tid + i * 256;
                int r = chunk >> 3, c = (chunk & 7) * 8;
                cp_async16(Kd + r*AT_PAD + c, kgn + r*64 + c);
                cp_async16(Vd + r*AT_PAD + c, vgn + r*64 + c);
            }
            cp_commit();
            cp_wait1();
        } else {
            cp_wait0();
        }
        __syncthreads();

        const __half* Ksm = Ks0 + (kt & 1) * 64*AT_PAD;
        const __half* Vsm = Vs0 + (kt & 1) * 64*AT_PAD;

        // ---- S = Q K^T (exp2 domain, scale pre-folded into Q)
        float s[8][4];
        #pragma unroll
        for (int j = 0; j < 8; j++)
            #pragma unroll
            for (int e = 0; e < 4; e++) s[j][e] = 0.f;

        #pragma unroll
        for (int jp = 0; jp < 4; jp++) {
            int krow = jp*16 + ((lane >> 4) << 3) + (lane & 7);
            int kcol = ((lane >> 3) & 1) * 8;
            #pragma unroll
            for (int kc = 0; kc < 4; kc++) {
                unsigned kb[4];
                ldmatrix_x4(kb, Ksm + krow*AT_PAD + kc*16 + kcol);
                mma16816(s[2*jp],   qf[kc], kb[0], kb[1]);
                mma16816(s[2*jp+1], qf[kc], kb[2], kb[3]);
            }
        }

        // ---- online softmax (rows r1 = m0+lane/4, r2 = r1+8)
        float mx1 = -1e30f, mx2 = -1e30f;
        #pragma unroll
        for (int j = 0; j < 8; j++) {
            mx1 = fmaxf(mx1, fmaxf(s[j][0], s[j][1]));
            mx2 = fmaxf(mx2, fmaxf(s[j][2], s[j][3]));
        }
        mx1 = fmaxf(mx1, __shfl_xor_sync(0xffffffffu, mx1, 1));
        mx1 = fmaxf(mx1, __shfl_xor_sync(0xffffffffu, mx1, 2));
        mx2 = fmaxf(mx2, __shfl_xor_sync(0xffffffffu, mx2, 1));
        mx2 = fmaxf(mx2, __shfl_xor_sync(0xffffffffu, mx2, 2));
        float mn1 = fmaxf(m1, mx1), mn2 = fmaxf(m2, mx2);
        float f1 = exp2f(m1 - mn1), f2 = exp2f(m2 - mn2);
        m1 = mn1; m2 = mn2;

        __half2 ph[8][2];
        __half2 a1 = __floats2half2_rn(0.f, 0.f);
        __half2 a2 = a1;
        #pragma unroll
        for (int j = 0; j < 8; j++) {
            ph[j][0] = h2exp2(__floats2half2_rn(s[j][0] - m1, s[j][1] - m1));
            ph[j][1] = h2exp2(__floats2half2_rn(s[j][2] - m2, s[j][3] - m2));
            a1 = __hadd2(a1, ph[j][0]);
            a2 = __hadd2(a2, ph[j][1]);
        }
        float sum1 = __low2float(a1) + __high2float(a1);
        float sum2 = __low2float(a2) + __high2float(a2);
        sum1 += __shfl_xor_sync(0xffffffffu, sum1, 1);
        sum1 += __shfl_xor_sync(0xffffffffu, sum1, 2);
        sum2 += __shfl_xor_sync(0xffffffffu, sum2, 1);
        sum2 += __shfl_xor_sync(0xffffffffu, sum2, 2);
        l1 = l1 * f1 + sum1;
        l2 = l2 * f2 + sum2;

        // rescale O
        #pragma unroll
        for (int j = 0; j < 8; j++) {
            o[j][0] *= f1; o[j][1] *= f1;
            o[j][2] *= f2; o[j][3] *= f2;
        }

        // ---- O += P V
        #pragma unroll
        for (int dp = 0; dp < 4; dp++) {
            int vcolb = dp*16 + (lane >> 4) * 8;
            int vrowb = ((lane >> 3) & 1) * 8 + (lane & 7);
            #pragma unroll
            for (int kc = 0; kc < 4; kc++) {
                unsigned vb[4];
                ldmatrix_x4_trans(vb, Vsm + (kc*16 + vrowb)*AT_PAD + vcolb);
                unsigned pa[4] = {
                    *(unsigned*)&ph[2*kc][0],   *(unsigned*)&ph[2*kc][1],
                    *(unsigned*)&ph[2*kc+1][0], *(unsigned*)&ph[2*kc+1][1] };
                mma16816(o[2*dp],   pa, vb[0], vb[1]);
                mma16816(o[2*dp+1], pa, vb[2], vb[3]);
            }
        }
        __syncthreads();
    }

    // ---- write output to cat[:, HID + h*64 + d]
    int b = bh >> 4, h = bh & 15;
    int r1 = lane >> 2, coff = (lane & 3) * 2;
    float inv1 = 1.0f / l1, inv2 = 1.0f / l2;
    size_t row1 = (size_t)b * N_ + n0 + m0 + r1;
    size_t row2 = row1 + 8;
    __nv_bfloat16* c1 = cat + row1 * F_ + HID_ + h * 64 + coff;
    __nv_bfloat16* c2 = cat + row2 * F_ + HID_ + h * 64 + coff;
    #pragma unroll
    for (int jd = 0; jd < 8; jd++) {
        *(__nv_bfloat162*)(c1 + jd*8) = __floats2bfloat162_rn(o[jd][0]*inv1, o[jd][1]*inv1);
        *(__nv_bfloat162*)(c2 + jd*8) = __floats2bfloat162_rn(o[jd][2]*inv2, o[jd][3]*inv2);
    }
}

// ---------------------------------------------------------------------------
// 6) GELU (exact, bf16 in/out)
// ---------------------------------------------------------------------------
__global__ void __launch_bounds__(256) gelu_kernel(
    const __nv_bfloat16* __restrict__ z, __nv_bfloat16* __restrict__ cat)
{
    int idx = blockIdx.x * blockDim.x + threadIdx.x;
    int row  = idx >> 10;
    int col4 = idx & 1023;
    const __nv_bfloat16* zp = z + (size_t)row * O1_ + col4 * 4;
    __nv_bfloat162 a = *(const __nv_bfloat162*)(zp);
    __nv_bfloat162 b = *(const __nv_bfloat162*)(zp + 2);
    float vx = __bfloat162float(a.x), vy = __bfloat162float(a.y);
    float vz = __bfloat162float(b.x), vw = __bfloat162float(b.y);
    vx *= normcdff(vx);
    vy *= normcdff(vy);
    vz *= normcdff(vz);
    vw *= normcdff(vw);
    __nv_bfloat16* cp = cat + (size_t)row * F_ + col4 * 4;
    *(__nv_bfloat162*)(cp)     = __floats2bfloat162_rn(vx, vy);
    *(__nv_bfloat162*)(cp + 2) = __floats2bfloat162_rn(vz, vw);
}

// ---------------------------------------------------------------------------
// 7) Final: out = x + ls_gamma * (o2[:, :C] + o2[:, C:])
// ---------------------------------------------------------------------------
__global__ void __launch_bounds__(256) final_kernel(
    const float* __restrict__ x, const float* __restrict__ o2,
    const float* __restrict__ lsg, float* __restrict__ out)
{
    int idx = blockIdx.x * blockDim.x + threadIdx.x;
    int row  = idx >> 8;
    int col4 = idx & 255;
    int c = col4 * 4;
    float4 xv = *(const float4*)(x + (size_t)row * C_ + c);
    float4 a  = *(const float4*)(o2 + (size_t)row * O2_ + c);
    float4 b  = *(const float4*)(o2 + (size_t)row * O2_ + C_ + c);
    float4 g  = *(const float4*)(lsg + c);
    float4 r;
    r.x = xv.x + g.x * (a.x + b.x);
    r.y = xv.y + g.y * (a.y + b.y);
    r.z = xv.z + g.z * (a.z + b.z);
    r.w = xv.w + g.w * (a.w + b.w);
    *(float4*)(out + (size_t)row * C_ + c) = r;
}

// ---------------------------------------------------------------------------
// launch
// ---------------------------------------------------------------------------
extern "C" void kernel_launch(void* const* d_in, const int* in_sizes, int n_in,
                              void* d_out, int out_size)
{
    const float* x          = (const float*)d_in[0];
    const float* in_norm_w  = (const float*)d_in[1];
    const float* in_norm_b  = (const float*)d_in[2];
    const float* in_proj_w  = (const float*)d_in[3];
    const float* mlp_bias   = (const float*)d_in[4];
    const float* q_norm_w   = (const float*)d_in[5];
    const float* q_norm_b   = (const float*)d_in[6];
    const float* k_norm_w   = (const float*)d_in[7];
    const float* k_norm_b   = (const float*)d_in[8];
    const float* out_proj_w = (const float*)d_in[9];
    const float* out_proj_b = (const float*)d_in[10];
    const float* ls_gamma   = (const float*)d_in[11];
    float* out = (float*)d_out;

    __nv_bfloat16 *y, *z, *w1, *w2, *cat;
    __half *qT, *kT, *vT;
    float *o2, *bias1;
    cudaGetSymbolAddress((void**)&y,     g_y);
    cudaGetSymbolAddress((void**)&z,     g_z);
    cudaGetSymbolAddress((void**)&w1,    g_w1);
    cudaGetSymbolAddress((void**)&w2,    g_w2);
    cudaGetSymbolAddress((void**)&cat,   g_cat);
    cudaGetSymbolAddress((void**)&qT,    g_qT);
    cudaGetSymbolAddress((void**)&kT,    g_kT);
    cudaGetSymbolAddress((void**)&vT,    g_vT);
    cudaGetSymbolAddress((void**)&o2,    g_o2);
    cudaGetSymbolAddress((void**)&bias1, g_bias1);

    cudaFuncSetAttribute(attn_mma_kernel,
                         cudaFuncAttributeMaxDynamicSharedMemorySize,
                         ATTN_SMEM_BYTES);
    cudaFuncSetAttribute(wmma_gemm_nt<true>,
                         cudaFuncAttributeMaxDynamicSharedMemorySize,
                         GEMM_SMEM_BYTES);
    cudaFuncSetAttribute(wmma_gemm_nt<false>,
                         cudaFuncAttributeMaxDynamicSharedMemorySize,
                         GEMM_SMEM_BYTES);

    // 0) weight conversion fp32 -> bf16
    f2bf_kernel<<<(O1_*C_/4 + 255)/256, 256>>>(in_proj_w, w1, O1_*C_/4);
    f2bf_kernel<<<(O2_*F_/4 + 255)/256, 256>>>(out_proj_w, w2, O2_*F_/4);

    // 1) input LN -> y (bf16)
    ln_in_kernel<<<M_, 256>>>(x, in_norm_w, in_norm_b, y);

    // 2) bias1
    build_bias1_kernel<<<(O1_ + 255) / 256, 256>>>(mlp_bias, bias1);

    // 3) z = y @ w1^T + bias1  (bf16 out)
    wmma_gemm_nt<true><<<dim3(O1_ / 128, M_ / 128), 256, GEMM_SMEM_BYTES>>>(
        y, w1, bias1, z, M_, O1_, C_);

    // 4) q/k LN + transpose (f16, Q pre-scaled), v transpose
    qkv_ln_transpose_kernel<<<(B_*N_*H_) / 8, 256>>>(
        z, q_norm_w, q_norm_b, k_norm_w, k_norm_b, qT, kT, vT);

    // 5) attention -> cat[:, HID:] (bf16)
    attn_mma_kernel<<<dim3(N_ / 128, B_ * H_), 256, ATTN_SMEM_BYTES>>>(
        qT, kT, vT, cat);

    // 6) gelu -> cat[:, :HID] (bf16)
    gelu_kernel<<<(M_ * (HID_ / 4)) / 256, 256>>>(z, cat);

    // 7) o2 = cat @ w2^T + out_proj_b  (fp32 out)
    wmma_gemm_nt<false><<<dim3(O2_ / 128, M_ / 128), 256, GEMM_SMEM_BYTES>>>(
        cat, w2, out_proj_b, o2, M_, O2_, F_);

    // 8) residual + layer scale
    final_kernel<<<(M_ * (C_ / 4)) / 256, 256>>>(x, o2, ls_gamma, out);
}

// round 13
// speedup vs baseline: 6.1559x; 1.0898x over previous
#include <cuda_runtime.h>
#include <cuda_bf16.h>
#include <cuda_fp16.h>
#include <mma.h>
#include <math.h>
#include <cstdint>

using namespace nvcuda;

// ---------------------------------------------------------------------------
// Problem dims (fixed)
// ---------------------------------------------------------------------------
#define B_   8
#define N_   1024
#define C_   1024
#define H_   16
#define D_   64
#define HID_ 4096
#define M_   (B_*N_)            // 8192 rows
#define O1_  (HID_ + 3*C_)      // 7168  (in_proj out)
#define F_   (HID_ + C_)        // 5120  (cat width)
#define O2_  (2*C_)             // 2048  (out_proj out)
#define EPS_ 1e-5f
// 1/sqrt(64) * log2(e), folded into Q so softmax works in exp2 domain
#define QSCALE_ 0.18033688011112042f

// ---------------------------------------------------------------------------
// Scratch (device globals)
// ---------------------------------------------------------------------------
__device__ __nv_bfloat16 g_y[(size_t)M_ * C_];        // LN(x) bf16        16 MB
__device__ __nv_bfloat16 g_z[(size_t)M_ * O1_];       // qkv cols only    117 MB
__device__ __nv_bfloat16 g_w1[(size_t)O1_ * C_];      // in_proj_w bf16    14 MB
__device__ __nv_bfloat16 g_w2[(size_t)O2_ * F_];      // out_proj_w bf16   21 MB
__device__ __nv_bfloat16 g_cat[(size_t)M_ * F_];      // [gelu | attn]     80 MB
__device__ __half g_qT[(size_t)B_*H_*N_*D_];          // f16               16 MB
__device__ __half g_kT[(size_t)B_*H_*N_*D_];          //                   16 MB
__device__ __half g_vT[(size_t)B_*H_*N_*D_];          //                   16 MB
__device__ float g_o2[(size_t)M_ * O2_];              // out_proj out      64 MB
__device__ float g_bias1[O1_];                        // concat(0(3C), mlp_bias)

// ---------------------------------------------------------------------------
// helpers
// ---------------------------------------------------------------------------
__device__ __forceinline__ unsigned smem_u32(const void* p) {
    return (unsigned)__cvta_generic_to_shared(p);
}
__device__ __forceinline__ void cp_async16(void* dst, const void* src) {
    asm volatile("cp.async.cg.shared.global [%0], [%1], 16;\n"
                 :: "r"(smem_u32(dst)), "l"(src));
}
__device__ __forceinline__ void cp_commit() {
    asm volatile("cp.async.commit_group;\n" ::: "memory");
}
__device__ __forceinline__ void cp_wait0() {
    asm volatile("cp.async.wait_group 0;\n" ::: "memory");
}
__device__ __forceinline__ void cp_wait1() {
    asm volatile("cp.async.wait_group 1;\n" ::: "memory");
}
__device__ __forceinline__ void ldmatrix_x4(unsigned* r, const void* p) {
    asm volatile("ldmatrix.sync.aligned.m8n8.x4.shared.b16 {%0,%1,%2,%3}, [%4];\n"
                 : "=r"(r[0]), "=r"(r[1]), "=r"(r[2]), "=r"(r[3])
                 : "r"(smem_u32(p)));
}
__device__ __forceinline__ void ldmatrix_x4_trans(unsigned* r, const void* p) {
    asm volatile("ldmatrix.sync.aligned.m8n8.x4.trans.shared.b16 {%0,%1,%2,%3}, [%4];\n"
                 : "=r"(r[0]), "=r"(r[1]), "=r"(r[2]), "=r"(r[3])
                 : "r"(smem_u32(p)));
}
__device__ __forceinline__ void mma16816(float* c, const unsigned* a,
                                         unsigned b0, unsigned b1) {
    asm volatile("mma.sync.aligned.m16n8k16.row.col.f32.f16.f16.f32 "
                 "{%0,%1,%2,%3}, {%4,%5,%6,%7}, {%8,%9}, {%0,%1,%2,%3};\n"
                 : "+f"(c[0]), "+f"(c[1]), "+f"(c[2]), "+f"(c[3])
                 : "r"(a[0]), "r"(a[1]), "r"(a[2]), "r"(a[3]),
                   "r"(b0), "r"(b1));
}

// FFMA-pipe fast exp2 (no MUFU). x <= 0 expected; rel err ~4e-5.
// Magic-constant round-to-nearest + degree-4 poly on [-0.5,0.5] + exponent splice.
__device__ __forceinline__ float fexp2(float x) {
    x = fmaxf(x, -100.0f);
    float t = x + 12582912.0f;            // 1.5 * 2^23
    int   i = __float_as_int(t);          // low bits hold round(x)
    float fl = t - 12582912.0f;           // round(x)
    float fr = x - fl;                    // [-0.5, 0.5]
    // 2^fr, Taylor deg-4: err ~4e-5 on [-0.5,0.5]
    float p = 0.0096181f;
    p = fmaf(p, fr, 0.0555041f);
    p = fmaf(p, fr, 0.2402265f);
    p = fmaf(p, fr, 0.6931472f);
    p = fmaf(p, fr, 1.0f);
    return __int_as_float(__float_as_int(p) + (i << 23));
}

// exact GELU via erff (polynomial, no MUFU in fast path)
__device__ __forceinline__ float gelu_exact(float v) {
    return 0.5f * v * (1.0f + erff(v * 0.7071067811865475f));
}

// ---------------------------------------------------------------------------
// fp32 -> bf16 conversion (for weights)
// ---------------------------------------------------------------------------
__global__ void __launch_bounds__(256) f2bf_kernel(
    const float* __restrict__ in, __nv_bfloat16* __restrict__ out, int n4)
{
    int i = blockIdx.x * blockDim.x + threadIdx.x;
    if (i >= n4) return;
    float4 v = ((const float4*)in)[i];
    __nv_bfloat162 a = __floats2bfloat162_rn(v.x, v.y);
    __nv_bfloat162 b = __floats2bfloat162_rn(v.z, v.w);
    ((__nv_bfloat162*)out)[i*2]   = a;
    ((__nv_bfloat162*)out)[i*2+1] = b;
}

// ---------------------------------------------------------------------------
// 1) Input LayerNorm
// ---------------------------------------------------------------------------
__global__ void __launch_bounds__(256) ln_in_kernel(
    const float* __restrict__ x, const float* __restrict__ w,
    const float* __restrict__ b, __nv_bfloat16* __restrict__ y)
{
    int row = blockIdx.x;
    const float4* xr = (const float4*)(x + (size_t)row * C_);
    float4 v = xr[threadIdx.x];
    float s  = v.x + v.y + v.z + v.w;
    float ss = v.x*v.x + v.y*v.y + v.z*v.z + v.w*v.w;

    #pragma unroll
    for (int o = 16; o; o >>= 1) {
        s  += __shfl_xor_sync(0xffffffffu, s,  o);
        ss += __shfl_xor_sync(0xffffffffu, ss, o);
    }
    __shared__ float sb[8], ssb[8];
    int wid = threadIdx.x >> 5, lane = threadIdx.x & 31;
    if (lane == 0) { sb[wid] = s; ssb[wid] = ss; }
    __syncthreads();
    __shared__ float s_mean, s_rstd;
    if (threadIdx.x == 0) {
        float t = 0.f, ts = 0.f;
        #pragma unroll
        for (int i = 0; i < 8; i++) { t += sb[i]; ts += ssb[i]; }
        float mean = t * (1.0f / C_);
        float var  = ts * (1.0f / C_) - mean * mean;
        s_mean = mean;
        s_rstd = rsqrtf(var + EPS_);
    }
    __syncthreads();
    float mean = s_mean, rstd = s_rstd;
    float4 wq = ((const float4*)w)[threadIdx.x];
    float4 bq = ((const float4*)b)[threadIdx.x];
    float ox = (v.x - mean) * rstd * wq.x + bq.x;
    float oy = (v.y - mean) * rstd * wq.y + bq.y;
    float oz = (v.z - mean) * rstd * wq.z + bq.z;
    float ow = (v.w - mean) * rstd * wq.w + bq.w;
    __nv_bfloat16* yr = y + (size_t)row * C_ + threadIdx.x * 4;
    *(__nv_bfloat162*)(yr)     = __floats2bfloat162_rn(ox, oy);
    *(__nv_bfloat162*)(yr + 2) = __floats2bfloat162_rn(oz, ow);
}

// ---------------------------------------------------------------------------
// 2) bias1 = concat(zeros(3C), mlp_bias)
// ---------------------------------------------------------------------------
__global__ void build_bias1_kernel(const float* __restrict__ mlp_bias,
                                   float* __restrict__ bias1)
{
    int o = blockIdx.x * blockDim.x + threadIdx.x;
    if (o < O1_) bias1[o] = (o < 3*C_) ? 0.f : mlp_bias[o - 3*C_];
}

// ---------------------------------------------------------------------------
// 3) bf16 WMMA GEMM: C[M,N] = A[M,K] * B[N,K]^T + bias[N]
//    MODE 0: GEMM1 fused epilogue (n0 < HID -> gelu into cat; else bf16 z)
//    MODE 1: fp32 output (GEMM2)
// ---------------------------------------------------------------------------
#define GPAD   72
#define GSTAGE (128 * GPAD)
#define GEMM_SMEM_BYTES (4 * GSTAGE * 2)

template<int MODE>
__global__ void __launch_bounds__(256) wmma_gemm_nt(
    const __nv_bfloat16* __restrict__ A, const __nv_bfloat16* __restrict__ Bm,
    const float* __restrict__ bias, void* __restrict__ Cout,
    __nv_bfloat16* __restrict__ catOut,
    int M, int N, int K)
{
    extern __shared__ __align__(16) char smraw[];
    __nv_bfloat16* smb = (__nv_bfloat16*)smraw;

    int tid = threadIdx.x;
    int m0 = blockIdx.y * 128;
    int n0 = blockIdx.x * 128;

    int wid = tid >> 5;
    int wm = wid >> 2;
    int wn = wid & 3;

    int crow[4], ccol[4];
    #pragma unroll
    for (int i = 0; i < 4; i++) {
        int chunk = tid + i * 256;
        crow[i] = chunk >> 3;
        ccol[i] = (chunk & 7) * 8;
    }

    wmma::fragment<wmma::accumulator, 16, 16, 16, float> acc[4][2];
    #pragma unroll
    for (int i = 0; i < 4; i++)
        #pragma unroll
        for (int j = 0; j < 2; j++)
            wmma::fill_fragment(acc[i][j], 0.0f);

    int nk = K >> 6;

    {
        __nv_bfloat16* sA = smb;
        __nv_bfloat16* sB = smb + 2 * GSTAGE;
        #pragma unroll
        for (int i = 0; i < 4; i++) {
            cp_async16(sA + crow[i]*GPAD + ccol[i],
                       A + (size_t)(m0 + crow[i]) * K + ccol[i]);
            cp_async16(sB + crow[i]*GPAD + ccol[i],
                       Bm + (size_t)(n0 + crow[i]) * K + ccol[i]);
        }
        cp_commit();
    }

    for (int k0 = 0; k0 < nk; k0++) {
        if (k0 + 1 < nk) {
            int s = (k0 + 1) & 1;
            int kofs = (k0 + 1) << 6;
            __nv_bfloat16* sA = smb + s * GSTAGE;
            __nv_bfloat16* sB = smb + 2 * GSTAGE + s * GSTAGE;
            #pragma unroll
            for (int i = 0; i < 4; i++) {
                cp_async16(sA + crow[i]*GPAD + ccol[i],
                           A + (size_t)(m0 + crow[i]) * K + kofs + ccol[i]);
                cp_async16(sB + crow[i]*GPAD + ccol[i],
                           Bm + (size_t)(n0 + crow[i]) * K + kofs + ccol[i]);
            }
            cp_commit();
            cp_wait1();
        } else {
            cp_wait0();
        }
        __syncthreads();

        int s = k0 & 1;
        const __nv_bfloat16* sA = smb + s * GSTAGE;
        const __nv_bfloat16* sB = smb + 2 * GSTAGE + s * GSTAGE;

        #pragma unroll
        for (int kk = 0; kk < 4; kk++) {
            wmma::fragment<wmma::matrix_a, 16, 16, 16, __nv_bfloat16, wmma::row_major> af[4];
            wmma::fragment<wmma::matrix_b, 16, 16, 16, __nv_bfloat16, wmma::col_major> bfr[2];
            #pragma unroll
            for (int i = 0; i < 4; i++)
                wmma::load_matrix_sync(af[i], sA + (wm*64 + i*16)*GPAD + kk*16, GPAD);
            #pragma unroll
            for (int j = 0; j < 2; j++)
                wmma::load_matrix_sync(bfr[j], sB + (wn*32 + j*16)*GPAD + kk*16, GPAD);
            #pragma unroll
            for (int i = 0; i < 4; i++)
                #pragma unroll
                for (int j = 0; j < 2; j++)
                    wmma::mma_sync(acc[i][j], af[i], bfr[j], acc[i][j]);
        }
        __syncthreads();
    }

    float* Cs = (float*)smraw;     // [128][132]
    #pragma unroll
    for (int i = 0; i < 4; i++)
        #pragma unroll
        for (int j = 0; j < 2; j++)
            wmma::store_matrix_sync(Cs + (size_t)(wm*64 + i*16)*132 + wn*32 + j*16,
                                    acc[i][j], 132, wmma::mem_row_major);
    __syncthreads();

    bool mlp_tile = (MODE == 0) && (n0 < HID_);

    #pragma unroll
    for (int it = 0; it < 16; it++) {
        int idx = tid + it * 256;
        int row = idx >> 5;
        int c4  = (idx & 31) * 4;
        float4 v = *(const float4*)(Cs + row*132 + c4);
        float4 bb = *(const float4*)(bias + n0 + c4);
        v.x += bb.x; v.y += bb.y; v.z += bb.z; v.w += bb.w;
        if (MODE == 1) {
            float* Cr = (float*)Cout + (size_t)(m0 + row) * N + n0 + c4;
            *(float4*)Cr = v;
        } else if (mlp_tile) {
            // fused exact GELU -> cat[:, n0+c4]
            v.x = gelu_exact(v.x); v.y = gelu_exact(v.y);
            v.z = gelu_exact(v.z); v.w = gelu_exact(v.w);
            __nv_bfloat16* Cr = catOut + (size_t)(m0 + row) * F_ + n0 + c4;
            *(__nv_bfloat162*)(Cr)     = __floats2bfloat162_rn(v.x, v.y);
            *(__nv_bfloat162*)(Cr + 2) = __floats2bfloat162_rn(v.z, v.w);
        } else {
            __nv_bfloat16* Cr = (__nv_bfloat16*)Cout + (size_t)(m0 + row) * N + n0 + c4;
            *(__nv_bfloat162*)(Cr)     = __floats2bfloat162_rn(v.x, v.y);
            *(__nv_bfloat162*)(Cr + 2) = __floats2bfloat162_rn(v.z, v.w);
        }
    }
}

// ---------------------------------------------------------------------------
// 4) q/k LayerNorm (reading bf16 z, writing f16) + transpose; v transpose.
// ---------------------------------------------------------------------------
__device__ __forceinline__ void ln64_warp(const __nv_bfloat16* __restrict__ src,
                                          const float* __restrict__ w,
                                          const float* __restrict__ b,
                                          __half* __restrict__ dst, int lane,
                                          float oscale)
{
    __nv_bfloat162 raw = *(const __nv_bfloat162*)(src + lane * 2);
    float2 v = make_float2(__bfloat162float(raw.x), __bfloat162float(raw.y));
    float s  = v.x + v.y;
    float ss = v.x*v.x + v.y*v.y;
    #pragma unroll
    for (int o = 16; o; o >>= 1) {
        s  += __shfl_xor_sync(0xffffffffu, s,  o);
        ss += __shfl_xor_sync(0xffffffffu, ss, o);
    }
    float mean = s * (1.0f / 64.0f);
    float var  = ss * (1.0f / 64.0f) - mean * mean;
    float rstd = rsqrtf(var + EPS_);
    float2 wv = *(const float2*)(w + lane * 2);
    float2 bv = *(const float2*)(b + lane * 2);
    float ox = ((v.x - mean) * rstd * wv.x + bv.x) * oscale;
    float oy = ((v.y - mean) * rstd * wv.y + bv.y) * oscale;
    *(__half2*)(dst + lane * 2) = __floats2half2_rn(ox, oy);
}

__global__ void __launch_bounds__(256) qkv_ln_transpose_kernel(
    const __nv_bfloat16* __restrict__ z,
    const float* __restrict__ qw, const float* __restrict__ qb,
    const float* __restrict__ kw, const float* __restrict__ kb,
    __half* __restrict__ Qo, __half* __restrict__ Ko, __half* __restrict__ Vo)
{
    int g = blockIdx.x * 8 + (threadIdx.x >> 5);   // (b, n, h) flat index
    int lane = threadIdx.x & 31;
    int b = g >> 14;
    int n = (g >> 4) & 1023;
    int h = g & 15;
    const __nv_bfloat16* zr = z + (size_t)(b * N_ + n) * O1_;
    size_t obase = ((size_t)(b * H_ + h) * N_ + n) * D_;

    ln64_warp(zr + HID_        + h*D_, qw, qb, Qo + obase, lane, QSCALE_);
    ln64_warp(zr + HID_ + C_   + h*D_, kw, kb, Ko + obase, lane, 1.0f);
    __nv_bfloat162 raw = *(const __nv_bfloat162*)(zr + HID_ + 2*C_ + h*D_ + lane * 2);
    *(__half2*)(Vo + obase + lane * 2) =
        __floats2half2_rn(__bfloat162float(raw.x), __bfloat162float(raw.y));
}

// ---------------------------------------------------------------------------
// 5) Flash attention, mma.sync f16, FFMA-pipe exp2 (no MUFU in hot path)
// ---------------------------------------------------------------------------
#define AT_PAD 72
#define ATTN_SMEM_BYTES ((128*AT_PAD + 4*64*AT_PAD) * 2)

__global__ void __launch_bounds__(256, 2) attn_mma_kernel(
    const __half* __restrict__ Qg, const __half* __restrict__ Kg,
    const __half* __restrict__ Vg, __nv_bfloat16* __restrict__ cat)
{
    extern __shared__ __align__(16) __half smh[];
    __half* Qs  = smh;
    __half* Ks0 = Qs + 128*AT_PAD;
    __half* Vs0 = Ks0 + 2*64*AT_PAD;

    int bh = blockIdx.y;
    int n0 = blockIdx.x * 128;
    const __half* qg = Qg + ((size_t)bh * N_ + n0) * D_;
    const __half* kg = Kg + (size_t)bh * N_ * D_;
    const __half* vg = Vg + (size_t)bh * N_ * D_;

    int tid = threadIdx.x;
    int lane = tid & 31, wid = tid >> 5;
    int m0 = wid * 16;

    #pragma unroll
    for (int i = 0; i < 4; i++) {
        int chunk = tid + i * 256;
        int r = chunk >> 3, c = (chunk & 7) * 8;
        cp_async16(Qs + r*AT_PAD + c, qg + r*64 + c);
    }
    cp_commit();
    #pragma unroll
    for (int i = 0; i < 2; i++) {
        int chunk = tid + i * 256;
        int r = chunk >> 3, c = (chunk & 7) * 8;
        cp_async16(Ks0 + r*AT_PAD + c, kg + r*64 + c);
        cp_async16(Vs0 + r*AT_PAD + c, vg + r*64 + c);
    }
    cp_commit();

    cp_wait1();
    __syncthreads();

    unsigned qf[4][4];
    {
        int row = m0 + (lane & 15);
        int colb = (lane >> 4) * 8;
        #pragma unroll
        for (int kc = 0; kc < 4; kc++)
            ldmatrix_x4(qf[kc], Qs + row*AT_PAD + kc*16 + colb);
    }

    float o[8][4];
    #pragma unroll
    for (int j = 0; j < 8; j++)
        #pragma unroll
        for (int e = 0; e < 4; e++) o[j][e] = 0.f;
    float m1 = -1e30f, m2 = -1e30f, l1 = 0.f, l2 = 0.f;

    for (int kt = 0; kt < 16; kt++) {
        if (kt + 1 < 16) {
            int s = (kt + 1) & 1;
            const __half* kgn = kg + (size_t)(kt + 1) * 64 * D_;
            const __half* vgn = vg + (size_t)(kt + 1) * 64 * D_;
            __half* Kd = Ks0 + s * 64*AT_PAD;
            __half* Vd = Vs0 + s * 64*AT_PAD;
            #pragma unroll
            for (int i = 0; i < 2; i++) {
                int chunk = tid + i * 256;
                int r = chunk >> 3, c = (chunk & 7) * 8;
                cp_async16(Kd + r*AT_PAD + c, kgn + r*64 + c);
                cp_async16(Vd + r*AT_PAD + c, vgn + r*64 + c);
            }
            cp_commit();
            cp_wait1();
        } else {
            cp_wait0();
        }
        __syncthreads();

        const __half* Ksm = Ks0 + (kt & 1) * 64*AT_PAD;
        const __half* Vsm = Vs0 + (kt & 1) * 64*AT_PAD;

        float s[8][4];
        #pragma unroll
        for (int j = 0; j < 8; j++)
            #pragma unroll
            for (int e = 0; e < 4; e++) s[j][e] = 0.f;

        #pragma unroll
        for (int jp = 0; jp < 4; jp++) {
            int krow = jp*16 + ((lane >> 4) << 3) + (lane & 7);
            int kcol = ((lane >> 3) & 1) * 8;
            #pragma unroll
            for (int kc = 0; kc < 4; kc++) {
                unsigned kb[4];
                ldmatrix_x4(kb, Ksm + krow*AT_PAD + kc*16 + kcol);
                mma16816(s[2*jp],   qf[kc], kb[0], kb[1]);
                mma16816(s[2*jp+1], qf[kc], kb[2], kb[3]);
            }
        }

        float mx1 = -1e30f, mx2 = -1e30f;
        #pragma unroll
        for (int j = 0; j < 8; j++) {
            mx1 = fmaxf(mx1, fmaxf(s[j][0], s[j][1]));
            mx2 = fmaxf(mx2, fmaxf(s[j][2], s[j][3]));
        }
        mx1 = fmaxf(mx1, __shfl_xor_sync(0xffffffffu, mx1, 1));
        mx1 = fmaxf(mx1, __shfl_xor_sync(0xffffffffu, mx1, 2));
        mx2 = fmaxf(mx2, __shfl_xor_sync(0xffffffffu, mx2, 1));
        mx2 = fmaxf(mx2, __shfl_xor_sync(0xffffffffu, mx2, 2));
        float mn1 = fmaxf(m1, mx1), mn2 = fmaxf(m2, mx2);
        float f1 = fexp2(m1 - mn1), f2 = fexp2(m2 - mn2);
        m1 = mn1; m2 = mn2;

        // exp via FFMA-pipe fast exp2, sums in fp32
        __half2 ph[8][2];
        float sum1 = 0.f, sum2 = 0.f;
        #pragma unroll
        for (int j = 0; j < 8; j++) {
            float p0 = fexp2(s[j][0] - m1);
            float p1 = fexp2(s[j][1] - m1);
            float p2 = fexp2(s[j][2] - m2);
            float p3 = fexp2(s[j][3] - m2);
            ph[j][0] = __floats2half2_rn(p0, p1);
            ph[j][1] = __floats2half2_rn(p2, p3);
            sum1 += p0 + p1;
            sum2 += p2 + p3;
        }
        sum1 += __shfl_xor_sync(0xffffffffu, sum1, 1);
        sum1 += __shfl_xor_sync(0xffffffffu, sum1, 2);
        sum2 += __shfl_xor_sync(0xffffffffu, sum2, 1);
        sum2 += __shfl_xor_sync(0xffffffffu, sum2, 2);
        l1 = l1 * f1 + sum1;
        l2 = l2 * f2 + sum2;

        #pragma unroll
        for (int j = 0; j < 8; j++) {
            o[j][0] *= f1; o[j][1] *= f1;
            o[j][2] *= f2; o[j][3] *= f2;
        }

        #pragma unroll
        for (int dp = 0; dp < 4; dp++) {
            int vcolb = dp*16 + (lane >> 4) * 8;
            int vrowb = ((lane >> 3) & 1) * 8 + (lane & 7);
            #pragma unroll
            for (int kc = 0; kc < 4; kc++) {
                unsigned vb[4];
                ldmatrix_x4_trans(vb, Vsm + (kc*16 + vrowb)*AT_PAD + vcolb);
                unsigned pa[4] = {
                    *(unsigned*)&ph[2*kc][0],   *(unsigned*)&ph[2*kc][1],
                    *(unsigned*)&ph[2*kc+1][0], *(unsigned*)&ph[2*kc+1][1] };
                mma16816(o[2*dp],   pa, vb[0], vb[1]);
                mma16816(o[2*dp+1], pa, vb[2], vb[3]);
            }
        }
        __syncthreads();
    }

    int b = bh >> 4, h = bh & 15;
    int r1 = lane >> 2, coff = (lane & 3) * 2;
    float inv1 = 1.0f / l1, inv2 = 1.0f / l2;
    size_t row1 = (size_t)b * N_ + n0 + m0 + r1;
    size_t row2 = row1 + 8;
    __nv_bfloat16* c1 = cat + row1 * F_ + HID_ + h * 64 + coff;
    __nv_bfloat16* c2 = cat + row2 * F_ + HID_ + h * 64 + coff;
    #pragma unroll
    for (int jd = 0; jd < 8; jd++) {
        *(__nv_bfloat162*)(c1 + jd*8) = __floats2bfloat162_rn(o[jd][0]*inv1, o[jd][1]*inv1);
        *(__nv_bfloat162*)(c2 + jd*8) = __floats2bfloat162_rn(o[jd][2]*inv2, o[jd][3]*inv2);
    }
}

// ---------------------------------------------------------------------------
// 7) Final: out = x + ls_gamma * (o2[:, :C] + o2[:, C:])
// ---------------------------------------------------------------------------
__global__ void __launch_bounds__(256) final_kernel(
    const float* __restrict__ x, const float* __restrict__ o2,
    const float* __restrict__ lsg, float* __restrict__ out)
{
    int idx = blockIdx.x * blockDim.x + threadIdx.x;
    int row  = idx >> 8;
    int col4 = idx & 255;
    int c = col4 * 4;
    float4 xv = *(const float4*)(x + (size_t)row * C_ + c);
    float4 a  = *(const float4*)(o2 + (size_t)row * O2_ + c);
    float4 b  = *(const float4*)(o2 + (size_t)row * O2_ + C_ + c);
    float4 g  = *(const float4*)(lsg + c);
    float4 r;
    r.x = xv.x + g.x * (a.x + b.x);
    r.y = xv.y + g.y * (a.y + b.y);
    r.z = xv.z + g.z * (a.z + b.z);
    r.w = xv.w + g.w * (a.w + b.w);
    *(float4*)(out + (size_t)row * C_ + c) = r;
}

// ---------------------------------------------------------------------------
// launch
// ---------------------------------------------------------------------------
extern "C" void kernel_launch(void* const* d_in, const int* in_sizes, int n_in,
                              void* d_out, int out_size)
{
    const float* x          = (const float*)d_in[0];
    const float* in_norm_w  = (const float*)d_in[1];
    const float* in_norm_b  = (const float*)d_in[2];
    const float* in_proj_w  = (const float*)d_in[3];
    const float* mlp_bias   = (const float*)d_in[4];
    const float* q_norm_w   = (const float*)d_in[5];
    const float* q_norm_b   = (const float*)d_in[6];
    const float* k_norm_w   = (const float*)d_in[7];
    const float* k_norm_b   = (const float*)d_in[8];
    const float* out_proj_w = (const float*)d_in[9];
    const float* out_proj_b = (const float*)d_in[10];
    const float* ls_gamma   = (const float*)d_in[11];
    float* out = (float*)d_out;

    __nv_bfloat16 *y, *z, *w1, *w2, *cat;
    __half *qT, *kT, *vT;
    float *o2, *bias1;
    cudaGetSymbolAddress((void**)&y,     g_y);
    cudaGetSymbolAddress((void**)&z,     g_z);
    cudaGetSymbolAddress((void**)&w1,    g_w1);
    cudaGetSymbolAddress((void**)&w2,    g_w2);
    cudaGetSymbolAddress((void**)&cat,   g_cat);
    cudaGetSymbolAddress((void**)&qT,    g_qT);
    cudaGetSymbolAddress((void**)&kT,    g_kT);
    cudaGetSymbolAddress((void**)&vT,    g_vT);
    cudaGetSymbolAddress((void**)&o2,    g_o2);
    cudaGetSymbolAddress((void**)&bias1, g_bias1);

    cudaFuncSetAttribute(attn_mma_kernel,
                         cudaFuncAttributeMaxDynamicSharedMemorySize,
                         ATTN_SMEM_BYTES);
    cudaFuncSetAttribute(wmma_gemm_nt<0>,
                         cudaFuncAttributeMaxDynamicSharedMemorySize,
                         GEMM_SMEM_BYTES);
    cudaFuncSetAttribute(wmma_gemm_nt<1>,
                         cudaFuncAttributeMaxDynamicSharedMemorySize,
                         GEMM_SMEM_BYTES);

    // 0) weight conversion fp32 -> bf16
    f2bf_kernel<<<(O1_*C_/4 + 255)/256, 256>>>(in_proj_w, w1, O1_*C_/4);
    f2bf_kernel<<<(O2_*F_/4 + 255)/256, 256>>>(out_proj_w, w2, O2_*F_/4);

    // 1) input LN -> y (bf16)
    ln_in_kernel<<<M_, 256>>>(x, in_norm_w, in_norm_b, y);

    // 2) bias1
    build_bias1_kernel<<<(O1_ + 255) / 256, 256>>>(mlp_bias, bias1);

    // 3) z = y @ w1^T + bias1; MLP cols fused-gelu into cat, QKV cols into z
    wmma_gemm_nt<0><<<dim3(O1_ / 128, M_ / 128), 256, GEMM_SMEM_BYTES>>>(
        y, w1, bias1, z, cat, M_, O1_, C_);

    // 4) q/k LN + transpose (f16, Q pre-scaled), v transpose
    qkv_ln_transpose_kernel<<<(B_*N_*H_) / 8, 256>>>(
        z, q_norm_w, q_norm_b, k_norm_w, k_norm_b, qT, kT, vT);

    // 5) attention -> cat[:, HID:] (bf16)
    attn_mma_kernel<<<dim3(N_ / 128, B_ * H_), 256, ATTN_SMEM_BYTES>>>(
        qT, kT, vT, cat);

    // 6) o2 = cat @ w2^T + out_proj_b  (fp32 out)
    wmma_gemm_nt<1><<<dim3(O2_ / 128, M_ / 128), 256, GEMM_SMEM_BYTES>>>(
        cat, w2, out_proj_b, o2, nullptr, M_, O2_, F_);

    // 7) residual + layer scale
    final_kernel<<<(M_ * (C_ / 4)) / 256, 256>>>(x, o2, ls_gamma, out);
}

// round 14
// speedup vs baseline: 8.0102x; 1.3012x over previous
#include <cuda_runtime.h>
#include <cuda_bf16.h>
#include <cuda_fp16.h>
#include <mma.h>
#include <math.h>
#include <cstdint>

using namespace nvcuda;

// ---------------------------------------------------------------------------
// Problem dims (fixed)
// ---------------------------------------------------------------------------
#define B_   8
#define N_   1024
#define C_   1024
#define H_   16
#define D_   64
#define HID_ 4096
#define M_   (B_*N_)            // 8192 rows
#define O1_  (HID_ + 3*C_)      // 7168  (in_proj out)
#define F_   (HID_ + C_)        // 5120  (cat width)
#define EPS_ 1e-5f
// 1/sqrt(64) * log2(e), folded into Q so softmax works in exp2 domain
#define QSCALE_ 0.18033688011112042f

// ---------------------------------------------------------------------------
// Scratch (device globals)
// ---------------------------------------------------------------------------
__device__ __nv_bfloat16 g_y[(size_t)M_ * C_];        // LN(x) bf16        16 MB
__device__ __nv_bfloat16 g_z[(size_t)M_ * O1_];       // qkv cols only    117 MB
__device__ __nv_bfloat16 g_w1[(size_t)O1_ * C_];      // in_proj_w bf16    14 MB
__device__ __nv_bfloat16 g_w2s[(size_t)C_ * F_];      // folded out_proj_w 10 MB
__device__ __nv_bfloat16 g_cat[(size_t)M_ * F_];      // [gelu | attn]     80 MB
__device__ __half g_qT[(size_t)B_*H_*N_*D_];          // f16               16 MB
__device__ __half g_kT[(size_t)B_*H_*N_*D_];          //                   16 MB
__device__ __half g_vT[(size_t)B_*H_*N_*D_];          //                   16 MB
__device__ float g_bias1[O1_];                        // concat(0(3C), mlp_bias)
__device__ float g_bias2[C_];                         // b2[:C] + b2[C:]

// ---------------------------------------------------------------------------
// helpers
// ---------------------------------------------------------------------------
__device__ __forceinline__ unsigned smem_u32(const void* p) {
    return (unsigned)__cvta_generic_to_shared(p);
}
__device__ __forceinline__ void cp_async16(void* dst, const void* src) {
    asm volatile("cp.async.cg.shared.global [%0], [%1], 16;\n"
                 :: "r"(smem_u32(dst)), "l"(src));
}
__device__ __forceinline__ void cp_commit() {
    asm volatile("cp.async.commit_group;\n" ::: "memory");
}
__device__ __forceinline__ void cp_wait0() {
    asm volatile("cp.async.wait_group 0;\n" ::: "memory");
}
__device__ __forceinline__ void cp_wait1() {
    asm volatile("cp.async.wait_group 1;\n" ::: "memory");
}
__device__ __forceinline__ void ldmatrix_x4(unsigned* r, const void* p) {
    asm volatile("ldmatrix.sync.aligned.m8n8.x4.shared.b16 {%0,%1,%2,%3}, [%4];\n"
                 : "=r"(r[0]), "=r"(r[1]), "=r"(r[2]), "=r"(r[3])
                 : "r"(smem_u32(p)));
}
__device__ __forceinline__ void ldmatrix_x4_trans(unsigned* r, const void* p) {
    asm volatile("ldmatrix.sync.aligned.m8n8.x4.trans.shared.b16 {%0,%1,%2,%3}, [%4];\n"
                 : "=r"(r[0]), "=r"(r[1]), "=r"(r[2]), "=r"(r[3])
                 : "r"(smem_u32(p)));
}
__device__ __forceinline__ void mma16816(float* c, const unsigned* a,
                                         unsigned b0, unsigned b1) {
    asm volatile("mma.sync.aligned.m16n8k16.row.col.f32.f16.f16.f32 "
                 "{%0,%1,%2,%3}, {%4,%5,%6,%7}, {%8,%9}, {%0,%1,%2,%3};\n"
                 : "+f"(c[0]), "+f"(c[1]), "+f"(c[2]), "+f"(c[3])
                 : "r"(a[0]), "r"(a[1]), "r"(a[2]), "r"(a[3]),
                   "r"(b0), "r"(b1));
}

// FFMA-pipe fast exp2 (no MUFU). x <= 0 expected; rel err ~4e-5.
__device__ __forceinline__ float fexp2(float x) {
    x = fmaxf(x, -100.0f);
    float t = x + 12582912.0f;            // 1.5 * 2^23
    int   i = __float_as_int(t);
    float fl = t - 12582912.0f;
    float fr = x - fl;                    // [-0.5, 0.5]
    float p = 0.0096181f;
    p = fmaf(p, fr, 0.0555041f);
    p = fmaf(p, fr, 0.2402265f);
    p = fmaf(p, fr, 0.6931472f);
    p = fmaf(p, fr, 1.0f);
    return __int_as_float(__float_as_int(p) + (i << 23));
}

// exact GELU via erff
__device__ __forceinline__ float gelu_exact(float v) {
    return 0.5f * v * (1.0f + erff(v * 0.7071067811865475f));
}

// ---------------------------------------------------------------------------
// fp32 -> bf16 conversion (for weights)
// ---------------------------------------------------------------------------
__global__ void __launch_bounds__(256) f2bf_kernel(
    const float* __restrict__ in, __nv_bfloat16* __restrict__ out, int n4)
{
    int i = blockIdx.x * blockDim.x + threadIdx.x;
    if (i >= n4) return;
    float4 v = ((const float4*)in)[i];
    ((__nv_bfloat162*)out)[i*2]   = __floats2bfloat162_rn(v.x, v.y);
    ((__nv_bfloat162*)out)[i*2+1] = __floats2bfloat162_rn(v.z, v.w);
}

// folded out_proj weights: w2s[c, f] = w2[c, f] + w2[c + C, f]  (bf16 out)
__global__ void __launch_bounds__(256) fold_w2_kernel(
    const float* __restrict__ w2, __nv_bfloat16* __restrict__ w2s)
{
    int i = blockIdx.x * blockDim.x + threadIdx.x;   // over C*F/4
    if (i >= C_ * F_ / 4) return;
    float4 a = ((const float4*)w2)[i];
    float4 b = ((const float4*)(w2 + (size_t)C_ * F_))[i];
    ((__nv_bfloat162*)w2s)[i*2]   = __floats2bfloat162_rn(a.x + b.x, a.y + b.y);
    ((__nv_bfloat162*)w2s)[i*2+1] = __floats2bfloat162_rn(a.z + b.z, a.w + b.w);
}

// ---------------------------------------------------------------------------
// 1) Input LayerNorm
// ---------------------------------------------------------------------------
__global__ void __launch_bounds__(256) ln_in_kernel(
    const float* __restrict__ x, const float* __restrict__ w,
    const float* __restrict__ b, __nv_bfloat16* __restrict__ y)
{
    int row = blockIdx.x;
    const float4* xr = (const float4*)(x + (size_t)row * C_);
    float4 v = xr[threadIdx.x];
    float s  = v.x + v.y + v.z + v.w;
    float ss = v.x*v.x + v.y*v.y + v.z*v.z + v.w*v.w;

    #pragma unroll
    for (int o = 16; o; o >>= 1) {
        s  += __shfl_xor_sync(0xffffffffu, s,  o);
        ss += __shfl_xor_sync(0xffffffffu, ss, o);
    }
    __shared__ float sb[8], ssb[8];
    int wid = threadIdx.x >> 5, lane = threadIdx.x & 31;
    if (lane == 0) { sb[wid] = s; ssb[wid] = ss; }
    __syncthreads();
    __shared__ float s_mean, s_rstd;
    if (threadIdx.x == 0) {
        float t = 0.f, ts = 0.f;
        #pragma unroll
        for (int i = 0; i < 8; i++) { t += sb[i]; ts += ssb[i]; }
        float mean = t * (1.0f / C_);
        float var  = ts * (1.0f / C_) - mean * mean;
        s_mean = mean;
        s_rstd = rsqrtf(var + EPS_);
    }
    __syncthreads();
    float mean = s_mean, rstd = s_rstd;
    float4 wq = ((const float4*)w)[threadIdx.x];
    float4 bq = ((const float4*)b)[threadIdx.x];
    float ox = (v.x - mean) * rstd * wq.x + bq.x;
    float oy = (v.y - mean) * rstd * wq.y + bq.y;
    float oz = (v.z - mean) * rstd * wq.z + bq.z;
    float ow = (v.w - mean) * rstd * wq.w + bq.w;
    __nv_bfloat16* yr = y + (size_t)row * C_ + threadIdx.x * 4;
    *(__nv_bfloat162*)(yr)     = __floats2bfloat162_rn(ox, oy);
    *(__nv_bfloat162*)(yr + 2) = __floats2bfloat162_rn(oz, ow);
}

// ---------------------------------------------------------------------------
// 2) bias1 = concat(zeros(3C), mlp_bias); bias2 = b2[:C] + b2[C:]
// ---------------------------------------------------------------------------
__global__ void build_bias_kernel(const float* __restrict__ mlp_bias,
                                  const float* __restrict__ out_proj_b,
                                  float* __restrict__ bias1,
                                  float* __restrict__ bias2)
{
    int o = blockIdx.x * blockDim.x + threadIdx.x;
    if (o < O1_) bias1[o] = (o < 3*C_) ? 0.f : mlp_bias[o - 3*C_];
    if (o < C_)  bias2[o] = out_proj_b[o] + out_proj_b[o + C_];
}

// ---------------------------------------------------------------------------
// 3) bf16 WMMA GEMM: acc = A[M,K] * B[N,K]^T
//    MODE 0: GEMM1 fused epilogue (n0 < HID -> gelu into cat; else bf16 z)
//    MODE 2: GEMM2 fused final: out = x + lsg * (acc + bias)   (fp32 out)
// ---------------------------------------------------------------------------
#define GPAD   72
#define GSTAGE (128 * GPAD)
#define GEMM_SMEM_BYTES (4 * GSTAGE * 2)

template<int MODE>
__global__ void __launch_bounds__(256) wmma_gemm_nt(
    const __nv_bfloat16* __restrict__ A, const __nv_bfloat16* __restrict__ Bm,
    const float* __restrict__ bias, void* __restrict__ Cout,
    __nv_bfloat16* __restrict__ catOut,
    const float* __restrict__ xres, const float* __restrict__ lsg,
    int M, int N, int K)
{
    extern __shared__ __align__(16) char smraw[];
    __nv_bfloat16* smb = (__nv_bfloat16*)smraw;

    int tid = threadIdx.x;
    int m0 = blockIdx.y * 128;
    int n0 = blockIdx.x * 128;

    int wid = tid >> 5;
    int wm = wid >> 2;
    int wn = wid & 3;

    int crow[4], ccol[4];
    #pragma unroll
    for (int i = 0; i < 4; i++) {
        int chunk = tid + i * 256;
        crow[i] = chunk >> 3;
        ccol[i] = (chunk & 7) * 8;
    }

    wmma::fragment<wmma::accumulator, 16, 16, 16, float> acc[4][2];
    #pragma unroll
    for (int i = 0; i < 4; i++)
        #pragma unroll
        for (int j = 0; j < 2; j++)
            wmma::fill_fragment(acc[i][j], 0.0f);

    int nk = K >> 6;

    {
        __nv_bfloat16* sA = smb;
        __nv_bfloat16* sB = smb + 2 * GSTAGE;
        #pragma unroll
        for (int i = 0; i < 4; i++) {
            cp_async16(sA + crow[i]*GPAD + ccol[i],
                       A + (size_t)(m0 + crow[i]) * K + ccol[i]);
            cp_async16(sB + crow[i]*GPAD + ccol[i],
                       Bm + (size_t)(n0 + crow[i]) * K + ccol[i]);
        }
        cp_commit();
    }

    for (int k0 = 0; k0 < nk; k0++) {
        if (k0 + 1 < nk) {
            int s = (k0 + 1) & 1;
            int kofs = (k0 + 1) << 6;
            __nv_bfloat16* sA = smb + s * GSTAGE;
            __nv_bfloat16* sB = smb + 2 * GSTAGE + s * GSTAGE;
            #pragma unroll
            for (int i = 0; i < 4; i++) {
                cp_async16(sA + crow[i]*GPAD + ccol[i],
                           A + (size_t)(m0 + crow[i]) * K + kofs + ccol[i]);
                cp_async16(sB + crow[i]*GPAD + ccol[i],
                           Bm + (size_t)(n0 + crow[i]) * K + kofs + ccol[i]);
            }
            cp_commit();
            cp_wait1();
        } else {
            cp_wait0();
        }
        __syncthreads();

        int s = k0 & 1;
        const __nv_bfloat16* sA = smb + s * GSTAGE;
        const __nv_bfloat16* sB = smb + 2 * GSTAGE + s * GSTAGE;

        #pragma unroll
        for (int kk = 0; kk < 4; kk++) {
            wmma::fragment<wmma::matrix_a, 16, 16, 16, __nv_bfloat16, wmma::row_major> af[4];
            wmma::fragment<wmma::matrix_b, 16, 16, 16, __nv_bfloat16, wmma::col_major> bfr[2];
            #pragma unroll
            for (int i = 0; i < 4; i++)
                wmma::load_matrix_sync(af[i], sA + (wm*64 + i*16)*GPAD + kk*16, GPAD);
            #pragma unroll
            for (int j = 0; j < 2; j++)
                wmma::load_matrix_sync(bfr[j], sB + (wn*32 + j*16)*GPAD + kk*16, GPAD);
            #pragma unroll
            for (int i = 0; i < 4; i++)
                #pragma unroll
                for (int j = 0; j < 2; j++)
                    wmma::mma_sync(acc[i][j], af[i], bfr[j], acc[i][j]);
        }
        __syncthreads();
    }

    float* Cs = (float*)smraw;     // [128][132]
    #pragma unroll
    for (int i = 0; i < 4; i++)
        #pragma unroll
        for (int j = 0; j < 2; j++)
            wmma::store_matrix_sync(Cs + (size_t)(wm*64 + i*16)*132 + wn*32 + j*16,
                                    acc[i][j], 132, wmma::mem_row_major);
    __syncthreads();

    bool mlp_tile = (MODE == 0) && (n0 < HID_);

    #pragma unroll
    for (int it = 0; it < 16; it++) {
        int idx = tid + it * 256;
        int row = idx >> 5;
        int c4  = (idx & 31) * 4;
        float4 v = *(const float4*)(Cs + row*132 + c4);
        float4 bb = *(const float4*)(bias + n0 + c4);
        v.x += bb.x; v.y += bb.y; v.z += bb.z; v.w += bb.w;
        if (MODE == 2) {
            // out = x + lsg * v   (fused residual + layer scale)
            float4 xv = *(const float4*)(xres + (size_t)(m0 + row) * C_ + n0 + c4);
            float4 gv = *(const float4*)(lsg + n0 + c4);
            float4 r;
            r.x = xv.x + gv.x * v.x;
            r.y = xv.y + gv.y * v.y;
            r.z = xv.z + gv.z * v.z;
            r.w = xv.w + gv.w * v.w;
            float* Cr = (float*)Cout + (size_t)(m0 + row) * N + n0 + c4;
            *(float4*)Cr = r;
        } else if (mlp_tile) {
            v.x = gelu_exact(v.x); v.y = gelu_exact(v.y);
            v.z = gelu_exact(v.z); v.w = gelu_exact(v.w);
            __nv_bfloat16* Cr = catOut + (size_t)(m0 + row) * F_ + n0 + c4;
            *(__nv_bfloat162*)(Cr)     = __floats2bfloat162_rn(v.x, v.y);
            *(__nv_bfloat162*)(Cr + 2) = __floats2bfloat162_rn(v.z, v.w);
        } else {
            __nv_bfloat16* Cr = (__nv_bfloat16*)Cout + (size_t)(m0 + row) * N + n0 + c4;
            *(__nv_bfloat162*)(Cr)     = __floats2bfloat162_rn(v.x, v.y);
            *(__nv_bfloat162*)(Cr + 2) = __floats2bfloat162_rn(v.z, v.w);
        }
    }
}

// ---------------------------------------------------------------------------
// 4) q/k LayerNorm (reading bf16 z, writing f16) + transpose; v transpose.
// ---------------------------------------------------------------------------
__device__ __forceinline__ void ln64_warp(const __nv_bfloat16* __restrict__ src,
                                          const float* __restrict__ w,
                                          const float* __restrict__ b,
                                          __half* __restrict__ dst, int lane,
                                          float oscale)
{
    __nv_bfloat162 raw = *(const __nv_bfloat162*)(src + lane * 2);
    float2 v = make_float2(__bfloat162float(raw.x), __bfloat162float(raw.y));
    float s  = v.x + v.y;
    float ss = v.x*v.x + v.y*v.y;
    #pragma unroll
    for (int o = 16; o; o >>= 1) {
        s  += __shfl_xor_sync(0xffffffffu, s,  o);
        ss += __shfl_xor_sync(0xffffffffu, ss, o);
    }
    float mean = s * (1.0f / 64.0f);
    float var  = ss * (1.0f / 64.0f) - mean * mean;
    float rstd = rsqrtf(var + EPS_);
    float2 wv = *(const float2*)(w + lane * 2);
    float2 bv = *(const float2*)(b + lane * 2);
    float ox = ((v.x - mean) * rstd * wv.x + bv.x) * oscale;
    float oy = ((v.y - mean) * rstd * wv.y + bv.y) * oscale;
    *(__half2*)(dst + lane * 2) = __floats2half2_rn(ox, oy);
}

__global__ void __launch_bounds__(256) qkv_ln_transpose_kernel(
    const __nv_bfloat16* __restrict__ z,
    const float* __restrict__ qw, const float* __restrict__ qb,
    const float* __restrict__ kw, const float* __restrict__ kb,
    __half* __restrict__ Qo, __half* __restrict__ Ko, __half* __restrict__ Vo)
{
    int g = blockIdx.x * 8 + (threadIdx.x >> 5);   // (b, n, h) flat index
    int lane = threadIdx.x & 31;
    int b = g >> 14;
    int n = (g >> 4) & 1023;
    int h = g & 15;
    const __nv_bfloat16* zr = z + (size_t)(b * N_ + n) * O1_;
    size_t obase = ((size_t)(b * H_ + h) * N_ + n) * D_;

    ln64_warp(zr + HID_        + h*D_, qw, qb, Qo + obase, lane, QSCALE_);
    ln64_warp(zr + HID_ + C_   + h*D_, kw, kb, Ko + obase, lane, 1.0f);
    __nv_bfloat162 raw = *(const __nv_bfloat162*)(zr + HID_ + 2*C_ + h*D_ + lane * 2);
    *(__half2*)(Vo + obase + lane * 2) =
        __floats2half2_rn(__bfloat162float(raw.x), __bfloat162float(raw.y));
}

// ---------------------------------------------------------------------------
// 5) Flash attention, mma.sync f16, FFMA-pipe exp2
// ---------------------------------------------------------------------------
#define AT_PAD 72
#define ATTN_SMEM_BYTES ((128*AT_PAD + 4*64*AT_PAD) * 2)

__global__ void __launch_bounds__(256, 2) attn_mma_kernel(
    const __half* __restrict__ Qg, const __half* __restrict__ Kg,
    const __half* __restrict__ Vg, __nv_bfloat16* __restrict__ cat)
{
    extern __shared__ __align__(16) __half smh[];
    __half* Qs  = smh;
    __half* Ks0 = Qs + 128*AT_PAD;
    __half* Vs0 = Ks0 + 2*64*AT_PAD;

    int bh = blockIdx.y;
    int n0 = blockIdx.x * 128;
    const __half* qg = Qg + ((size_t)bh * N_ + n0) * D_;
    const __half* kg = Kg + (size_t)bh * N_ * D_;
    const __half* vg = Vg + (size_t)bh * N_ * D_;

    int tid = threadIdx.x;
    int lane = tid & 31, wid = tid >> 5;
    int m0 = wid * 16;

    #pragma unroll
    for (int i = 0; i < 4; i++) {
        int chunk = tid + i * 256;
        int r = chunk >> 3, c = (chunk & 7) * 8;
        cp_async16(Qs + r*AT_PAD + c, qg + r*64 + c);
    }
    cp_commit();
    #pragma unroll
    for (int i = 0; i < 2; i++) {
        int chunk = tid + i * 256;
        int r = chunk >> 3, c = (chunk & 7) * 8;
        cp_async16(Ks0 + r*AT_PAD + c, kg + r*64 + c);
        cp_async16(Vs0 + r*AT_PAD + c, vg + r*64 + c);
    }
    cp_commit();

    cp_wait1();
    __syncthreads();

    unsigned qf[4][4];
    {
        int row = m0 + (lane & 15);
        int colb = (lane >> 4) * 8;
        #pragma unroll
        for (int kc = 0; kc < 4; kc++)
            ldmatrix_x4(qf[kc], Qs + row*AT_PAD + kc*16 + colb);
    }

    float o[8][4];
    #pragma unroll
    for (int j = 0; j < 8; j++)
        #pragma unroll
        for (int e = 0; e < 4; e++) o[j][e] = 0.f;
    float m1 = -1e30f, m2 = -1e30f, l1 = 0.f, l2 = 0.f;

    for (int kt = 0; kt < 16; kt++) {
        if (kt + 1 < 16) {
            int s = (kt + 1) & 1;
            const __half* kgn = kg + (size_t)(kt + 1) * 64 * D_;
            const __half* vgn = vg + (size_t)(kt + 1) * 64 * D_;
            __half* Kd = Ks0 + s * 64*AT_PAD;
            __half* Vd = Vs0 + s * 64*AT_PAD;
            #pragma unroll
            for (int i = 0; i < 2; i++) {
                int chunk = tid + i * 256;
                int r = chunk >> 3, c = (chunk & 7) * 8;
                cp_async16(Kd + r*AT_PAD + c, kgn + r*64 + c);
                cp_async16(Vd + r*AT_PAD + c, vgn + r*64 + c);
            }
            cp_commit();
            cp_wait1();
        } else {
            cp_wait0();
        }
        __syncthreads();

        const __half* Ksm = Ks0 + (kt & 1) * 64*AT_PAD;
        const __half* Vsm = Vs0 + (kt & 1) * 64*AT_PAD;

        float s[8][4];
        #pragma unroll
        for (int j = 0; j < 8; j++)
            #pragma unroll
            for (int e = 0; e < 4; e++) s[j][e] = 0.f;

        #pragma unroll
        for (int jp = 0; jp < 4; jp++) {
            int krow = jp*16 + ((lane >> 4) << 3) + (lane & 7);
            int kcol = ((lane >> 3) & 1) * 8;
            #pragma unroll
            for (int kc = 0; kc < 4; kc++) {
                unsigned kb[4];
                ldmatrix_x4(kb, Ksm + krow*AT_PAD + kc*16 + kcol);
                mma16816(s[2*jp],   qf[kc], kb[0], kb[1]);
                mma16816(s[2*jp+1], qf[kc], kb[2], kb[3]);
            }
        }

        float mx1 = -1e30f, mx2 = -1e30f;
        #pragma unroll
        for (int j = 0; j < 8; j++) {
            mx1 = fmaxf(mx1, fmaxf(s[j][0], s[j][1]));
            mx2 = fmaxf(mx2, fmaxf(s[j][2], s[j][3]));
        }
        mx1 = fmaxf(mx1, __shfl_xor_sync(0xffffffffu, mx1, 1));
        mx1 = fmaxf(mx1, __shfl_xor_sync(0xffffffffu, mx1, 2));
        mx2 = fmaxf(mx2, __shfl_xor_sync(0xffffffffu, mx2, 1));
        mx2 = fmaxf(mx2, __shfl_xor_sync(0xffffffffu, mx2, 2));
        float mn1 = fmaxf(m1, mx1), mn2 = fmaxf(m2, mx2);
        float f1 = fexp2(m1 - mn1), f2 = fexp2(m2 - mn2);
        m1 = mn1; m2 = mn2;

        __half2 ph[8][2];
        float sum1 = 0.f, sum2 = 0.f;
        #pragma unroll
        for (int j = 0; j < 8; j++) {
            float p0 = fexp2(s[j][0] - m1);
            float p1 = fexp2(s[j][1] - m1);
            float p2 = fexp2(s[j][2] - m2);
            float p3 = fexp2(s[j][3] - m2);
            ph[j][0] = __floats2half2_rn(p0, p1);
            ph[j][1] = __floats2half2_rn(p2, p3);
            sum1 += p0 + p1;
            sum2 += p2 + p3;
        }
        sum1 += __shfl_xor_sync(0xffffffffu, sum1, 1);
        sum1 += __shfl_xor_sync(0xffffffffu, sum1, 2);
        sum2 += __shfl_xor_sync(0xffffffffu, sum2, 1);
        sum2 += __shfl_xor_sync(0xffffffffu, sum2, 2);
        l1 = l1 * f1 + sum1;
        l2 = l2 * f2 + sum2;

        #pragma unroll
        for (int j = 0; j < 8; j++) {
            o[j][0] *= f1; o[j][1] *= f1;
            o[j][2] *= f2; o[j][3] *= f2;
        }

        #pragma unroll
        for (int dp = 0; dp < 4; dp++) {
            int vcolb = dp*16 + (lane >> 4) * 8;
            int vrowb = ((lane >> 3) & 1) * 8 + (lane & 7);
            #pragma unroll
            for (int kc = 0; kc < 4; kc++) {
                unsigned vb[4];
                ldmatrix_x4_trans(vb, Vsm + (kc*16 + vrowb)*AT_PAD + vcolb);
                unsigned pa[4] = {
                    *(unsigned*)&ph[2*kc][0],   *(unsigned*)&ph[2*kc][1],
                    *(unsigned*)&ph[2*kc+1][0], *(unsigned*)&ph[2*kc+1][1] };
                mma16816(o[2*dp],   pa, vb[0], vb[1]);
                mma16816(o[2*dp+1], pa, vb[2], vb[3]);
            }
        }
        __syncthreads();
    }

    int b = bh >> 4, h = bh & 15;
    int r1 = lane >> 2, coff = (lane & 3) * 2;
    float inv1 = 1.0f / l1, inv2 = 1.0f / l2;
    size_t row1 = (size_t)b * N_ + n0 + m0 + r1;
    size_t row2 = row1 + 8;
    __nv_bfloat16* c1 = cat + row1 * F_ + HID_ + h * 64 + coff;
    __nv_bfloat16* c2 = cat + row2 * F_ + HID_ + h * 64 + coff;
    #pragma unroll
    for (int jd = 0; jd < 8; jd++) {
        *(__nv_bfloat162*)(c1 + jd*8) = __floats2bfloat162_rn(o[jd][0]*inv1, o[jd][1]*inv1);
        *(__nv_bfloat162*)(c2 + jd*8) = __floats2bfloat162_rn(o[jd][2]*inv2, o[jd][3]*inv2);
    }
}

// ---------------------------------------------------------------------------
// launch
// ---------------------------------------------------------------------------
extern "C" void kernel_launch(void* const* d_in, const int* in_sizes, int n_in,
                              void* d_out, int out_size)
{
    const float* x          = (const float*)d_in[0];
    const float* in_norm_w  = (const float*)d_in[1];
    const float* in_norm_b  = (const float*)d_in[2];
    const float* in_proj_w  = (const float*)d_in[3];
    const float* mlp_bias   = (const float*)d_in[4];
    const float* q_norm_w   = (const float*)d_in[5];
    const float* q_norm_b   = (const float*)d_in[6];
    const float* k_norm_w   = (const float*)d_in[7];
    const float* k_norm_b   = (const float*)d_in[8];
    const float* out_proj_w = (const float*)d_in[9];
    const float* out_proj_b = (const float*)d_in[10];
    const float* ls_gamma   = (const float*)d_in[11];
    float* out = (float*)d_out;

    __nv_bfloat16 *y, *z, *w1, *w2s, *cat;
    __half *qT, *kT, *vT;
    float *bias1, *bias2;
    cudaGetSymbolAddress((void**)&y,     g_y);
    cudaGetSymbolAddress((void**)&z,     g_z);
    cudaGetSymbolAddress((void**)&w1,    g_w1);
    cudaGetSymbolAddress((void**)&w2s,   g_w2s);
    cudaGetSymbolAddress((void**)&cat,   g_cat);
    cudaGetSymbolAddress((void**)&qT,    g_qT);
    cudaGetSymbolAddress((void**)&kT,    g_kT);
    cudaGetSymbolAddress((void**)&vT,    g_vT);
    cudaGetSymbolAddress((void**)&bias1, g_bias1);
    cudaGetSymbolAddress((void**)&bias2, g_bias2);

    cudaFuncSetAttribute(attn_mma_kernel,
                         cudaFuncAttributeMaxDynamicSharedMemorySize,
                         ATTN_SMEM_BYTES);
    cudaFuncSetAttribute(wmma_gemm_nt<0>,
                         cudaFuncAttributeMaxDynamicSharedMemorySize,
                         GEMM_SMEM_BYTES);
    cudaFuncSetAttribute(wmma_gemm_nt<2>,
                         cudaFuncAttributeMaxDynamicSharedMemorySize,
                         GEMM_SMEM_BYTES);

    // 0) weight conversion / folding
    f2bf_kernel<<<(O1_*C_/4 + 255)/256, 256>>>(in_proj_w, w1, O1_*C_/4);
    fold_w2_kernel<<<(C_*F_/4 + 255)/256, 256>>>(out_proj_w, w2s);

    // 1) input LN -> y (bf16)
    ln_in_kernel<<<M_, 256>>>(x, in_norm_w, in_norm_b, y);

    // 2) biases
    build_bias_kernel<<<(O1_ + 255) / 256, 256>>>(mlp_bias, out_proj_b,
                                                  bias1, bias2);

    // 3) z = y @ w1^T + bias1; MLP cols fused-gelu into cat, QKV cols into z
    wmma_gemm_nt<0><<<dim3(O1_ / 128, M_ / 128), 256, GEMM_SMEM_BYTES>>>(
        y, w1, bias1, z, cat, nullptr, nullptr, M_, O1_, C_);

    // 4) q/k LN + transpose (f16, Q pre-scaled), v transpose
    qkv_ln_transpose_kernel<<<(B_*N_*H_) / 8, 256>>>(
        z, q_norm_w, q_norm_b, k_norm_w, k_norm_b, qT, kT, vT);

    // 5) attention -> cat[:, HID:] (bf16)
    attn_mma_kernel<<<dim3(N_ / 128, B_ * H_), 256, ATTN_SMEM_BYTES>>>(
        qT, kT, vT, cat);

    // 6) out = x + lsg * (cat @ w2s^T + bias2)   — folded GEMM2 + residual
    wmma_gemm_nt<2><<<dim3(C_ / 128, M_ / 128), 256, GEMM_SMEM_BYTES>>>(
        cat, w2s, bias2, out, nullptr, x, ls_gamma, M_, C_, F_);
}

// round 15
// speedup vs baseline: 8.1924x; 1.0228x over previous
#include <cuda_runtime.h>
#include <cuda_bf16.h>
#include <cuda_fp16.h>
#include <math.h>
#include <cstdint>

// ---------------------------------------------------------------------------
// Problem dims (fixed)
// ---------------------------------------------------------------------------
#define B_   8
#define N_   1024
#define C_   1024
#define H_   16
#define D_   64
#define HID_ 4096
#define M_   (B_*N_)            // 8192 rows
#define O1_  (HID_ + 3*C_)      // 7168  (in_proj out)
#define F_   (HID_ + C_)        // 5120  (cat width)
#define EPS_ 1e-5f
// 1/sqrt(64) * log2(e), folded into Q so softmax works in exp2 domain
#define QSCALE_ 0.18033688011112042f
#define WSCALE_ 32.0f
#define RSCALE_ (1.0f/32.0f)

// ---------------------------------------------------------------------------
// Scratch (device globals)
// ---------------------------------------------------------------------------
__device__ uint8_t g_y8[(size_t)M_ * C_];             // LN(x) e4m3         8 MB
__device__ __nv_bfloat16 g_z[(size_t)M_ * O1_];       // qkv cols (bf16)  117 MB
__device__ uint8_t g_w1[(size_t)O1_ * C_];            // in_proj_w e4m3*32  7 MB
__device__ uint8_t g_w2s[(size_t)C_ * F_];            // folded w2 e4m3*32  5 MB
__device__ uint8_t g_cat[(size_t)M_ * F_];            // [gelu|attn] e4m3  40 MB
__device__ __half g_qT[(size_t)B_*H_*N_*D_];          // f16               16 MB
__device__ __half g_kT[(size_t)B_*H_*N_*D_];          //                   16 MB
__device__ __half g_vT[(size_t)B_*H_*N_*D_];          //                   16 MB
__device__ float g_bias1[O1_];                        // concat(0(3C), mlp_bias)
__device__ float g_bias2[C_];                         // b2[:C] + b2[C:]

// ---------------------------------------------------------------------------
// helpers
// ---------------------------------------------------------------------------
__device__ __forceinline__ unsigned smem_u32(const void* p) {
    return (unsigned)__cvta_generic_to_shared(p);
}
__device__ __forceinline__ void cp_async16(void* dst, const void* src) {
    asm volatile("cp.async.cg.shared.global [%0], [%1], 16;\n"
                 :: "r"(smem_u32(dst)), "l"(src));
}
__device__ __forceinline__ void cp_commit() {
    asm volatile("cp.async.commit_group;\n" ::: "memory");
}
__device__ __forceinline__ void cp_wait0() {
    asm volatile("cp.async.wait_group 0;\n" ::: "memory");
}
__device__ __forceinline__ void cp_wait1() {
    asm volatile("cp.async.wait_group 1;\n" ::: "memory");
}
__device__ __forceinline__ void ldmatrix_x4(unsigned* r, const void* p) {
    asm volatile("ldmatrix.sync.aligned.m8n8.x4.shared.b16 {%0,%1,%2,%3}, [%4];\n"
                 : "=r"(r[0]), "=r"(r[1]), "=r"(r[2]), "=r"(r[3])
                 : "r"(smem_u32(p)));
}
__device__ __forceinline__ void ldmatrix_x4_trans(unsigned* r, const void* p) {
    asm volatile("ldmatrix.sync.aligned.m8n8.x4.trans.shared.b16 {%0,%1,%2,%3}, [%4];\n"
                 : "=r"(r[0]), "=r"(r[1]), "=r"(r[2]), "=r"(r[3])
                 : "r"(smem_u32(p)));
}
__device__ __forceinline__ void mma16816(float* c, const unsigned* a,
                                         unsigned b0, unsigned b1) {
    asm volatile("mma.sync.aligned.m16n8k16.row.col.f32.f16.f16.f32 "
                 "{%0,%1,%2,%3}, {%4,%5,%6,%7}, {%8,%9}, {%0,%1,%2,%3};\n"
                 : "+f"(c[0]), "+f"(c[1]), "+f"(c[2]), "+f"(c[3])
                 : "r"(a[0]), "r"(a[1]), "r"(a[2]), "r"(a[3]),
                   "r"(b0), "r"(b1));
}
// FP8 e4m3 MMA, k32
__device__ __forceinline__ void mma16832(float* c, const unsigned* a,
                                         unsigned b0, unsigned b1) {
    asm volatile("mma.sync.aligned.m16n8k32.row.col.f32.e4m3.e4m3.f32 "
                 "{%0,%1,%2,%3}, {%4,%5,%6,%7}, {%8,%9}, {%0,%1,%2,%3};\n"
                 : "+f"(c[0]), "+f"(c[1]), "+f"(c[2]), "+f"(c[3])
                 : "r"(a[0]), "r"(a[1]), "r"(a[2]), "r"(a[3]),
                   "r"(b0), "r"(b1));
}
// pack two floats to e4m3x2 (lo in low byte)
__device__ __forceinline__ unsigned short fp8x2(float lo, float hi) {
    unsigned short r;
    asm("{\n\t.reg .b16 t;\n\tcvt.rn.satfinite.e4m3x2.f32 t, %1, %2;\n\t"
        "mov.b16 %0, t;\n\t}" : "=h"(r) : "f"(hi), "f"(lo));
    return r;
}

// FFMA-pipe fast exp2 (no MUFU). x <= 0 expected; rel err ~4e-5.
__device__ __forceinline__ float fexp2(float x) {
    x = fmaxf(x, -100.0f);
    float t = x + 12582912.0f;            // 1.5 * 2^23
    int   i = __float_as_int(t);
    float fl = t - 12582912.0f;
    float fr = x - fl;                    // [-0.5, 0.5]
    float p = 0.0096181f;
    p = fmaf(p, fr, 0.0555041f);
    p = fmaf(p, fr, 0.2402265f);
    p = fmaf(p, fr, 0.6931472f);
    p = fmaf(p, fr, 1.0f);
    return __int_as_float(__float_as_int(p) + (i << 23));
}

// exact GELU via erff
__device__ __forceinline__ float gelu_exact(float v) {
    return 0.5f * v * (1.0f + erff(v * 0.7071067811865475f));
}

// ---------------------------------------------------------------------------
// fp32 -> e4m3 conversion with scale (weights)
// ---------------------------------------------------------------------------
__global__ void __launch_bounds__(256) f2fp8_kernel(
    const float* __restrict__ in, uint8_t* __restrict__ out, float scale, int n4)
{
    int i = blockIdx.x * blockDim.x + threadIdx.x;
    if (i >= n4) return;
    float4 v = ((const float4*)in)[i];
    unsigned r = (unsigned)fp8x2(v.x*scale, v.y*scale)
               | ((unsigned)fp8x2(v.z*scale, v.w*scale) << 16);
    ((unsigned*)out)[i] = r;
}

// folded out_proj: w2s[c,f] = (w2[c,f] + w2[c+C,f]) * WSCALE  (e4m3)
__global__ void __launch_bounds__(256) fold_w2_kernel(
    const float* __restrict__ w2, uint8_t* __restrict__ w2s)
{
    int i = blockIdx.x * blockDim.x + threadIdx.x;   // over C*F/4
    if (i >= C_ * F_ / 4) return;
    float4 a = ((const float4*)w2)[i];
    float4 b = ((const float4*)(w2 + (size_t)C_ * F_))[i];
    unsigned r = (unsigned)fp8x2((a.x+b.x)*WSCALE_, (a.y+b.y)*WSCALE_)
               | ((unsigned)fp8x2((a.z+b.z)*WSCALE_, (a.w+b.w)*WSCALE_) << 16);
    ((unsigned*)w2s)[i] = r;
}

// ---------------------------------------------------------------------------
// 1) Input LayerNorm -> e4m3
// ---------------------------------------------------------------------------
__global__ void __launch_bounds__(256) ln_in_kernel(
    const float* __restrict__ x, const float* __restrict__ w,
    const float* __restrict__ b, uint8_t* __restrict__ y)
{
    int row = blockIdx.x;
    const float4* xr = (const float4*)(x + (size_t)row * C_);
    float4 v = xr[threadIdx.x];
    float s  = v.x + v.y + v.z + v.w;
    float ss = v.x*v.x + v.y*v.y + v.z*v.z + v.w*v.w;

    #pragma unroll
    for (int o = 16; o; o >>= 1) {
        s  += __shfl_xor_sync(0xffffffffu, s,  o);
        ss += __shfl_xor_sync(0xffffffffu, ss, o);
    }
    __shared__ float sb[8], ssb[8];
    int wid = threadIdx.x >> 5, lane = threadIdx.x & 31;
    if (lane == 0) { sb[wid] = s; ssb[wid] = ss; }
    __syncthreads();
    __shared__ float s_mean, s_rstd;
    if (threadIdx.x == 0) {
        float t = 0.f, ts = 0.f;
        #pragma unroll
        for (int i = 0; i < 8; i++) { t += sb[i]; ts += ssb[i]; }
        float mean = t * (1.0f / C_);
        float var  = ts * (1.0f / C_) - mean * mean;
        s_mean = mean;
        s_rstd = rsqrtf(var + EPS_);
    }
    __syncthreads();
    float mean = s_mean, rstd = s_rstd;
    float4 wq = ((const float4*)w)[threadIdx.x];
    float4 bq = ((const float4*)b)[threadIdx.x];
    float ox = (v.x - mean) * rstd * wq.x + bq.x;
    float oy = (v.y - mean) * rstd * wq.y + bq.y;
    float oz = (v.z - mean) * rstd * wq.z + bq.z;
    float ow = (v.w - mean) * rstd * wq.w + bq.w;
    unsigned r = (unsigned)fp8x2(ox, oy) | ((unsigned)fp8x2(oz, ow) << 16);
    *(unsigned*)(y + (size_t)row * C_ + threadIdx.x * 4) = r;
}

// ---------------------------------------------------------------------------
// 2) bias1 = concat(zeros(3C), mlp_bias); bias2 = b2[:C] + b2[C:]
// ---------------------------------------------------------------------------
__global__ void build_bias_kernel(const float* __restrict__ mlp_bias,
                                  const float* __restrict__ out_proj_b,
                                  float* __restrict__ bias1,
                                  float* __restrict__ bias2)
{
    int o = blockIdx.x * blockDim.x + threadIdx.x;
    if (o < O1_) bias1[o] = (o < 3*C_) ? 0.f : mlp_bias[o - 3*C_];
    if (o < C_)  bias2[o] = out_proj_b[o] + out_proj_b[o + C_];
}

// ---------------------------------------------------------------------------
// 3) FP8 e4m3 GEMM: acc = A[M,K] * B[N,K]^T  (weights pre-scaled by 32)
//    128x128 tile, BK=64 (64 B rows, 80 B stride), 8 warps (2x4), warp 64x32.
//    MODE 0: GEMM1 epilogue (n0 < HID -> gelu -> e4m3 cat; else bf16 z)
//    MODE 2: GEMM2 fused final: out = x + lsg * (acc/32 + bias)  (fp32)
// ---------------------------------------------------------------------------
#define GP8  80
#define GST8 (128*GP8)                    // 10240 B per tile stage
#define GEMM_SMEM_BYTES (128*132*4)       // epilogue float staging dominates

template<int MODE>
__global__ void __launch_bounds__(256) fp8_gemm_nt(
    const uint8_t* __restrict__ A, const uint8_t* __restrict__ Bm,
    const float* __restrict__ bias, void* __restrict__ Cout,
    uint8_t* __restrict__ catOut,
    const float* __restrict__ xres, const float* __restrict__ lsg,
    int M, int N, int K)
{
    extern __shared__ __align__(16) char smraw[];
    char* smb = smraw;

    int tid = threadIdx.x;
    int m0 = blockIdx.y * 128;
    int n0 = blockIdx.x * 128;
    int wid = tid >> 5, lane = tid & 31;
    int wm = wid >> 2, wn = wid & 3;

    // copy mapping: 512 16B-chunks per tile, 2 per thread
    int crow[2], ccol[2];
    #pragma unroll
    for (int i = 0; i < 2; i++) {
        int chunk = tid + i * 256;
        crow[i] = chunk >> 2;
        ccol[i] = (chunk & 3) * 16;
    }

    float acc[4][4][4];
    #pragma unroll
    for (int i = 0; i < 4; i++)
        #pragma unroll
        for (int j = 0; j < 4; j++)
            #pragma unroll
            for (int e = 0; e < 4; e++) acc[i][j][e] = 0.f;

    int nk = K >> 6;

    // prologue: stage 0
    {
        char* sA = smb;
        char* sB = smb + 2*GST8;
        #pragma unroll
        for (int i = 0; i < 2; i++) {
            cp_async16(sA + crow[i]*GP8 + ccol[i],
                       A + (size_t)(m0 + crow[i]) * K + ccol[i]);
            cp_async16(sB + crow[i]*GP8 + ccol[i],
                       Bm + (size_t)(n0 + crow[i]) * K + ccol[i]);
        }
        cp_commit();
    }

    for (int k0 = 0; k0 < nk; k0++) {
        if (k0 + 1 < nk) {
            int s = (k0 + 1) & 1;
            int kofs = (k0 + 1) << 6;
            char* sA = smb + s*GST8;
            char* sB = smb + 2*GST8 + s*GST8;
            #pragma unroll
            for (int i = 0; i < 2; i++) {
                cp_async16(sA + crow[i]*GP8 + ccol[i],
                           A + (size_t)(m0 + crow[i]) * K + kofs + ccol[i]);
                cp_async16(sB + crow[i]*GP8 + ccol[i],
                           Bm + (size_t)(n0 + crow[i]) * K + kofs + ccol[i]);
            }
            cp_commit();
            cp_wait1();
        } else {
            cp_wait0();
        }
        __syncthreads();

        int s = k0 & 1;
        const char* sA = smb + s*GST8;
        const char* sB = smb + 2*GST8 + s*GST8;

        #pragma unroll
        for (int kc = 0; kc < 2; kc++) {
            unsigned af[4][4];
            #pragma unroll
            for (int i = 0; i < 4; i++)
                ldmatrix_x4(af[i], sA + (wm*64 + i*16 + (lane & 15))*GP8
                                      + kc*32 + (lane >> 4)*16);
            #pragma unroll
            for (int jp = 0; jp < 2; jp++) {
                unsigned bf[4];
                ldmatrix_x4(bf, sB + (wn*32 + jp*16 + ((lane >> 4) << 3) + (lane & 7))*GP8
                                   + kc*32 + ((lane >> 3) & 1)*16);
                #pragma unroll
                for (int i = 0; i < 4; i++) {
                    mma16832(acc[i][2*jp],   af[i], bf[0], bf[1]);
                    mma16832(acc[i][2*jp+1], af[i], bf[2], bf[3]);
                }
            }
        }
        __syncthreads();
    }

    // stage accumulators to smem (fp32, [128][132])
    float* Cs = (float*)smraw;
    int r1 = lane >> 2, cpos = (lane & 3) * 2;
    #pragma unroll
    for (int i = 0; i < 4; i++)
        #pragma unroll
        for (int n = 0; n < 4; n++) {
            float* base = Cs + (size_t)(wm*64 + i*16) * 132 + wn*32 + n*8 + cpos;
            *(float2*)(base + r1*132)     = make_float2(acc[i][n][0], acc[i][n][1]);
            *(float2*)(base + (r1+8)*132) = make_float2(acc[i][n][2], acc[i][n][3]);
        }
    __syncthreads();

    bool mlp_tile = (MODE == 0) && (n0 < HID_);

    #pragma unroll
    for (int it = 0; it < 16; it++) {
        int idx = tid + it * 256;
        int row = idx >> 5;
        int c4  = (idx & 31) * 4;
        float4 v = *(const float4*)(Cs + row*132 + c4);
        float4 bb = *(const float4*)(bias + n0 + c4);
        v.x = v.x * RSCALE_ + bb.x;
        v.y = v.y * RSCALE_ + bb.y;
        v.z = v.z * RSCALE_ + bb.z;
        v.w = v.w * RSCALE_ + bb.w;
        if (MODE == 2) {
            float4 xv = *(const float4*)(xres + (size_t)(m0 + row) * C_ + n0 + c4);
            float4 gv = *(const float4*)(lsg + n0 + c4);
            float4 r;
            r.x = xv.x + gv.x * v.x;
            r.y = xv.y + gv.y * v.y;
            r.z = xv.z + gv.z * v.z;
            r.w = xv.w + gv.w * v.w;
            float* Cr = (float*)Cout + (size_t)(m0 + row) * N + n0 + c4;
            *(float4*)Cr = r;
        } else if (mlp_tile) {
            v.x = gelu_exact(v.x); v.y = gelu_exact(v.y);
            v.z = gelu_exact(v.z); v.w = gelu_exact(v.w);
            unsigned r = (unsigned)fp8x2(v.x, v.y) | ((unsigned)fp8x2(v.z, v.w) << 16);
            *(unsigned*)(catOut + (size_t)(m0 + row) * F_ + n0 + c4) = r;
        } else {
            __nv_bfloat16* Cr = (__nv_bfloat16*)Cout + (size_t)(m0 + row) * N + n0 + c4;
            *(__nv_bfloat162*)(Cr)     = __floats2bfloat162_rn(v.x, v.y);
            *(__nv_bfloat162*)(Cr + 2) = __floats2bfloat162_rn(v.z, v.w);
        }
    }
}

// ---------------------------------------------------------------------------
// 4) q/k LayerNorm (reading bf16 z, writing f16) + transpose; v transpose.
// ---------------------------------------------------------------------------
__device__ __forceinline__ void ln64_warp(const __nv_bfloat16* __restrict__ src,
                                          const float* __restrict__ w,
                                          const float* __restrict__ b,
                                          __half* __restrict__ dst, int lane,
                                          float oscale)
{
    __nv_bfloat162 raw = *(const __nv_bfloat162*)(src + lane * 2);
    float2 v = make_float2(__bfloat162float(raw.x), __bfloat162float(raw.y));
    float s  = v.x + v.y;
    float ss = v.x*v.x + v.y*v.y;
    #pragma unroll
    for (int o = 16; o; o >>= 1) {
        s  += __shfl_xor_sync(0xffffffffu, s,  o);
        ss += __shfl_xor_sync(0xffffffffu, ss, o);
    }
    float mean = s * (1.0f / 64.0f);
    float var  = ss * (1.0f / 64.0f) - mean * mean;
    float rstd = rsqrtf(var + EPS_);
    float2 wv = *(const float2*)(w + lane * 2);
    float2 bv = *(const float2*)(b + lane * 2);
    float ox = ((v.x - mean) * rstd * wv.x + bv.x) * oscale;
    float oy = ((v.y - mean) * rstd * wv.y + bv.y) * oscale;
    *(__half2*)(dst + lane * 2) = __floats2half2_rn(ox, oy);
}

__global__ void __launch_bounds__(256) qkv_ln_transpose_kernel(
    const __nv_bfloat16* __restrict__ z,
    const float* __restrict__ qw, const float* __restrict__ qb,
    const float* __restrict__ kw, const float* __restrict__ kb,
    __half* __restrict__ Qo, __half* __restrict__ Ko, __half* __restrict__ Vo)
{
    int g = blockIdx.x * 8 + (threadIdx.x >> 5);   // (b, n, h) flat index
    int lane = threadIdx.x & 31;
    int b = g >> 14;
    int n = (g >> 4) & 1023;
    int h = g & 15;
    const __nv_bfloat16* zr = z + (size_t)(b * N_ + n) * O1_;
    size_t obase = ((size_t)(b * H_ + h) * N_ + n) * D_;

    ln64_warp(zr + HID_        + h*D_, qw, qb, Qo + obase, lane, QSCALE_);
    ln64_warp(zr + HID_ + C_   + h*D_, kw, kb, Ko + obase, lane, 1.0f);
    __nv_bfloat162 raw = *(const __nv_bfloat162*)(zr + HID_ + 2*C_ + h*D_ + lane * 2);
    *(__half2*)(Vo + obase + lane * 2) =
        __floats2half2_rn(__bfloat162float(raw.x), __bfloat162float(raw.y));
}

// ---------------------------------------------------------------------------
// 5) Flash attention, mma.sync f16, FFMA-pipe exp2; e4m3 output into cat
// ---------------------------------------------------------------------------
#define AT_PAD 72
#define ATTN_SMEM_BYTES ((128*AT_PAD + 4*64*AT_PAD) * 2)

__global__ void __launch_bounds__(256, 2) attn_mma_kernel(
    const __half* __restrict__ Qg, const __half* __restrict__ Kg,
    const __half* __restrict__ Vg, uint8_t* __restrict__ cat)
{
    extern __shared__ __align__(16) __half smh[];
    __half* Qs  = smh;
    __half* Ks0 = Qs + 128*AT_PAD;
    __half* Vs0 = Ks0 + 2*64*AT_PAD;

    int bh = blockIdx.y;
    int n0 = blockIdx.x * 128;
    const __half* qg = Qg + ((size_t)bh * N_ + n0) * D_;
    const __half* kg = Kg + (size_t)bh * N_ * D_;
    const __half* vg = Vg + (size_t)bh * N_ * D_;

    int tid = threadIdx.x;
    int lane = tid & 31, wid = tid >> 5;
    int m0 = wid * 16;

    #pragma unroll
    for (int i = 0; i < 4; i++) {
        int chunk = tid + i * 256;
        int r = chunk >> 3, c = (chunk & 7) * 8;
        cp_async16(Qs + r*AT_PAD + c, qg + r*64 + c);
    }
    cp_commit();
    #pragma unroll
    for (int i = 0; i < 2; i++) {
        int chunk = tid + i * 256;
        int r = chunk >> 3, c = (chunk & 7) * 8;
        cp_async16(Ks0 + r*AT_PAD + c, kg + r*64 + c);
        cp_async16(Vs0 + r*AT_PAD + c, vg + r*64 + c);
    }
    cp_commit();

    cp_wait1();
    __syncthreads();

    unsigned qf[4][4];
    {
        int row = m0 + (lane & 15);
        int colb = (lane >> 4) * 8;
        #pragma unroll
        for (int kc = 0; kc < 4; kc++)
            ldmatrix_x4(qf[kc], Qs + row*AT_PAD + kc*16 + colb);
    }

    float o[8][4];
    #pragma unroll
    for (int j = 0; j < 8; j++)
        #pragma unroll
        for (int e = 0; e < 4; e++) o[j][e] = 0.f;
    float m1 = -1e30f, m2 = -1e30f, l1 = 0.f, l2 = 0.f;

    for (int kt = 0; kt < 16; kt++) {
        if (kt + 1 < 16) {
            int s = (kt + 1) & 1;
            const __half* kgn = kg + (size_t)(kt + 1) * 64 * D_;
            const __half* vgn = vg + (size_t)(kt + 1) * 64 * D_;
            __half* Kd = Ks0 + s * 64*AT_PAD;
            __half* Vd = Vs0 + s * 64*AT_PAD;
            #pragma unroll
            for (int i = 0; i < 2; i++) {
                int chunk = tid + i * 256;
                int r = chunk >> 3, c = (chunk & 7) * 8;
                cp_async16(Kd + r*AT_PAD + c, kgn + r*64 + c);
                cp_async16(Vd + r*AT_PAD + c, vgn + r*64 + c);
            }
            cp_commit();
            cp_wait1();
        } else {
            cp_wait0();
        }
        __syncthreads();

        const __half* Ksm = Ks0 + (kt & 1) * 64*AT_PAD;
        const __half* Vsm = Vs0 + (kt & 1) * 64*AT_PAD;

        float s[8][4];
        #pragma unroll
        for (int j = 0; j < 8; j++)
            #pragma unroll
            for (int e = 0; e < 4; e++) s[j][e] = 0.f;

        #pragma unroll
        for (int jp = 0; jp < 4; jp++) {
            int krow = jp*16 + ((lane >> 4) << 3) + (lane & 7);
            int kcol = ((lane >> 3) & 1) * 8;
            #pragma unroll
            for (int kc = 0; kc < 4; kc++) {
                unsigned kb[4];
                ldmatrix_x4(kb, Ksm + krow*AT_PAD + kc*16 + kcol);
                mma16816(s[2*jp],   qf[kc], kb[0], kb[1]);
                mma16816(s[2*jp+1], qf[kc], kb[2], kb[3]);
            }
        }

        float mx1 = -1e30f, mx2 = -1e30f;
        #pragma unroll
        for (int j = 0; j < 8; j++) {
            mx1 = fmaxf(mx1, fmaxf(s[j][0], s[j][1]));
            mx2 = fmaxf(mx2, fmaxf(s[j][2], s[j][3]));
        }
        mx1 = fmaxf(mx1, __shfl_xor_sync(0xffffffffu, mx1, 1));
        mx1 = fmaxf(mx1, __shfl_xor_sync(0xffffffffu, mx1, 2));
        mx2 = fmaxf(mx2, __shfl_xor_sync(0xffffffffu, mx2, 1));
        mx2 = fmaxf(mx2, __shfl_xor_sync(0xffffffffu, mx2, 2));
        float mn1 = fmaxf(m1, mx1), mn2 = fmaxf(m2, mx2);
        float f1 = fexp2(m1 - mn1), f2 = fexp2(m2 - mn2);
        m1 = mn1; m2 = mn2;

        __half2 ph[8][2];
        float sum1 = 0.f, sum2 = 0.f;
        #pragma unroll
        for (int j = 0; j < 8; j++) {
            float p0 = fexp2(s[j][0] - m1);
            float p1 = fexp2(s[j][1] - m1);
            float p2 = fexp2(s[j][2] - m2);
            float p3 = fexp2(s[j][3] - m2);
            ph[j][0] = __floats2half2_rn(p0, p1);
            ph[j][1] = __floats2half2_rn(p2, p3);
            sum1 += p0 + p1;
            sum2 += p2 + p3;
        }
        sum1 += __shfl_xor_sync(0xffffffffu, sum1, 1);
        sum1 += __shfl_xor_sync(0xffffffffu, sum1, 2);
        sum2 += __shfl_xor_sync(0xffffffffu, sum2, 1);
        sum2 += __shfl_xor_sync(0xffffffffu, sum2, 2);
        l1 = l1 * f1 + sum1;
        l2 = l2 * f2 + sum2;

        #pragma unroll
        for (int j = 0; j < 8; j++) {
            o[j][0] *= f1; o[j][1] *= f1;
            o[j][2] *= f2; o[j][3] *= f2;
        }

        #pragma unroll
        for (int dp = 0; dp < 4; dp++) {
            int vcolb = dp*16 + (lane >> 4) * 8;
            int vrowb = ((lane >> 3) & 1) * 8 + (lane & 7);
            #pragma unroll
            for (int kc = 0; kc < 4; kc++) {
                unsigned vb[4];
                ldmatrix_x4_trans(vb, Vsm + (kc*16 + vrowb)*AT_PAD + vcolb);
                unsigned pa[4] = {
                    *(unsigned*)&ph[2*kc][0],   *(unsigned*)&ph[2*kc][1],
                    *(unsigned*)&ph[2*kc+1][0], *(unsigned*)&ph[2*kc+1][1] };
                mma16816(o[2*dp],   pa, vb[0], vb[1]);
                mma16816(o[2*dp+1], pa, vb[2], vb[3]);
            }
        }
        __syncthreads();
    }

    int b = bh >> 4, h = bh & 15;
    int r1 = lane >> 2, coff = (lane & 3) * 2;
    float inv1 = 1.0f / l1, inv2 = 1.0f / l2;
    size_t row1 = (size_t)b * N_ + n0 + m0 + r1;
    size_t row2 = row1 + 8;
    uint8_t* c1 = cat + row1 * F_ + HID_ + h * 64 + coff;
    uint8_t* c2 = cat + row2 * F_ + HID_ + h * 64 + coff;
    #pragma unroll
    for (int jd = 0; jd < 8; jd++) {
        *(unsigned short*)(c1 + jd*8) = fp8x2(o[jd][0]*inv1, o[jd][1]*inv1);
        *(unsigned short*)(c2 + jd*8) = fp8x2(o[jd][2]*inv2, o[jd][3]*inv2);
    }
}

// ---------------------------------------------------------------------------
// launch
// ---------------------------------------------------------------------------
extern "C" void kernel_launch(void* const* d_in, const int* in_sizes, int n_in,
                              void* d_out, int out_size)
{
    const float* x          = (const float*)d_in[0];
    const float* in_norm_w  = (const float*)d_in[1];
    const float* in_norm_b  = (const float*)d_in[2];
    const float* in_proj_w  = (const float*)d_in[3];
    const float* mlp_bias   = (const float*)d_in[4];
    const float* q_norm_w   = (const float*)d_in[5];
    const float* q_norm_b   = (const float*)d_in[6];
    const float* k_norm_w   = (const float*)d_in[7];
    const float* k_norm_b   = (const float*)d_in[8];
    const float* out_proj_w = (const float*)d_in[9];
    const float* out_proj_b = (const float*)d_in[10];
    const float* ls_gamma   = (const float*)d_in[11];
    float* out = (float*)d_out;

    uint8_t *y8, *w1, *w2s, *cat;
    __nv_bfloat16 *z;
    __half *qT, *kT, *vT;
    float *bias1, *bias2;
    cudaGetSymbolAddress((void**)&y8,    g_y8);
    cudaGetSymbolAddress((void**)&z,     g_z);
    cudaGetSymbolAddress((void**)&w1,    g_w1);
    cudaGetSymbolAddress((void**)&w2s,   g_w2s);
    cudaGetSymbolAddress((void**)&cat,   g_cat);
    cudaGetSymbolAddress((void**)&qT,    g_qT);
    cudaGetSymbolAddress((void**)&kT,    g_kT);
    cudaGetSymbolAddress((void**)&vT,    g_vT);
    cudaGetSymbolAddress((void**)&bias1, g_bias1);
    cudaGetSymbolAddress((void**)&bias2, g_bias2);

    cudaFuncSetAttribute(attn_mma_kernel,
                         cudaFuncAttributeMaxDynamicSharedMemorySize,
                         ATTN_SMEM_BYTES);
    cudaFuncSetAttribute(fp8_gemm_nt<0>,
                         cudaFuncAttributeMaxDynamicSharedMemorySize,
                         GEMM_SMEM_BYTES);
    cudaFuncSetAttribute(fp8_gemm_nt<2>,
                         cudaFuncAttributeMaxDynamicSharedMemorySize,
                         GEMM_SMEM_BYTES);

    // 0) weight conversion / folding (e4m3, scale 32)
    f2fp8_kernel<<<(O1_*C_/4 + 255)/256, 256>>>(in_proj_w, w1, WSCALE_, O1_*C_/4);
    fold_w2_kernel<<<(C_*F_/4 + 255)/256, 256>>>(out_proj_w, w2s);

    // 1) input LN -> y (e4m3)
    ln_in_kernel<<<M_, 256>>>(x, in_norm_w, in_norm_b, y8);

    // 2) biases
    build_bias_kernel<<<(O1_ + 255) / 256, 256>>>(mlp_bias, out_proj_b,
                                                  bias1, bias2);

    // 3) z = y @ w1^T + bias1; MLP cols fused-gelu into cat(e4m3), QKV -> z
    fp8_gemm_nt<0><<<dim3(O1_ / 128, M_ / 128), 256, GEMM_SMEM_BYTES>>>(
        y8, w1, bias1, z, cat, nullptr, nullptr, M_, O1_, C_);

    // 4) q/k LN + transpose (f16, Q pre-scaled), v transpose
    qkv_ln_transpose_kernel<<<(B_*N_*H_) / 8, 256>>>(
        z, q_norm_w, q_norm_b, k_norm_w, k_norm_b, qT, kT, vT);

    // 5) attention -> cat[:, HID:] (e4m3)
    attn_mma_kernel<<<dim3(N_ / 128, B_ * H_), 256, ATTN_SMEM_BYTES>>>(
        qT, kT, vT, cat);

    // 6) out = x + lsg * (cat @ w2s^T / 32 + bias2)  — folded GEMM2 + residual
    fp8_gemm_nt<2><<<dim3(C_ / 128, M_ / 128), 256, GEMM_SMEM_BYTES>>>(
        cat, w2s, bias2, out, nullptr, x, ls_gamma, M_, C_, F_);
}

// round 16
// speedup vs baseline: 8.6416x; 1.0548x over previous
#include <cuda_runtime.h>
#include <cuda_bf16.h>
#include <cuda_fp16.h>
#include <math.h>
#include <cstdint>

// ---------------------------------------------------------------------------
// Problem dims (fixed)
// ---------------------------------------------------------------------------
#define B_   8
#define N_   1024
#define C_   1024
#define H_   16
#define D_   64
#define HID_ 4096
#define M_   (B_*N_)            // 8192 rows
#define O1_  (HID_ + 3*C_)      // 7168  (in_proj out)
#define F_   (HID_ + C_)        // 5120  (cat width)
#define EPS_ 1e-5f
// 1/sqrt(64) * log2(e), folded into Q so softmax works in exp2 domain
#define QSCALE_ 0.18033688011112042f
#define WSCALE_ 32.0f
#define RSCALE_ (1.0f/32.0f)

// ---------------------------------------------------------------------------
// Scratch (device globals)
// ---------------------------------------------------------------------------
__device__ uint8_t g_y8[(size_t)M_ * C_];             // LN(x) e4m3         8 MB
__device__ uint8_t g_w1[(size_t)O1_ * C_];            // in_proj_w e4m3*32  7 MB
__device__ uint8_t g_w2s[(size_t)C_ * F_];            // folded w2 e4m3*32  5 MB
__device__ uint8_t g_cat[(size_t)M_ * F_];            // [gelu|attn] e4m3  40 MB
__device__ __half g_qT[(size_t)B_*H_*N_*D_];          // f16               16 MB
__device__ __half g_kT[(size_t)B_*H_*N_*D_];          //                   16 MB
__device__ __half g_vT[(size_t)B_*H_*N_*D_];          //                   16 MB
__device__ float g_bias1[O1_];                        // concat(0(3C), mlp_bias)
__device__ float g_bias2[C_];                         // b2[:C] + b2[C:]

// ---------------------------------------------------------------------------
// helpers
// ---------------------------------------------------------------------------
__device__ __forceinline__ unsigned smem_u32(const void* p) {
    return (unsigned)__cvta_generic_to_shared(p);
}
__device__ __forceinline__ void cp_async16(void* dst, const void* src) {
    asm volatile("cp.async.cg.shared.global [%0], [%1], 16;\n"
                 :: "r"(smem_u32(dst)), "l"(src));
}
__device__ __forceinline__ void cp_commit() {
    asm volatile("cp.async.commit_group;\n" ::: "memory");
}
__device__ __forceinline__ void cp_wait0() {
    asm volatile("cp.async.wait_group 0;\n" ::: "memory");
}
__device__ __forceinline__ void cp_wait1() {
    asm volatile("cp.async.wait_group 1;\n" ::: "memory");
}
__device__ __forceinline__ void ldmatrix_x4(unsigned* r, const void* p) {
    asm volatile("ldmatrix.sync.aligned.m8n8.x4.shared.b16 {%0,%1,%2,%3}, [%4];\n"
                 : "=r"(r[0]), "=r"(r[1]), "=r"(r[2]), "=r"(r[3])
                 : "r"(smem_u32(p)));
}
__device__ __forceinline__ void ldmatrix_x4_trans(unsigned* r, const void* p) {
    asm volatile("ldmatrix.sync.aligned.m8n8.x4.trans.shared.b16 {%0,%1,%2,%3}, [%4];\n"
                 : "=r"(r[0]), "=r"(r[1]), "=r"(r[2]), "=r"(r[3])
                 : "r"(smem_u32(p)));
}
__device__ __forceinline__ void mma16816(float* c, const unsigned* a,
                                         unsigned b0, unsigned b1) {
    asm volatile("mma.sync.aligned.m16n8k16.row.col.f32.f16.f16.f32 "
                 "{%0,%1,%2,%3}, {%4,%5,%6,%7}, {%8,%9}, {%0,%1,%2,%3};\n"
                 : "+f"(c[0]), "+f"(c[1]), "+f"(c[2]), "+f"(c[3])
                 : "r"(a[0]), "r"(a[1]), "r"(a[2]), "r"(a[3]),
                   "r"(b0), "r"(b1));
}
// FP8 e4m3 MMA, k32
__device__ __forceinline__ void mma16832(float* c, const unsigned* a,
                                         unsigned b0, unsigned b1) {
    asm volatile("mma.sync.aligned.m16n8k32.row.col.f32.e4m3.e4m3.f32 "
                 "{%0,%1,%2,%3}, {%4,%5,%6,%7}, {%8,%9}, {%0,%1,%2,%3};\n"
                 : "+f"(c[0]), "+f"(c[1]), "+f"(c[2]), "+f"(c[3])
                 : "r"(a[0]), "r"(a[1]), "r"(a[2]), "r"(a[3]),
                   "r"(b0), "r"(b1));
}
// pack two floats to e4m3x2 (lo in low byte)
__device__ __forceinline__ unsigned short fp8x2(float lo, float hi) {
    unsigned short r;
    asm("{\n\t.reg .b16 t;\n\tcvt.rn.satfinite.e4m3x2.f32 t, %1, %2;\n\t"
        "mov.b16 %0, t;\n\t}" : "=h"(r) : "f"(hi), "f"(lo));
    return r;
}

// FFMA-pipe fast exp2 (no MUFU). x <= 0 expected; rel err ~4e-5.
__device__ __forceinline__ float fexp2(float x) {
    x = fmaxf(x, -100.0f);
    float t = x + 12582912.0f;            // 1.5 * 2^23
    int   i = __float_as_int(t);
    float fl = t - 12582912.0f;
    float fr = x - fl;                    // [-0.5, 0.5]
    float p = 0.0096181f;
    p = fmaf(p, fr, 0.0555041f);
    p = fmaf(p, fr, 0.2402265f);
    p = fmaf(p, fr, 0.6931472f);
    p = fmaf(p, fr, 1.0f);
    return __int_as_float(__float_as_int(p) + (i << 23));
}

// exact GELU via erff
__device__ __forceinline__ float gelu_exact(float v) {
    return 0.5f * v * (1.0f + erff(v * 0.7071067811865475f));
}

// ---------------------------------------------------------------------------
// fp32 -> e4m3 conversion with scale (weights)
// ---------------------------------------------------------------------------
__global__ void __launch_bounds__(256) f2fp8_kernel(
    const float* __restrict__ in, uint8_t* __restrict__ out, float scale, int n4)
{
    int i = blockIdx.x * blockDim.x + threadIdx.x;
    if (i >= n4) return;
    float4 v = ((const float4*)in)[i];
    unsigned r = (unsigned)fp8x2(v.x*scale, v.y*scale)
               | ((unsigned)fp8x2(v.z*scale, v.w*scale) << 16);
    ((unsigned*)out)[i] = r;
}

// folded out_proj: w2s[c,f] = (w2[c,f] + w2[c+C,f]) * WSCALE  (e4m3)
__global__ void __launch_bounds__(256) fold_w2_kernel(
    const float* __restrict__ w2, uint8_t* __restrict__ w2s)
{
    int i = blockIdx.x * blockDim.x + threadIdx.x;   // over C*F/4
    if (i >= C_ * F_ / 4) return;
    float4 a = ((const float4*)w2)[i];
    float4 b = ((const float4*)(w2 + (size_t)C_ * F_))[i];
    unsigned r = (unsigned)fp8x2((a.x+b.x)*WSCALE_, (a.y+b.y)*WSCALE_)
               | ((unsigned)fp8x2((a.z+b.z)*WSCALE_, (a.w+b.w)*WSCALE_) << 16);
    ((unsigned*)w2s)[i] = r;
}

// ---------------------------------------------------------------------------
// 1) Input LayerNorm -> e4m3
// ---------------------------------------------------------------------------
__global__ void __launch_bounds__(256) ln_in_kernel(
    const float* __restrict__ x, const float* __restrict__ w,
    const float* __restrict__ b, uint8_t* __restrict__ y)
{
    int row = blockIdx.x;
    const float4* xr = (const float4*)(x + (size_t)row * C_);
    float4 v = xr[threadIdx.x];
    float s  = v.x + v.y + v.z + v.w;
    float ss = v.x*v.x + v.y*v.y + v.z*v.z + v.w*v.w;

    #pragma unroll
    for (int o = 16; o; o >>= 1) {
        s  += __shfl_xor_sync(0xffffffffu, s,  o);
        ss += __shfl_xor_sync(0xffffffffu, ss, o);
    }
    __shared__ float sb[8], ssb[8];
    int wid = threadIdx.x >> 5, lane = threadIdx.x & 31;
    if (lane == 0) { sb[wid] = s; ssb[wid] = ss; }
    __syncthreads();
    __shared__ float s_mean, s_rstd;
    if (threadIdx.x == 0) {
        float t = 0.f, ts = 0.f;
        #pragma unroll
        for (int i = 0; i < 8; i++) { t += sb[i]; ts += ssb[i]; }
        float mean = t * (1.0f / C_);
        float var  = ts * (1.0f / C_) - mean * mean;
        s_mean = mean;
        s_rstd = rsqrtf(var + EPS_);
    }
    __syncthreads();
    float mean = s_mean, rstd = s_rstd;
    float4 wq = ((const float4*)w)[threadIdx.x];
    float4 bq = ((const float4*)b)[threadIdx.x];
    float ox = (v.x - mean) * rstd * wq.x + bq.x;
    float oy = (v.y - mean) * rstd * wq.y + bq.y;
    float oz = (v.z - mean) * rstd * wq.z + bq.z;
    float ow = (v.w - mean) * rstd * wq.w + bq.w;
    unsigned r = (unsigned)fp8x2(ox, oy) | ((unsigned)fp8x2(oz, ow) << 16);
    *(unsigned*)(y + (size_t)row * C_ + threadIdx.x * 4) = r;
}

// ---------------------------------------------------------------------------
// 2) bias1 = concat(zeros(3C), mlp_bias); bias2 = b2[:C] + b2[C:]
// ---------------------------------------------------------------------------
__global__ void build_bias_kernel(const float* __restrict__ mlp_bias,
                                  const float* __restrict__ out_proj_b,
                                  float* __restrict__ bias1,
                                  float* __restrict__ bias2)
{
    int o = blockIdx.x * blockDim.x + threadIdx.x;
    if (o < O1_) bias1[o] = (o < 3*C_) ? 0.f : mlp_bias[o - 3*C_];
    if (o < C_)  bias2[o] = out_proj_b[o] + out_proj_b[o + C_];
}

// ---------------------------------------------------------------------------
// 3) FP8 e4m3 GEMM: acc = A[M,K] * B[N,K]^T  (weights pre-scaled by 32)
//    128x128 tile, BK=64, 3-stage cp.async, ONE sync per k-iter.
//    MODE 0: GEMM1 epilogue:
//            n0 < HID -> gelu -> e4m3 cat
//            else      -> fused q/k LN (+QSCALE for q) / v copy -> f16 [B,H,N,D]
//    MODE 2: GEMM2 fused final: out = x + lsg * (acc/32 + bias)  (fp32)
// ---------------------------------------------------------------------------
#define GP8  80
#define GST8 (128*GP8)                    // 10240 B per tile stage
#define GEMM_SMEM_BYTES (128*132*4)       // epilogue float staging dominates (67584)

template<int MODE>
__global__ void __launch_bounds__(256) fp8_gemm_nt(
    const uint8_t* __restrict__ A, const uint8_t* __restrict__ Bm,
    const float* __restrict__ bias, void* __restrict__ Cout,
    uint8_t* __restrict__ catOut,
    const float* __restrict__ xres, const float* __restrict__ lsg,
    __half* __restrict__ qT, __half* __restrict__ kT, __half* __restrict__ vT,
    const float* __restrict__ qw, const float* __restrict__ qb,
    const float* __restrict__ kw, const float* __restrict__ kb,
    int M, int N, int K)
{
    extern __shared__ __align__(16) char smraw[];
    char* smb = smraw;
    // A stages at smb + s*GST8 (s=0..2); B stages at smb + 3*GST8 + s*GST8

    int tid = threadIdx.x;
    int m0 = blockIdx.y * 128;
    int n0 = blockIdx.x * 128;
    int wid = tid >> 5, lane = tid & 31;
    int wm = wid >> 2, wn = wid & 3;

    // copy mapping: 512 16B-chunks per tile, 2 per thread
    int crow[2], ccol[2];
    #pragma unroll
    for (int i = 0; i < 2; i++) {
        int chunk = tid + i * 256;
        crow[i] = chunk >> 2;
        ccol[i] = (chunk & 3) * 16;
    }

    float acc[4][4][4];
    #pragma unroll
    for (int i = 0; i < 4; i++)
        #pragma unroll
        for (int j = 0; j < 4; j++)
            #pragma unroll
            for (int e = 0; e < 4; e++) acc[i][j][e] = 0.f;

    int nk = K >> 6;

    // prologue: stages 0 and 1
    #pragma unroll
    for (int st = 0; st < 2; st++) {
        char* sA = smb + st*GST8;
        char* sB = smb + 3*GST8 + st*GST8;
        int kofs = st << 6;
        #pragma unroll
        for (int i = 0; i < 2; i++) {
            cp_async16(sA + crow[i]*GP8 + ccol[i],
                       A + (size_t)(m0 + crow[i]) * K + kofs + ccol[i]);
            cp_async16(sB + crow[i]*GP8 + ccol[i],
                       Bm + (size_t)(n0 + crow[i]) * K + kofs + ccol[i]);
        }
        cp_commit();
    }

    int sc = 0;        // compute stage
    int sp = 2;        // prefetch stage

    for (int k0 = 0; k0 < nk; k0++) {
        if (k0 + 1 < nk) cp_wait1(); else cp_wait0();
        __syncthreads();

        if (k0 + 2 < nk) {
            int kofs = (k0 + 2) << 6;
            char* sA = smb + sp*GST8;
            char* sB = smb + 3*GST8 + sp*GST8;
            #pragma unroll
            for (int i = 0; i < 2; i++) {
                cp_async16(sA + crow[i]*GP8 + ccol[i],
                           A + (size_t)(m0 + crow[i]) * K + kofs + ccol[i]);
                cp_async16(sB + crow[i]*GP8 + ccol[i],
                           Bm + (size_t)(n0 + crow[i]) * K + kofs + ccol[i]);
            }
            cp_commit();
        }

        const char* sA = smb + sc*GST8;
        const char* sB = smb + 3*GST8 + sc*GST8;

        #pragma unroll
        for (int kc = 0; kc < 2; kc++) {
            unsigned af[4][4];
            #pragma unroll
            for (int i = 0; i < 4; i++)
                ldmatrix_x4(af[i], sA + (wm*64 + i*16 + (lane & 15))*GP8
                                      + kc*32 + (lane >> 4)*16);
            #pragma unroll
            for (int jp = 0; jp < 2; jp++) {
                unsigned bf[4];
                ldmatrix_x4(bf, sB + (wn*32 + jp*16 + ((lane >> 4) << 3) + (lane & 7))*GP8
                                   + kc*32 + ((lane >> 3) & 1)*16);
                #pragma unroll
                for (int i = 0; i < 4; i++) {
                    mma16832(acc[i][2*jp],   af[i], bf[0], bf[1]);
                    mma16832(acc[i][2*jp+1], af[i], bf[2], bf[3]);
                }
            }
        }

        sc = (sc == 2) ? 0 : sc + 1;
        sp = (sp == 2) ? 0 : sp + 1;
    }

    __syncthreads();   // before reusing smem for epilogue staging

    // stage accumulators to smem (fp32, [128][132])
    float* Cs = (float*)smraw;
    {
        int r1 = lane >> 2, cpos = (lane & 3) * 2;
        #pragma unroll
        for (int i = 0; i < 4; i++)
            #pragma unroll
            for (int n = 0; n < 4; n++) {
                float* base = Cs + (size_t)(wm*64 + i*16) * 132 + wn*32 + n*8 + cpos;
                *(float2*)(base + r1*132)     = make_float2(acc[i][n][0], acc[i][n][1]);
                *(float2*)(base + (r1+8)*132) = make_float2(acc[i][n][2], acc[i][n][3]);
            }
    }
    __syncthreads();

    if (MODE == 2) {
        #pragma unroll
        for (int it = 0; it < 16; it++) {
            int idx = tid + it * 256;
            int row = idx >> 5;
            int c4  = (idx & 31) * 4;
            float4 v = *(const float4*)(Cs + row*132 + c4);
            float4 bb = *(const float4*)(bias + n0 + c4);
            v.x = v.x * RSCALE_ + bb.x;
            v.y = v.y * RSCALE_ + bb.y;
            v.z = v.z * RSCALE_ + bb.z;
            v.w = v.w * RSCALE_ + bb.w;
            float4 xv = *(const float4*)(xres + (size_t)(m0 + row) * C_ + n0 + c4);
            float4 gv = *(const float4*)(lsg + n0 + c4);
            float4 r;
            r.x = xv.x + gv.x * v.x;
            r.y = xv.y + gv.y * v.y;
            r.z = xv.z + gv.z * v.z;
            r.w = xv.w + gv.w * v.w;
            float* Cr = (float*)Cout + (size_t)(m0 + row) * N + n0 + c4;
            *(float4*)Cr = r;
        }
    } else if (n0 < HID_) {
        // MLP tile: gelu -> e4m3 cat
        #pragma unroll
        for (int it = 0; it < 16; it++) {
            int idx = tid + it * 256;
            int row = idx >> 5;
            int c4  = (idx & 31) * 4;
            float4 v = *(const float4*)(Cs + row*132 + c4);
            float4 bb = *(const float4*)(bias + n0 + c4);
            v.x = gelu_exact(v.x * RSCALE_ + bb.x);
            v.y = gelu_exact(v.y * RSCALE_ + bb.y);
            v.z = gelu_exact(v.z * RSCALE_ + bb.z);
            v.w = gelu_exact(v.w * RSCALE_ + bb.w);
            unsigned r = (unsigned)fp8x2(v.x, v.y) | ((unsigned)fp8x2(v.z, v.w) << 16);
            *(unsigned*)(catOut + (size_t)(m0 + row) * F_ + n0 + c4) = r;
        }
    } else {
        // QKV tile: fused per-head LN (q/k) or copy (v) -> f16 [B,H,N,D]
        int seg = (n0 - HID_) >> 10;               // 0=q, 1=k, 2=v
        int h0  = ((n0 - HID_) & 1023) >> 6;       // head for cols 0..63
        const float* lnw = (seg == 0) ? qw : kw;
        const float* lnb = (seg == 0) ? qb : kb;
        float oscale = (seg == 0) ? QSCALE_ : 1.0f;
        __half* dstB = (seg == 0) ? qT : ((seg == 1) ? kT : vT);
        int h = h0 + (lane >> 4);                  // lanes 0-15: h0, 16-31: h0+1
        int d = (lane & 15) * 4;

        #pragma unroll
        for (int it = 0; it < 16; it++) {
            int idx = tid + it * 256;
            int row = idx >> 5;
            int c4  = (idx & 31) * 4;
            float4 v = *(const float4*)(Cs + row*132 + c4);
            float4 bb = *(const float4*)(bias + n0 + c4);
            v.x = v.x * RSCALE_ + bb.x;
            v.y = v.y * RSCALE_ + bb.y;
            v.z = v.z * RSCALE_ + bb.z;
            v.w = v.w * RSCALE_ + bb.w;

            int m = m0 + row;
            int bidx = m >> 10, nn = m & 1023;
            size_t off = (((size_t)(bidx * 16 + h)) * 1024 + nn) * 64 + d;

            float o0, o1, o2v, o3;
            if (seg < 2) {
                float s  = v.x + v.y + v.z + v.w;
                float ss = v.x*v.x + v.y*v.y + v.z*v.z + v.w*v.w;
                #pragma unroll
                for (int msk = 1; msk <= 8; msk <<= 1) {
                    s  += __shfl_xor_sync(0xffffffffu, s,  msk);
                    ss += __shfl_xor_sync(0xffffffffu, ss, msk);
                }
                float mean = s * (1.0f / 64.0f);
                float var  = ss * (1.0f / 64.0f) - mean * mean;
                float rstd = rsqrtf(var + EPS_);
                float4 w4 = *(const float4*)(lnw + d);
                float4 b4 = *(const float4*)(lnb + d);
                o0  = ((v.x - mean) * rstd * w4.x + b4.x) * oscale;
                o1  = ((v.y - mean) * rstd * w4.y + b4.y) * oscale;
                o2v = ((v.z - mean) * rstd * w4.z + b4.z) * oscale;
                o3  = ((v.w - mean) * rstd * w4.w + b4.w) * oscale;
            } else {
                o0 = v.x; o1 = v.y; o2v = v.z; o3 = v.w;
            }
            __half2 p0 = __floats2half2_rn(o0, o1);
            __half2 p1 = __floats2half2_rn(o2v, o3);
            uint2 u;
            u.x = *(unsigned*)&p0;
            u.y = *(unsigned*)&p1;
            *(uint2*)(dstB + off) = u;
        }
    }
}

// ---------------------------------------------------------------------------
// 5) Flash attention, mma.sync f16, FFMA-pipe exp2; e4m3 output into cat
// ---------------------------------------------------------------------------
#define AT_PAD 72
#define ATTN_SMEM_BYTES ((128*AT_PAD + 4*64*AT_PAD) * 2)

__global__ void __launch_bounds__(256, 2) attn_mma_kernel(
    const __half* __restrict__ Qg, const __half* __restrict__ Kg,
    const __half* __restrict__ Vg, uint8_t* __restrict__ cat)
{
    extern __shared__ __align__(16) __half smh[];
    __half* Qs  = smh;
    __half* Ks0 = Qs + 128*AT_PAD;
    __half* Vs0 = Ks0 + 2*64*AT_PAD;

    int bh = blockIdx.y;
    int n0 = blockIdx.x * 128;
    const __half* qg = Qg + ((size_t)bh * N_ + n0) * D_;
    const __half* kg = Kg + (size_t)bh * N_ * D_;
    const __half* vg = Vg + (size_t)bh * N_ * D_;

    int tid = threadIdx.x;
    int lane = tid & 31, wid = tid >> 5;
    int m0 = wid * 16;

    #pragma unroll
    for (int i = 0; i < 4; i++) {
        int chunk = tid + i * 256;
        int r = chunk >> 3, c = (chunk & 7) * 8;
        cp_async16(Qs + r*AT_PAD + c, qg + r*64 + c);
    }
    cp_commit();
    #pragma unroll
    for (int i = 0; i < 2; i++) {
        int chunk = tid + i * 256;
        int r = chunk >> 3, c = (chunk & 7) * 8;
        cp_async16(Ks0 + r*AT_PAD + c, kg + r*64 + c);
        cp_async16(Vs0 + r*AT_PAD + c, vg + r*64 + c);
    }
    cp_commit();

    cp_wait1();
    __syncthreads();

    unsigned qf[4][4];
    {
        int row = m0 + (lane & 15);
        int colb = (lane >> 4) * 8;
        #pragma unroll
        for (int kc = 0; kc < 4; kc++)
            ldmatrix_x4(qf[kc], Qs + row*AT_PAD + kc*16 + colb);
    }

    float o[8][4];
    #pragma unroll
    for (int j = 0; j < 8; j++)
        #pragma unroll
        for (int e = 0; e < 4; e++) o[j][e] = 0.f;
    float m1 = -1e30f, m2 = -1e30f, l1 = 0.f, l2 = 0.f;

    for (int kt = 0; kt < 16; kt++) {
        if (kt + 1 < 16) {
            int s = (kt + 1) & 1;
            const __half* kgn = kg + (size_t)(kt + 1) * 64 * D_;
            const __half* vgn = vg + (size_t)(kt + 1) * 64 * D_;
            __half* Kd = Ks0 + s * 64*AT_PAD;
            __half* Vd = Vs0 + s * 64*AT_PAD;
            #pragma unroll
            for (int i = 0; i < 2; i++) {
                int chunk = tid + i * 256;
                int r = chunk >> 3, c = (chunk & 7) * 8;
                cp_async16(Kd + r*AT_PAD + c, kgn + r*64 + c);
                cp_async16(Vd + r*AT_PAD + c, vgn + r*64 + c);
            }
            cp_commit();
            cp_wait1();
        } else {
            cp_wait0();
        }
        __syncthreads();

        const __half* Ksm = Ks0 + (kt & 1) * 64*AT_PAD;
        const __half* Vsm = Vs0 + (kt & 1) * 64*AT_PAD;

        float s[8][4];
        #pragma unroll
        for (int j = 0; j < 8; j++)
            #pragma unroll
            for (int e = 0; e < 4; e++) s[j][e] = 0.f;

        #pragma unroll
        for (int jp = 0; jp < 4; jp++) {
            int krow = jp*16 + ((lane >> 4) << 3) + (lane & 7);
            int kcol = ((lane >> 3) & 1) * 8;
            #pragma unroll
            for (int kc = 0; kc < 4; kc++) {
                unsigned kb[4];
                ldmatrix_x4(kb, Ksm + krow*AT_PAD + kc*16 + kcol);
                mma16816(s[2*jp],   qf[kc], kb[0], kb[1]);
                mma16816(s[2*jp+1], qf[kc], kb[2], kb[3]);
            }
        }

        float mx1 = -1e30f, mx2 = -1e30f;
        #pragma unroll
        for (int j = 0; j < 8; j++) {
            mx1 = fmaxf(mx1, fmaxf(s[j][0], s[j][1]));
            mx2 = fmaxf(mx2, fmaxf(s[j][2], s[j][3]));
        }
        mx1 = fmaxf(mx1, __shfl_xor_sync(0xffffffffu, mx1, 1));
        mx1 = fmaxf(mx1, __shfl_xor_sync(0xffffffffu, mx1, 2));
        mx2 = fmaxf(mx2, __shfl_xor_sync(0xffffffffu, mx2, 1));
        mx2 = fmaxf(mx2, __shfl_xor_sync(0xffffffffu, mx2, 2));
        float mn1 = fmaxf(m1, mx1), mn2 = fmaxf(m2, mx2);
        float f1 = fexp2(m1 - mn1), f2 = fexp2(m2 - mn2);
        m1 = mn1; m2 = mn2;

        __half2 ph[8][2];
        float sum1 = 0.f, sum2 = 0.f;
        #pragma unroll
        for (int j = 0; j < 8; j++) {
            float p0 = fexp2(s[j][0] - m1);
            float p1 = fexp2(s[j][1] - m1);
            float p2 = fexp2(s[j][2] - m2);
            float p3 = fexp2(s[j][3] - m2);
            ph[j][0] = __floats2half2_rn(p0, p1);
            ph[j][1] = __floats2half2_rn(p2, p3);
            sum1 += p0 + p1;
            sum2 += p2 + p3;
        }
        sum1 += __shfl_xor_sync(0xffffffffu, sum1, 1);
        sum1 += __shfl_xor_sync(0xffffffffu, sum1, 2);
        sum2 += __shfl_xor_sync(0xffffffffu, sum2, 1);
        sum2 += __shfl_xor_sync(0xffffffffu, sum2, 2);
        l1 = l1 * f1 + sum1;
        l2 = l2 * f2 + sum2;

        #pragma unroll
        for (int j = 0; j < 8; j++) {
            o[j][0] *= f1; o[j][1] *= f1;
            o[j][2] *= f2; o[j][3] *= f2;
        }

        #pragma unroll
        for (int dp = 0; dp < 4; dp++) {
            int vcolb = dp*16 + (lane >> 4) * 8;
            int vrowb = ((lane >> 3) & 1) * 8 + (lane & 7);
            #pragma unroll
            for (int kc = 0; kc < 4; kc++) {
                unsigned vb[4];
                ldmatrix_x4_trans(vb, Vsm + (kc*16 + vrowb)*AT_PAD + vcolb);
                unsigned pa[4] = {
                    *(unsigned*)&ph[2*kc][0],   *(unsigned*)&ph[2*kc][1],
                    *(unsigned*)&ph[2*kc+1][0], *(unsigned*)&ph[2*kc+1][1] };
                mma16816(o[2*dp],   pa, vb[0], vb[1]);
                mma16816(o[2*dp+1], pa, vb[2], vb[3]);
            }
        }
        __syncthreads();
    }

    int b = bh >> 4, h = bh & 15;
    int r1 = lane >> 2, coff = (lane & 3) * 2;
    float inv1 = 1.0f / l1, inv2 = 1.0f / l2;
    size_t row1 = (size_t)b * N_ + n0 + m0 + r1;
    size_t row2 = row1 + 8;
    uint8_t* c1 = cat + row1 * F_ + HID_ + h * 64 + coff;
    uint8_t* c2 = cat + row2 * F_ + HID_ + h * 64 + coff;
    #pragma unroll
    for (int jd = 0; jd < 8; jd++) {
        *(unsigned short*)(c1 + jd*8) = fp8x2(o[jd][0]*inv1, o[jd][1]*inv1);
        *(unsigned short*)(c2 + jd*8) = fp8x2(o[jd][2]*inv2, o[jd][3]*inv2);
    }
}

// ---------------------------------------------------------------------------
// launch
// ---------------------------------------------------------------------------
extern "C" void kernel_launch(void* const* d_in, const int* in_sizes, int n_in,
                              void* d_out, int out_size)
{
    const float* x          = (const float*)d_in[0];
    const float* in_norm_w  = (const float*)d_in[1];
    const float* in_norm_b  = (const float*)d_in[2];
    const float* in_proj_w  = (const float*)d_in[3];
    const float* mlp_bias   = (const float*)d_in[4];
    const float* q_norm_w   = (const float*)d_in[5];
    const float* q_norm_b   = (const float*)d_in[6];
    const float* k_norm_w   = (const float*)d_in[7];
    const float* k_norm_b   = (const float*)d_in[8];
    const float* out_proj_w = (const float*)d_in[9];
    const float* out_proj_b = (const float*)d_in[10];
    const float* ls_gamma   = (const float*)d_in[11];
    float* out = (float*)d_out;

    uint8_t *y8, *w1, *w2s, *cat;
    __half *qT, *kT, *vT;
    float *bias1, *bias2;
    cudaGetSymbolAddress((void**)&y8,    g_y8);
    cudaGetSymbolAddress((void**)&w1,    g_w1);
    cudaGetSymbolAddress((void**)&w2s,   g_w2s);
    cudaGetSymbolAddress((void**)&cat,   g_cat);
    cudaGetSymbolAddress((void**)&qT,    g_qT);
    cudaGetSymbolAddress((void**)&kT,    g_kT);
    cudaGetSymbolAddress((void**)&vT,    g_vT);
    cudaGetSymbolAddress((void**)&bias1, g_bias1);
    cudaGetSymbolAddress((void**)&bias2, g_bias2);

    cudaFuncSetAttribute(attn_mma_kernel,
                         cudaFuncAttributeMaxDynamicSharedMemorySize,
                         ATTN_SMEM_BYTES);
    cudaFuncSetAttribute(fp8_gemm_nt<0>,
                         cudaFuncAttributeMaxDynamicSharedMemorySize,
                         GEMM_SMEM_BYTES);
    cudaFuncSetAttribute(fp8_gemm_nt<2>,
                         cudaFuncAttributeMaxDynamicSharedMemorySize,
                         GEMM_SMEM_BYTES);

    // 0) weight conversion / folding (e4m3, scale 32)
    f2fp8_kernel<<<(O1_*C_/4 + 255)/256, 256>>>(in_proj_w, w1, WSCALE_, O1_*C_/4);
    fold_w2_kernel<<<(C_*F_/4 + 255)/256, 256>>>(out_proj_w, w2s);

    // 1) input LN -> y (e4m3)
    ln_in_kernel<<<M_, 256>>>(x, in_norm_w, in_norm_b, y8);

    // 2) biases
    build_bias_kernel<<<(O1_ + 255) / 256, 256>>>(mlp_bias, out_proj_b,
                                                  bias1, bias2);

    // 3) GEMM1: mlp tiles -> gelu -> cat(e4m3); qkv tiles -> fused LN -> f16 q/k/v
    fp8_gemm_nt<0><<<dim3(O1_ / 128, M_ / 128), 256, GEMM_SMEM_BYTES>>>(
        y8, w1, bias1, nullptr, cat, nullptr, nullptr,
        qT, kT, vT, q_norm_w, q_norm_b, k_norm_w, k_norm_b, M_, O1_, C_);

    // 4) attention -> cat[:, HID:] (e4m3)
    attn_mma_kernel<<<dim3(N_ / 128, B_ * H_), 256, ATTN_SMEM_BYTES>>>(
        qT, kT, vT, cat);

    // 5) out = x + lsg * (cat @ w2s^T / 32 + bias2)  — folded GEMM2 + residual
    fp8_gemm_nt<2><<<dim3(C_ / 128, M_ / 128), 256, GEMM_SMEM_BYTES>>>(
        cat, w2s, bias2, out, nullptr, x, ls_gamma,
        nullptr, nullptr, nullptr, nullptr, nullptr, nullptr, nullptr,
        M_, C_, F_);
}